// round 4
// baseline (speedup 1.0000x reference)
#include <cuda_runtime.h>
#include <cuda_bf16.h>
#include <cstdint>

// Problem constants
#define Bb   128
#define Fdim 1536
#define Ed   512
#define Hd   512
#define H4   2048
#define Vd   10000
#define Tl   40
#define BT   (Bb*Tl)     // 5120
#define K3E  (3*Ed)      // 1536

// ---------------- scratch (static device memory) -----------------------------
__device__ float g_seq[(size_t)BT * Ed];        // [T*B, E]  row r = t*B + b
__device__ float g_xg[(size_t)BT * H4];         // [T*B, 4H]
__device__ float g_hidden[(size_t)BT * Hd];     // [B*T, H]  row r = b*T + t
__device__ float g_h[Bb * Hd];
__device__ float g_c[Bb * Hd];

// split-bf16 operand buffers (K-concatenated 3-way split)
__device__ __align__(16) __nv_bfloat16 s_seq [(size_t)BT * K3E];
__device__ __align__(16) __nv_bfloat16 s_Wih [(size_t)H4 * K3E];
__device__ __align__(16) __nv_bfloat16 s_hid [(size_t)BT * K3E];
__device__ __align__(16) __nv_bfloat16 s_Wout[(size_t)Vd * K3E];

__device__ __forceinline__ float sigmoidf_(float x) { return 1.0f / (1.0f + __expf(-x)); }

__device__ __forceinline__ uint32_t smem_u32(const void* p) {
    return (uint32_t)__cvta_generic_to_shared(p);
}

// ---------------- exact fp32 SIMT GEMM (for x0): C = A @ B^T + bias -----------
template<int BM, int BN, int BK, int TM, int TN>
__global__ void gemm_tn(const float* __restrict__ A,
                        const float* __restrict__ Bw,
                        const float* __restrict__ bias,
                        float* __restrict__ C,
                        int M, int N, int K)
{
    constexpr int NT = (BM / TM) * (BN / TN);
    static_assert(NT == 256, "need 256 threads");
    __shared__ float As[BK][BM];
    __shared__ float Bs[BK][BN];

    const int m0 = blockIdx.y * BM;
    const int n0 = blockIdx.x * BN;
    const int tid = threadIdx.x;
    constexpr int NTX = BN / TN;
    const int tc = tid % NTX;
    const int tr = tid / NTX;

    float acc[TM][TN];
    #pragma unroll
    for (int i = 0; i < TM; i++)
        #pragma unroll
        for (int j = 0; j < TN; j++) acc[i][j] = 0.0f;

    constexpr int A_LD4 = BM * BK / 4;
    constexpr int B_LD4 = BN * BK / 4;
    constexpr int K4 = BK / 4;

    for (int k0 = 0; k0 < K; k0 += BK) {
        #pragma unroll
        for (int i = tid; i < A_LD4; i += NT) {
            int row = i / K4;
            int kc  = (i % K4) * 4;
            float4 v = *reinterpret_cast<const float4*>(
                A + (size_t)(m0 + row) * K + k0 + kc);
            As[kc + 0][row] = v.x; As[kc + 1][row] = v.y;
            As[kc + 2][row] = v.z; As[kc + 3][row] = v.w;
        }
        #pragma unroll
        for (int i = tid; i < B_LD4; i += NT) {
            int row = i / K4;
            int kc  = (i % K4) * 4;
            float4 v = make_float4(0.f, 0.f, 0.f, 0.f);
            if (n0 + row < N)
                v = *reinterpret_cast<const float4*>(
                    Bw + (size_t)(n0 + row) * K + k0 + kc);
            Bs[kc + 0][row] = v.x; Bs[kc + 1][row] = v.y;
            Bs[kc + 2][row] = v.z; Bs[kc + 3][row] = v.w;
        }
        __syncthreads();

        #pragma unroll
        for (int k = 0; k < BK; k++) {
            float ra[TM], rb[TN];
            #pragma unroll
            for (int i = 0; i < TM; i++) ra[i] = As[k][tr * TM + i];
            #pragma unroll
            for (int j = 0; j < TN; j++) rb[j] = Bs[k][tc * TN + j];
            #pragma unroll
            for (int i = 0; i < TM; i++)
                #pragma unroll
                for (int j = 0; j < TN; j++)
                    acc[i][j] = fmaf(ra[i], rb[j], acc[i][j]);
        }
        __syncthreads();
    }

    #pragma unroll
    for (int i = 0; i < TM; i++) {
        int m = m0 + tr * TM + i;
        #pragma unroll
        for (int j = 0; j < TN; j++) {
            int n = n0 + tc * TN + j;
            if (n < N)
                C[(size_t)m * N + n] = acc[i][j] + bias[n];
        }
    }
}

// ---------------- bf16 HMMA GEMM: C = A @ B^T + bias --------------------------
// A: [M, K] bf16 (M % 128 == 0), B: [N, K] bf16 (N ragged OK), K % 32 == 0.
// Block tile 128x256, 512 threads (16 warps, warp tile 64x32), 4-stage cp.async.
#define STRIDEg  40                       // smem row stride (bf16) -> conflict-free
#define SA_STG   (128 * STRIDEg)          // 5120 bf16
#define SB_STG   (256 * STRIDEg)          // 10240 bf16
#define NSTAGE   4
#define SMEM_HM  (NSTAGE * (SA_STG + SB_STG) * 2)   // 122880 bytes

__global__ void __launch_bounds__(512, 1)
gemm_hmma(const __nv_bfloat16* __restrict__ A,
          const __nv_bfloat16* __restrict__ B,
          const float* __restrict__ bias,
          float* __restrict__ C,
          int M, int N, int K)
{
    extern __shared__ __align__(16) __nv_bfloat16 sm[];
    __nv_bfloat16* As = sm;                       // NSTAGE x SA_STG
    __nv_bfloat16* Bs = sm + NSTAGE * SA_STG;     // NSTAGE x SB_STG

    const int tid  = threadIdx.x;
    const int warp = tid >> 5, lane = tid & 31;
    const int wm = (warp >> 3) * 64;   // 0 or 64
    const int wn = (warp & 7) * 32;    // 0..224
    const int m0 = blockIdx.y * 128, n0 = blockIdx.x * 256;
    const int KT = K / 32;

    float acc[4][4][4];
    #pragma unroll
    for (int i = 0; i < 4; i++)
        #pragma unroll
        for (int j = 0; j < 4; j++)
            #pragma unroll
            for (int r = 0; r < 4; r++) acc[i][j][r] = 0.0f;

    auto load_tile = [&](int buf, int kt) {
        const int k0 = kt * 32;
        {   // A: 128 rows x 4 chunks = 512 tasks (1/thread)
            int r = tid >> 2, c = tid & 3;
            uint32_t dst = smem_u32(&As[buf * SA_STG + r * STRIDEg + c * 8]);
            const void* src = A + (size_t)(m0 + r) * K + k0 + c * 8;
            asm volatile("cp.async.cg.shared.global [%0],[%1],16;\n" :: "r"(dst), "l"(src));
        }
        #pragma unroll
        for (int it = 0; it < 2; it++) {   // B: 256 rows x 4 chunks = 1024 tasks
            int task = tid + it * 512;
            int r = task >> 2, c = task & 3;
            if (n0 + r < N) {
                uint32_t dst = smem_u32(&Bs[buf * SB_STG + r * STRIDEg + c * 8]);
                const void* src = B + (size_t)(n0 + r) * K + k0 + c * 8;
                asm volatile("cp.async.cg.shared.global [%0],[%1],16;\n" :: "r"(dst), "l"(src));
            }
        }
        asm volatile("cp.async.commit_group;\n");
    };

    // prefetch up to 3 stages
    #pragma unroll
    for (int s = 0; s < 3; s++) {
        if (s < KT) load_tile(s, s);
        else        asm volatile("cp.async.commit_group;\n");
    }

    for (int ck = 0; ck < KT; ck++) {
        if (ck + 3 < KT) load_tile((ck + 3) & 3, ck + 3);
        else             asm volatile("cp.async.commit_group;\n");
        asm volatile("cp.async.wait_group 3;\n");
        __syncthreads();

        const int buf = ck & 3;
        const __nv_bfloat16* as = As + buf * SA_STG;
        const __nv_bfloat16* bs = Bs + buf * SB_STG;

        #pragma unroll
        for (int kk = 0; kk < 32; kk += 16) {
            uint32_t afr[4][4];
            #pragma unroll
            for (int i = 0; i < 4; i++) {
                int row = wm + i * 16 + (lane & 15);
                int col = kk + (lane >> 4) * 8;
                uint32_t addr = smem_u32(&as[row * STRIDEg + col]);
                asm volatile("ldmatrix.sync.aligned.m8n8.x4.shared.b16 {%0,%1,%2,%3},[%4];"
                             : "=r"(afr[i][0]), "=r"(afr[i][1]), "=r"(afr[i][2]), "=r"(afr[i][3])
                             : "r"(addr));
            }
            uint32_t bfr[4][2];
            #pragma unroll
            for (int j = 0; j < 2; j++) {
                int grp = lane >> 3;
                int row = wn + j * 16 + (grp >> 1) * 8 + (lane & 7);
                int col = kk + (grp & 1) * 8;
                uint32_t addr = smem_u32(&bs[row * STRIDEg + col]);
                uint32_t r0, r1, r2, r3;
                asm volatile("ldmatrix.sync.aligned.m8n8.x4.shared.b16 {%0,%1,%2,%3},[%4];"
                             : "=r"(r0), "=r"(r1), "=r"(r2), "=r"(r3) : "r"(addr));
                bfr[j * 2][0] = r0; bfr[j * 2][1] = r1;
                bfr[j * 2 + 1][0] = r2; bfr[j * 2 + 1][1] = r3;
            }
            #pragma unroll
            for (int i = 0; i < 4; i++)
                #pragma unroll
                for (int j = 0; j < 4; j++) {
                    asm volatile(
                        "mma.sync.aligned.m16n8k16.row.col.f32.bf16.bf16.f32 "
                        "{%0,%1,%2,%3},{%4,%5,%6,%7},{%8,%9},{%0,%1,%2,%3};"
                        : "+f"(acc[i][j][0]), "+f"(acc[i][j][1]),
                          "+f"(acc[i][j][2]), "+f"(acc[i][j][3])
                        : "r"(afr[i][0]), "r"(afr[i][1]), "r"(afr[i][2]), "r"(afr[i][3]),
                          "r"(bfr[j][0]), "r"(bfr[j][1]));
                }
        }
        __syncthreads();
    }

    // epilogue
    const int mrow = lane >> 2, nc2 = (lane & 3) * 2;
    #pragma unroll
    for (int i = 0; i < 4; i++) {
        int gm = m0 + wm + i * 16 + mrow;
        float* Crow0 = C + (size_t)gm * N;
        float* Crow1 = C + (size_t)(gm + 8) * N;
        #pragma unroll
        for (int j = 0; j < 4; j++) {
            int gn = n0 + wn + j * 8 + nc2;
            if (gn < N) {
                float bv = bias[gn];
                Crow0[gn] = acc[i][j][0] + bv;
                Crow1[gn] = acc[i][j][2] + bv;
            }
            if (gn + 1 < N) {
                float bv = bias[gn + 1];
                Crow0[gn + 1] = acc[i][j][1] + bv;
                Crow1[gn + 1] = acc[i][j][3] + bv;
            }
        }
    }
}

// ---------------- split fp32 -> 3-segment bf16 --------------------------------
// MODE_B==0 (A-side): [hi | hi | lo]      MODE_B==1 (B-side): [hi | lo | hi]
template<int MODE_B>
__global__ void split3(const float* __restrict__ X, __nv_bfloat16* __restrict__ Y,
                       int M, int K)
{
    size_t i = (size_t)blockIdx.x * blockDim.x + threadIdx.x;
    size_t total = (size_t)M * K;
    if (i >= total) return;
    int m = (int)(i / K), k = (int)(i % K);
    float x = X[i];
    __nv_bfloat16 hi = __float2bfloat16_rn(x);
    __nv_bfloat16 lo = __float2bfloat16_rn(x - __bfloat162float(hi));
    __nv_bfloat16* row = Y + (size_t)m * (3 * K);
    if (MODE_B) { row[k] = hi; row[K + k] = lo; row[2 * K + k] = hi; }
    else        { row[k] = hi; row[K + k] = hi; row[2 * K + k] = lo; }
}

// ---------------- gather word embeddings into g_seq rows t>=1 -----------------
__global__ void gather_emb(const int* __restrict__ seqs,
                           const float* __restrict__ emb)
{
    int bid = blockIdx.x;
    int t1  = bid / Bb;
    int b   = bid % Bb;
    int word = seqs[b * (Tl - 1) + t1];
    const float4* src = reinterpret_cast<const float4*>(emb + (size_t)word * Ed);
    float4* dst = reinterpret_cast<float4*>(g_seq + (size_t)((t1 + 1) * Bb + b) * Ed);
    for (int i = threadIdx.x; i < Ed / 4; i += blockDim.x) dst[i] = src[i];
}

// ---------------- zero h, c ----------------------------------------------------
__global__ void init_state()
{
    int i = blockIdx.x * blockDim.x + threadIdx.x;
    if (i < Bb * Hd) { g_h[i] = 0.0f; g_c[i] = 0.0f; }
}

// ---------------- fused LSTM step: gates GEMM + cell ---------------------------
__global__ void __launch_bounds__(256)
lstm_step(const float* __restrict__ Whh,   // [4H, H]
          const float* __restrict__ bhh,   // [4H]
          const float* __restrict__ xg_t,  // [B, 4H]
          int t)
{
    __shared__ float As2[32][33];
    __shared__ float Bs2[32][65];
    __shared__ float Gs [32][65];

    const int tid = threadIdx.x;
    const int jt = blockIdx.x;
    const int b0 = blockIdx.y * 32;
    const int tr = tid >> 4, tc = tid & 15;

    float acc[2][4];
    #pragma unroll
    for (int i = 0; i < 2; i++)
        #pragma unroll
        for (int j = 0; j < 4; j++) acc[i][j] = 0.0f;

    for (int kc = 0; kc < Hd; kc += 32) {
        {
            int r = tid >> 3, c = tid & 7;
            float4 v = *reinterpret_cast<const float4*>(
                g_h + (size_t)(b0 + r) * Hd + kc + c * 4);
            As2[c * 4 + 0][r] = v.x; As2[c * 4 + 1][r] = v.y;
            As2[c * 4 + 2][r] = v.z; As2[c * 4 + 3][r] = v.w;
        }
        #pragma unroll
        for (int it = 0; it < 2; it++) {
            int task = tid + it * 256;
            int r = task >> 3, c = task & 7;
            int grow = (r >> 4) * Hd + jt * 16 + (r & 15);
            float4 v = *reinterpret_cast<const float4*>(
                Whh + (size_t)grow * Hd + kc + c * 4);
            Bs2[c * 4 + 0][r] = v.x; Bs2[c * 4 + 1][r] = v.y;
            Bs2[c * 4 + 2][r] = v.z; Bs2[c * 4 + 3][r] = v.w;
        }
        __syncthreads();

        #pragma unroll
        for (int k = 0; k < 32; k++) {
            float ra0 = As2[k][tr * 2 + 0];
            float ra1 = As2[k][tr * 2 + 1];
            float rb[4];
            #pragma unroll
            for (int j = 0; j < 4; j++) rb[j] = Bs2[k][tc * 4 + j];
            #pragma unroll
            for (int j = 0; j < 4; j++) {
                acc[0][j] = fmaf(ra0, rb[j], acc[0][j]);
                acc[1][j] = fmaf(ra1, rb[j], acc[1][j]);
            }
        }
        __syncthreads();
    }

    #pragma unroll
    for (int i = 0; i < 2; i++) {
        int m = tr * 2 + i;
        #pragma unroll
        for (int j = 0; j < 4; j++) {
            int n = tc * 4 + j;
            int gcol = (n >> 4) * Hd + jt * 16 + (n & 15);
            Gs[m][n] = acc[i][j] + xg_t[(size_t)(b0 + m) * H4 + gcol] + bhh[gcol];
        }
    }
    __syncthreads();

    #pragma unroll
    for (int it = 0; it < 2; it++) {
        int task = tid + it * 256;
        int bl = task >> 4, jj = task & 15;
        float ig = sigmoidf_(Gs[bl][jj]);
        float fg = sigmoidf_(Gs[bl][16 + jj]);
        float gg = tanhf(Gs[bl][32 + jj]);
        float og = sigmoidf_(Gs[bl][48 + jj]);
        size_t idx = (size_t)(b0 + bl) * Hd + jt * 16 + jj;
        float c = fmaf(fg, g_c[idx], ig * gg);
        g_c[idx] = c;
        float h = og * tanhf(c);
        g_h[idx] = h;
        g_hidden[((size_t)(b0 + bl) * Tl + t) * Hd + jt * 16 + jj] = h;
    }
}

// ---------------- launch --------------------------------------------------------
extern "C" void kernel_launch(void* const* d_in, const int* in_sizes, int n_in,
                              void* d_out, int out_size)
{
    const float* features = (const float*)d_in[0];   // [B,F]
    const int*   seqs     = (const int*)  d_in[1];   // [B,T-1]
    const float* W_in  = (const float*)d_in[3];      // [E,F]
    const float* b_in  = (const float*)d_in[4];      // [E]
    const float* emb   = (const float*)d_in[5];      // [V,E]
    const float* W_ih  = (const float*)d_in[6];      // [4H,E]
    const float* W_hh  = (const float*)d_in[7];      // [4H,H]
    const float* b_ih  = (const float*)d_in[8];      // [4H]
    const float* b_hh  = (const float*)d_in[9];      // [4H]
    const float* W_out = (const float*)d_in[10];     // [V,H]
    const float* b_out = (const float*)d_in[11];     // [V]
    float* out = (float*)d_out;                      // [B,T,V]

    float *p_seq, *p_xg, *p_hidden;
    cudaGetSymbolAddress((void**)&p_seq,    g_seq);
    cudaGetSymbolAddress((void**)&p_xg,     g_xg);
    cudaGetSymbolAddress((void**)&p_hidden, g_hidden);
    __nv_bfloat16 *p_sseq, *p_Wih, *p_hid, *p_Wout;
    cudaGetSymbolAddress((void**)&p_sseq, s_seq);
    cudaGetSymbolAddress((void**)&p_Wih,  s_Wih);
    cudaGetSymbolAddress((void**)&p_hid,  s_hid);
    cudaGetSymbolAddress((void**)&p_Wout, s_Wout);

    cudaFuncSetAttribute(gemm_hmma, cudaFuncAttributeMaxDynamicSharedMemorySize, SMEM_HM);

    const int TPB = 256;
    auto nb = [](size_t n, int t) { return (int)((n + t - 1) / t); };

    // 1) x0 = features @ W_in^T + b_in (exact fp32) -> g_seq rows [0,128)
    {
        dim3 grid(Ed / 32, Bb / 32);   // (16,4) = 64 CTAs
        gemm_tn<32, 32, 8, 2, 2><<<grid, 256>>>(
            features, W_in, b_in, p_seq, Bb, Ed, Fdim);
    }

    // 2) gather embeddings for t = 1..T-1
    gather_emb<<<(Tl - 1) * Bb, 128>>>(seqs, emb);

    // 3) split seq / W_ih, xg GEMM  [5120, 2048]
    split3<0><<<nb((size_t)BT * Ed, TPB), TPB>>>(p_seq, p_sseq, BT, Ed);
    split3<1><<<nb((size_t)H4 * Ed, TPB), TPB>>>(W_ih, p_Wih, H4, Ed);
    {
        dim3 grid(H4 / 256, BT / 128);   // (8,40)
        gemm_hmma<<<grid, 512, SMEM_HM>>>(p_sseq, p_Wih, b_ih, p_xg, BT, H4, K3E);
    }

    // 4) init h, c = 0
    init_state<<<(Bb * Hd + 255) / 256, 256>>>();

    // 5) recurrence: 40 fused steps
    for (int t = 0; t < Tl; t++) {
        dim3 grid(32, 4);
        lstm_step<<<grid, 256>>>(W_hh, b_hh, p_xg + (size_t)t * Bb * H4, t);
    }

    // 6) split hiddens / W_out, output GEMM  [5120, 10000]
    split3<0><<<nb((size_t)BT * Hd, TPB), TPB>>>(p_hidden, p_hid, BT, Hd);
    split3<1><<<nb((size_t)Vd * Hd, TPB), TPB>>>(W_out, p_Wout, Vd, Hd);
    {
        dim3 grid((Vd + 255) / 256, BT / 128);   // (40,40)
        gemm_hmma<<<grid, 512, SMEM_HM>>>(p_hid, p_Wout, b_out, out, BT, Vd, K3E);
    }
}

// round 5
// speedup vs baseline: 1.2126x; 1.2126x over previous
#include <cuda_runtime.h>
#include <cuda_bf16.h>
#include <cuda_fp16.h>
#include <cstdint>

// Problem constants
#define Bb   128
#define Fdim 1536
#define Ed   512
#define Hd   512
#define H4   2048
#define Vd   10000
#define Tl   40
#define BT   (Bb*Tl)     // 5120
#define K3E  (3*Ed)      // 1536
#define K2E  (2*Ed)      // 1024

// ---------------- scratch (static device memory) -----------------------------
__device__ float g_seq[(size_t)BT * Ed];        // [T*B, E]  row r = t*B + b
__device__ float g_xg[(size_t)BT * H4];         // [T*B, 4H]
__device__ float g_hidden[(size_t)BT * Hd];     // [B*T, H]  row r = b*T + t
__device__ float g_hbuf[2][Bb * Hd];
__device__ float g_c[Bb * Hd];

// split operand buffers
__device__ __align__(16) __nv_bfloat16 s_seq [(size_t)BT * K3E];   // bf16 3-split
__device__ __align__(16) __nv_bfloat16 s_Wih [(size_t)H4 * K3E];
__device__ __align__(16) __half        s_hid [(size_t)BT * K2E];   // fp16 2-split
__device__ __align__(16) __half        s_Wout[(size_t)Vd * K2E];

// grid barrier state
__device__ unsigned int g_bar_cnt = 0;
__device__ volatile unsigned int g_bar_gen = 0;

__device__ __forceinline__ float sigmoidf_(float x) { return 1.0f / (1.0f + __expf(-x)); }

__device__ __forceinline__ uint32_t smem_u32(const void* p) {
    return (uint32_t)__cvta_generic_to_shared(p);
}

// ---------------- exact fp32 SIMT GEMM (for x0): C = A @ B^T + bias -----------
template<int BM, int BN, int BK, int TM, int TN>
__global__ void gemm_tn(const float* __restrict__ A,
                        const float* __restrict__ Bw,
                        const float* __restrict__ bias,
                        float* __restrict__ C,
                        int M, int N, int K)
{
    constexpr int NT = (BM / TM) * (BN / TN);
    static_assert(NT == 256, "need 256 threads");
    __shared__ float As[BK][BM];
    __shared__ float Bs[BK][BN];

    const int m0 = blockIdx.y * BM;
    const int n0 = blockIdx.x * BN;
    const int tid = threadIdx.x;
    constexpr int NTX = BN / TN;
    const int tc = tid % NTX;
    const int tr = tid / NTX;

    float acc[TM][TN];
    #pragma unroll
    for (int i = 0; i < TM; i++)
        #pragma unroll
        for (int j = 0; j < TN; j++) acc[i][j] = 0.0f;

    constexpr int A_LD4 = BM * BK / 4;
    constexpr int B_LD4 = BN * BK / 4;
    constexpr int K4 = BK / 4;

    for (int k0 = 0; k0 < K; k0 += BK) {
        #pragma unroll
        for (int i = tid; i < A_LD4; i += NT) {
            int row = i / K4;
            int kc  = (i % K4) * 4;
            float4 v = *reinterpret_cast<const float4*>(
                A + (size_t)(m0 + row) * K + k0 + kc);
            As[kc + 0][row] = v.x; As[kc + 1][row] = v.y;
            As[kc + 2][row] = v.z; As[kc + 3][row] = v.w;
        }
        #pragma unroll
        for (int i = tid; i < B_LD4; i += NT) {
            int row = i / K4;
            int kc  = (i % K4) * 4;
            float4 v = *reinterpret_cast<const float4*>(
                Bw + (size_t)(n0 + row) * K + k0 + kc);
            Bs[kc + 0][row] = v.x; Bs[kc + 1][row] = v.y;
            Bs[kc + 2][row] = v.z; Bs[kc + 3][row] = v.w;
        }
        __syncthreads();

        #pragma unroll
        for (int k = 0; k < BK; k++) {
            float ra[TM], rb[TN];
            #pragma unroll
            for (int i = 0; i < TM; i++) ra[i] = As[k][tr * TM + i];
            #pragma unroll
            for (int j = 0; j < TN; j++) rb[j] = Bs[k][tc * TN + j];
            #pragma unroll
            for (int i = 0; i < TM; i++)
                #pragma unroll
                for (int j = 0; j < TN; j++)
                    acc[i][j] = fmaf(ra[i], rb[j], acc[i][j]);
        }
        __syncthreads();
    }

    #pragma unroll
    for (int i = 0; i < TM; i++) {
        int m = m0 + tr * TM + i;
        #pragma unroll
        for (int j = 0; j < TN; j++) {
            int n = n0 + tc * TN + j;
            C[(size_t)m * N + n] = acc[i][j] + bias[n];
        }
    }
}

// ---------------- tensor-core GEMM: C = A @ B^T + bias (round-2 config) -------
// HALF=0: bf16 operands; HALF=1: fp16 operands. Elements passed as uint16_t.
// Tile 128x128x32, 256 threads (8 warps, warp 64x32), 2-stage cp.async.
#define STRIDEg 40   // smem row stride in elems (80B) -> conflict-free ldmatrix

template<int HALF>
__global__ void __launch_bounds__(256)
gemm_mma(const uint16_t* __restrict__ A,
         const uint16_t* __restrict__ B,
         const float* __restrict__ bias,
         float* __restrict__ C,
         int M, int N, int K)
{
    __shared__ __align__(16) uint16_t As[2][128 * STRIDEg];
    __shared__ __align__(16) uint16_t Bs[2][128 * STRIDEg];

    const int tid  = threadIdx.x;
    const int warp = tid >> 5, lane = tid & 31;
    const int wm = (warp >> 2) * 64;
    const int wn = (warp & 3) * 32;
    const int m0 = blockIdx.y * 128, n0 = blockIdx.x * 128;

    float acc[4][4][4];
    #pragma unroll
    for (int i = 0; i < 4; i++)
        #pragma unroll
        for (int j = 0; j < 4; j++)
            #pragma unroll
            for (int r = 0; r < 4; r++) acc[i][j][r] = 0.0f;

    const int KT = K / 32;

    auto load_tile = [&](int buf, int kt) {
        const int k0 = kt * 32;
        #pragma unroll
        for (int it = 0; it < 2; it++) {
            int task = tid + it * 256;
            int r = task >> 2, c = task & 3;
            uint32_t dst = smem_u32(&As[buf][r * STRIDEg + c * 8]);
            const void* src = A + (size_t)(m0 + r) * K + k0 + c * 8;
            asm volatile("cp.async.cg.shared.global [%0],[%1],16;\n" :: "r"(dst), "l"(src));
        }
        #pragma unroll
        for (int it = 0; it < 2; it++) {
            int task = tid + it * 256;
            int r = task >> 2, c = task & 3;
            if (n0 + r < N) {
                uint32_t dst = smem_u32(&Bs[buf][r * STRIDEg + c * 8]);
                const void* src = B + (size_t)(n0 + r) * K + k0 + c * 8;
                asm volatile("cp.async.cg.shared.global [%0],[%1],16;\n" :: "r"(dst), "l"(src));
            }
        }
        asm volatile("cp.async.commit_group;\n");
    };

    load_tile(0, 0);
    int buf = 0;
    for (int kt = 0; kt < KT; kt++) {
        if (kt + 1 < KT) {
            load_tile(buf ^ 1, kt + 1);
            asm volatile("cp.async.wait_group 1;\n");
        } else {
            asm volatile("cp.async.wait_group 0;\n");
        }
        __syncthreads();

        #pragma unroll
        for (int kk = 0; kk < 32; kk += 16) {
            uint32_t afr[4][4];
            #pragma unroll
            for (int i = 0; i < 4; i++) {
                int row = wm + i * 16 + (lane & 15);
                int col = kk + (lane >> 4) * 8;
                uint32_t addr = smem_u32(&As[buf][row * STRIDEg + col]);
                asm volatile("ldmatrix.sync.aligned.m8n8.x4.shared.b16 {%0,%1,%2,%3},[%4];"
                             : "=r"(afr[i][0]), "=r"(afr[i][1]), "=r"(afr[i][2]), "=r"(afr[i][3])
                             : "r"(addr));
            }
            uint32_t bfr[4][2];
            #pragma unroll
            for (int j = 0; j < 2; j++) {
                int grp = lane >> 3;
                int row = wn + j * 16 + (grp >> 1) * 8 + (lane & 7);
                int col = kk + (grp & 1) * 8;
                uint32_t addr = smem_u32(&Bs[buf][row * STRIDEg + col]);
                uint32_t r0, r1, r2, r3;
                asm volatile("ldmatrix.sync.aligned.m8n8.x4.shared.b16 {%0,%1,%2,%3},[%4];"
                             : "=r"(r0), "=r"(r1), "=r"(r2), "=r"(r3) : "r"(addr));
                bfr[j * 2][0] = r0; bfr[j * 2][1] = r1;
                bfr[j * 2 + 1][0] = r2; bfr[j * 2 + 1][1] = r3;
            }
            #pragma unroll
            for (int i = 0; i < 4; i++)
                #pragma unroll
                for (int j = 0; j < 4; j++) {
                    if constexpr (HALF) {
                        asm volatile(
                            "mma.sync.aligned.m16n8k16.row.col.f32.f16.f16.f32 "
                            "{%0,%1,%2,%3},{%4,%5,%6,%7},{%8,%9},{%0,%1,%2,%3};"
                            : "+f"(acc[i][j][0]), "+f"(acc[i][j][1]),
                              "+f"(acc[i][j][2]), "+f"(acc[i][j][3])
                            : "r"(afr[i][0]), "r"(afr[i][1]), "r"(afr[i][2]), "r"(afr[i][3]),
                              "r"(bfr[j][0]), "r"(bfr[j][1]));
                    } else {
                        asm volatile(
                            "mma.sync.aligned.m16n8k16.row.col.f32.bf16.bf16.f32 "
                            "{%0,%1,%2,%3},{%4,%5,%6,%7},{%8,%9},{%0,%1,%2,%3};"
                            : "+f"(acc[i][j][0]), "+f"(acc[i][j][1]),
                              "+f"(acc[i][j][2]), "+f"(acc[i][j][3])
                            : "r"(afr[i][0]), "r"(afr[i][1]), "r"(afr[i][2]), "r"(afr[i][3]),
                              "r"(bfr[j][0]), "r"(bfr[j][1]));
                    }
                }
        }
        __syncthreads();
        buf ^= 1;
    }

    const int mrow = lane >> 2, nc2 = (lane & 3) * 2;
    #pragma unroll
    for (int i = 0; i < 4; i++) {
        int gm = m0 + wm + i * 16 + mrow;
        float* Crow0 = C + (size_t)gm * N;
        float* Crow1 = C + (size_t)(gm + 8) * N;
        #pragma unroll
        for (int j = 0; j < 4; j++) {
            int gn = n0 + wn + j * 8 + nc2;
            if (gn < N) {
                float bv = bias[gn];
                Crow0[gn] = acc[i][j][0] + bv;
                Crow1[gn] = acc[i][j][2] + bv;
            }
            if (gn + 1 < N) {
                float bv = bias[gn + 1];
                Crow0[gn + 1] = acc[i][j][1] + bv;
                Crow1[gn + 1] = acc[i][j][3] + bv;
            }
        }
    }
}

// ---------------- split kernels ------------------------------------------------
// bf16 3-split:  A-side [hi|hi|lo], B-side [hi|lo|hi]
template<int MODE_B>
__global__ void split3(const float* __restrict__ X, __nv_bfloat16* __restrict__ Y,
                       int M, int K)
{
    size_t i = (size_t)blockIdx.x * blockDim.x + threadIdx.x;
    size_t total = (size_t)M * K;
    if (i >= total) return;
    int m = (int)(i / K), k = (int)(i % K);
    float x = X[i];
    __nv_bfloat16 hi = __float2bfloat16_rn(x);
    __nv_bfloat16 lo = __float2bfloat16_rn(x - __bfloat162float(hi));
    __nv_bfloat16* row = Y + (size_t)m * (3 * K);
    if (MODE_B) { row[k] = hi; row[K + k] = lo; row[2 * K + k] = hi; }
    else        { row[k] = hi; row[K + k] = hi; row[2 * K + k] = lo; }
}

// fp16 2-split: DUP==0 -> [hi|lo] (A-side), DUP==1 -> [hi|hi] (B-side)
template<int DUP>
__global__ void split2h(const float* __restrict__ X, __half* __restrict__ Y,
                        int M, int K)
{
    size_t i = (size_t)blockIdx.x * blockDim.x + threadIdx.x;
    size_t total = (size_t)M * K;
    if (i >= total) return;
    int m = (int)(i / K), k = (int)(i % K);
    float x = X[i];
    __half hi = __float2half_rn(x);
    __half* row = Y + (size_t)m * (2 * K);
    row[k] = hi;
    if (DUP) row[K + k] = hi;
    else     row[K + k] = __float2half_rn(x - __half2float(hi));
}

// ---------------- gather word embeddings into g_seq rows t>=1 -----------------
__global__ void gather_emb(const int* __restrict__ seqs,
                           const float* __restrict__ emb)
{
    int bid = blockIdx.x;
    int t1  = bid / Bb;
    int b   = bid % Bb;
    int word = seqs[b * (Tl - 1) + t1];
    const float4* src = reinterpret_cast<const float4*>(emb + (size_t)word * Ed);
    float4* dst = reinterpret_cast<float4*>(g_seq + (size_t)((t1 + 1) * Bb + b) * Ed);
    for (int i = threadIdx.x; i < Ed / 4; i += blockDim.x) dst[i] = src[i];
}

// ---------------- persistent LSTM recurrence ------------------------------------
// grid = (32, 4) = 128 CTAs (all co-resident: 128 < 148 SMs), 256 threads.
// CTA (jt, bt): 32 batch rows x 16 j's x 4 gates. One grid barrier per step
// (h double-buffered; c is CTA-private read-modify-write).
__device__ __forceinline__ void grid_sync_128()
{
    __syncthreads();
    if (threadIdx.x == 0) {
        unsigned gen = g_bar_gen;
        __threadfence();
        if (atomicAdd(&g_bar_cnt, 1u) == 127u) {
            g_bar_cnt = 0;
            __threadfence();
            g_bar_gen = gen + 1;
        } else {
            while (g_bar_gen == gen) __nanosleep(32);
            __threadfence();
        }
    }
    __syncthreads();
}

__global__ void __launch_bounds__(256, 1)
lstm_persistent(const float* __restrict__ Whh,   // [4H, H]
                const float* __restrict__ bhh)   // [4H]
{
    __shared__ float As2[32][34];   // [k][m(b)]  stride 34 -> aligned float2
    __shared__ float Bs2[32][68];   // [k][n]     stride 68 -> aligned float4
    __shared__ float Gs [32][65];   // gates [b][n]

    const int tid = threadIdx.x;
    const int jt = blockIdx.x;           // 0..31
    const int b0 = blockIdx.y * 32;      // batch origin
    const int tr = tid >> 4, tc = tid & 15;

    // zero this CTA's slices of c and hbuf[0]
    #pragma unroll
    for (int it = 0; it < 2; it++) {
        int task = tid + it * 256;
        int bl = task >> 4, jj = task & 15;
        size_t idx = (size_t)(b0 + bl) * Hd + jt * 16 + jj;
        g_c[idx] = 0.0f;
        g_hbuf[0][idx] = 0.0f;
    }
    grid_sync_128();

    for (int t = 0; t < Tl; t++) {
        const float* hin  = g_hbuf[t & 1];
        float*       hout = g_hbuf[(t + 1) & 1];
        const float* xg_t = g_xg + (size_t)t * Bb * H4;

        float acc[2][4];
        #pragma unroll
        for (int i = 0; i < 2; i++)
            #pragma unroll
            for (int j = 0; j < 4; j++) acc[i][j] = 0.0f;

        for (int kc = 0; kc < Hd; kc += 32) {
            {   // h tile: 32 b x 32 k
                int r = tid >> 3, c = tid & 7;
                float4 v = *reinterpret_cast<const float4*>(
                    hin + (size_t)(b0 + r) * Hd + kc + c * 4);
                As2[c * 4 + 0][r] = v.x; As2[c * 4 + 1][r] = v.y;
                As2[c * 4 + 2][r] = v.z; As2[c * 4 + 3][r] = v.w;
            }
            #pragma unroll
            for (int it = 0; it < 2; it++) {   // W tile: 64 n x 32 k
                int task = tid + it * 256;
                int r = task >> 3, c = task & 7;
                int grow = (r >> 4) * Hd + jt * 16 + (r & 15);
                float4 v = *reinterpret_cast<const float4*>(
                    Whh + (size_t)grow * Hd + kc + c * 4);
                Bs2[c * 4 + 0][r] = v.x; Bs2[c * 4 + 1][r] = v.y;
                Bs2[c * 4 + 2][r] = v.z; Bs2[c * 4 + 3][r] = v.w;
            }
            __syncthreads();

            #pragma unroll
            for (int k = 0; k < 32; k++) {
                float2 ra = *reinterpret_cast<const float2*>(&As2[k][tr * 2]);
                float4 rb = *reinterpret_cast<const float4*>(&Bs2[k][tc * 4]);
                acc[0][0] = fmaf(ra.x, rb.x, acc[0][0]);
                acc[0][1] = fmaf(ra.x, rb.y, acc[0][1]);
                acc[0][2] = fmaf(ra.x, rb.z, acc[0][2]);
                acc[0][3] = fmaf(ra.x, rb.w, acc[0][3]);
                acc[1][0] = fmaf(ra.y, rb.x, acc[1][0]);
                acc[1][1] = fmaf(ra.y, rb.y, acc[1][1]);
                acc[1][2] = fmaf(ra.y, rb.z, acc[1][2]);
                acc[1][3] = fmaf(ra.y, rb.w, acc[1][3]);
            }
            __syncthreads();
        }

        #pragma unroll
        for (int i = 0; i < 2; i++) {
            int m = tr * 2 + i;
            #pragma unroll
            for (int j = 0; j < 4; j++) {
                int n = tc * 4 + j;
                int gcol = (n >> 4) * Hd + jt * 16 + (n & 15);
                Gs[m][n] = acc[i][j] + xg_t[(size_t)(b0 + m) * H4 + gcol] + bhh[gcol];
            }
        }
        __syncthreads();

        #pragma unroll
        for (int it = 0; it < 2; it++) {
            int task = tid + it * 256;
            int bl = task >> 4, jj = task & 15;
            float ig = sigmoidf_(Gs[bl][jj]);
            float fg = sigmoidf_(Gs[bl][16 + jj]);
            float gg = tanhf(Gs[bl][32 + jj]);
            float og = sigmoidf_(Gs[bl][48 + jj]);
            size_t idx = (size_t)(b0 + bl) * Hd + jt * 16 + jj;
            float c = fmaf(fg, g_c[idx], ig * gg);
            g_c[idx] = c;
            float h = og * tanhf(c);
            hout[idx] = h;
            g_hidden[((size_t)(b0 + bl) * Tl + t) * Hd + jt * 16 + jj] = h;
        }
        grid_sync_128();
    }
}

// ---------------- launch --------------------------------------------------------
extern "C" void kernel_launch(void* const* d_in, const int* in_sizes, int n_in,
                              void* d_out, int out_size)
{
    const float* features = (const float*)d_in[0];   // [B,F]
    const int*   seqs     = (const int*)  d_in[1];   // [B,T-1]
    const float* W_in  = (const float*)d_in[3];      // [E,F]
    const float* b_in  = (const float*)d_in[4];      // [E]
    const float* emb   = (const float*)d_in[5];      // [V,E]
    const float* W_ih  = (const float*)d_in[6];      // [4H,E]
    const float* W_hh  = (const float*)d_in[7];      // [4H,H]
    const float* b_ih  = (const float*)d_in[8];      // [4H]
    const float* b_hh  = (const float*)d_in[9];      // [4H]
    const float* W_out = (const float*)d_in[10];     // [V,H]
    const float* b_out = (const float*)d_in[11];     // [V]
    float* out = (float*)d_out;                      // [B,T,V]

    float *p_seq, *p_xg, *p_hidden;
    cudaGetSymbolAddress((void**)&p_seq,    g_seq);
    cudaGetSymbolAddress((void**)&p_xg,     g_xg);
    cudaGetSymbolAddress((void**)&p_hidden, g_hidden);
    __nv_bfloat16 *p_sseq, *p_Wih;
    __half *p_hid, *p_Wout;
    cudaGetSymbolAddress((void**)&p_sseq, s_seq);
    cudaGetSymbolAddress((void**)&p_Wih,  s_Wih);
    cudaGetSymbolAddress((void**)&p_hid,  s_hid);
    cudaGetSymbolAddress((void**)&p_Wout, s_Wout);

    const int TPB = 256;
    auto nb = [](size_t n, int t) { return (int)((n + t - 1) / t); };

    // 1) x0 = features @ W_in^T + b_in (exact fp32) -> g_seq rows [0,128)
    {
        dim3 grid(Ed / 32, Bb / 32);   // (16,4) = 64 CTAs
        gemm_tn<32, 32, 8, 2, 2><<<grid, 256>>>(
            features, W_in, b_in, p_seq, Bb, Ed, Fdim);
    }

    // 2) gather embeddings for t = 1..T-1
    gather_emb<<<(Tl - 1) * Bb, 128>>>(seqs, emb);

    // 3) split seq / W_ih (bf16 3-split), xg GEMM  [5120, 2048] K=1536
    split3<0><<<nb((size_t)BT * Ed, TPB), TPB>>>(p_seq, p_sseq, BT, Ed);
    split3<1><<<nb((size_t)H4 * Ed, TPB), TPB>>>(W_ih, p_Wih, H4, Ed);
    {
        dim3 grid(H4 / 128, BT / 128);   // (16,40)
        gemm_mma<0><<<grid, 256>>>((const uint16_t*)p_sseq, (const uint16_t*)p_Wih,
                                   b_ih, p_xg, BT, H4, K3E);
    }

    // 4) persistent recurrence (includes state init)
    {
        dim3 grid(32, 4);
        lstm_persistent<<<grid, 256>>>(W_hh, b_hh);
    }

    // 5) split hiddens / W_out (fp16 2-split), output GEMM [5120, 10000] K=1024
    split2h<0><<<nb((size_t)BT * Hd, TPB), TPB>>>(p_hidden, p_hid, BT, Hd);
    split2h<1><<<nb((size_t)Vd * Hd, TPB), TPB>>>(W_out, p_Wout, Vd, Hd);
    {
        dim3 grid((Vd + 127) / 128, BT / 128);   // (79,40)
        gemm_mma<1><<<grid, 256>>>((const uint16_t*)p_hid, (const uint16_t*)p_Wout,
                                   b_out, out, BT, Vd, K2E);
    }
}

// round 6
// speedup vs baseline: 1.4437x; 1.1906x over previous
#include <cuda_runtime.h>
#include <cuda_bf16.h>
#include <cuda_fp16.h>
#include <cstdint>

// Problem constants
#define Bb   128
#define Fdim 1536
#define Ed   512
#define Hd   512
#define H4   2048
#define Vd   10000
#define Tl   40
#define BT   (Bb*Tl)     // 5120
#define K2E  (2*Ed)      // 1024

// ---------------- scratch (static device memory) -----------------------------
__device__ float g_seq[(size_t)BT * Ed];        // [T*B, E]  row r = t*B + b
__device__ float g_xg[(size_t)BT * H4];         // [T*B, 4H]
__device__ float g_hbuf[2][Bb * Hd];
__device__ float g_c[Bb * Hd];

// fp16 operand buffers
__device__ __align__(16) __half s_seq [(size_t)BT * K2E];   // A of xg: [hi|lo]
__device__ __align__(16) __half s_Wih [(size_t)H4 * K2E];   // B of xg: [hi|hi]
__device__ __align__(16) __half s_hid [(size_t)BT * Ed];    // A of out: h fp16 (written by recurrence)
__device__ __align__(16) __half s_Wout[(size_t)Vd * Ed];    // B of out: fp16 convert

// grid barrier state
__device__ unsigned int g_bar_cnt = 0;
__device__ volatile unsigned int g_bar_gen = 0;

__device__ __forceinline__ float sigmoidf_(float x) { return 1.0f / (1.0f + __expf(-x)); }

__device__ __forceinline__ uint32_t smem_u32(const void* p) {
    return (uint32_t)__cvta_generic_to_shared(p);
}

// ---------------- exact fp32 SIMT GEMM (for x0): C = A @ B^T + bias -----------
template<int BM, int BN, int BK, int TM, int TN>
__global__ void gemm_tn(const float* __restrict__ A,
                        const float* __restrict__ Bw,
                        const float* __restrict__ bias,
                        float* __restrict__ C,
                        int M, int N, int K)
{
    constexpr int NT = (BM / TM) * (BN / TN);
    static_assert(NT == 256, "need 256 threads");
    __shared__ float As[BK][BM];
    __shared__ float Bs[BK][BN];

    const int m0 = blockIdx.y * BM;
    const int n0 = blockIdx.x * BN;
    const int tid = threadIdx.x;
    constexpr int NTX = BN / TN;
    const int tc = tid % NTX;
    const int tr = tid / NTX;

    float acc[TM][TN];
    #pragma unroll
    for (int i = 0; i < TM; i++)
        #pragma unroll
        for (int j = 0; j < TN; j++) acc[i][j] = 0.0f;

    constexpr int A_LD4 = BM * BK / 4;
    constexpr int B_LD4 = BN * BK / 4;
    constexpr int K4 = BK / 4;

    for (int k0 = 0; k0 < K; k0 += BK) {
        #pragma unroll
        for (int i = tid; i < A_LD4; i += NT) {
            int row = i / K4;
            int kc  = (i % K4) * 4;
            float4 v = *reinterpret_cast<const float4*>(
                A + (size_t)(m0 + row) * K + k0 + kc);
            As[kc + 0][row] = v.x; As[kc + 1][row] = v.y;
            As[kc + 2][row] = v.z; As[kc + 3][row] = v.w;
        }
        #pragma unroll
        for (int i = tid; i < B_LD4; i += NT) {
            int row = i / K4;
            int kc  = (i % K4) * 4;
            float4 v = *reinterpret_cast<const float4*>(
                Bw + (size_t)(n0 + row) * K + k0 + kc);
            Bs[kc + 0][row] = v.x; Bs[kc + 1][row] = v.y;
            Bs[kc + 2][row] = v.z; Bs[kc + 3][row] = v.w;
        }
        __syncthreads();

        #pragma unroll
        for (int k = 0; k < BK; k++) {
            float ra[TM], rb[TN];
            #pragma unroll
            for (int i = 0; i < TM; i++) ra[i] = As[k][tr * TM + i];
            #pragma unroll
            for (int j = 0; j < TN; j++) rb[j] = Bs[k][tc * TN + j];
            #pragma unroll
            for (int i = 0; i < TM; i++)
                #pragma unroll
                for (int j = 0; j < TN; j++)
                    acc[i][j] = fmaf(ra[i], rb[j], acc[i][j]);
        }
        __syncthreads();
    }

    #pragma unroll
    for (int i = 0; i < TM; i++) {
        int m = m0 + tr * TM + i;
        #pragma unroll
        for (int j = 0; j < TN; j++) {
            int n = n0 + tc * TN + j;
            C[(size_t)m * N + n] = acc[i][j] + bias[n];
        }
    }
}

// ---------------- fp16 HMMA GEMM: C = A @ B^T + bias ---------------------------
// A: [M, K] fp16 (M % 128 == 0), B: [N, K] fp16 (N ragged OK), K % 32 == 0.
// Tile 128x128x32, 256 threads (8 warps, warp 64x32), 3-stage cp.async pipe,
// dynamic smem, 2 CTAs/SM.
#define STRIDEg 40                       // smem row stride (elems) -> conflict-free
#define SA_ST   (128 * STRIDEg)          // 5120 elems per stage per matrix
#define NST     3
#define SMEM_MM (NST * 2 * SA_ST * 2)    // 61440 bytes

__global__ void __launch_bounds__(256, 2)
gemm_mma(const __half* __restrict__ A,
         const __half* __restrict__ B,
         const float* __restrict__ bias,
         float* __restrict__ C,
         int M, int N, int K)
{
    extern __shared__ __align__(16) uint16_t smbuf[];
    uint16_t* Asm = smbuf;                 // NST x SA_ST
    uint16_t* Bsm = smbuf + NST * SA_ST;   // NST x SA_ST

    const int tid  = threadIdx.x;
    const int warp = tid >> 5, lane = tid & 31;
    const int wm = (warp >> 2) * 64;
    const int wn = (warp & 3) * 32;
    const int m0 = blockIdx.y * 128, n0 = blockIdx.x * 128;
    const int KT = K / 32;

    float acc[4][4][4];
    #pragma unroll
    for (int i = 0; i < 4; i++)
        #pragma unroll
        for (int j = 0; j < 4; j++)
            #pragma unroll
            for (int r = 0; r < 4; r++) acc[i][j][r] = 0.0f;

    auto load_tile = [&](int buf, int kt) {
        const int k0 = kt * 32;
        #pragma unroll
        for (int it = 0; it < 2; it++) {
            int task = tid + it * 256;
            int r = task >> 2, c = task & 3;
            uint32_t dst = smem_u32(&Asm[buf * SA_ST + r * STRIDEg + c * 8]);
            const void* src = A + (size_t)(m0 + r) * K + k0 + c * 8;
            asm volatile("cp.async.cg.shared.global [%0],[%1],16;\n" :: "r"(dst), "l"(src));
        }
        #pragma unroll
        for (int it = 0; it < 2; it++) {
            int task = tid + it * 256;
            int r = task >> 2, c = task & 3;
            if (n0 + r < N) {
                uint32_t dst = smem_u32(&Bsm[buf * SA_ST + r * STRIDEg + c * 8]);
                const void* src = B + (size_t)(n0 + r) * K + k0 + c * 8;
                asm volatile("cp.async.cg.shared.global [%0],[%1],16;\n" :: "r"(dst), "l"(src));
            }
        }
        asm volatile("cp.async.commit_group;\n");
    };

    // prefetch 2 stages
    load_tile(0, 0);
    if (KT > 1) load_tile(1, 1);
    else        asm volatile("cp.async.commit_group;\n");

    int buf = 0;
    for (int ck = 0; ck < KT; ck++) {
        if (ck + 2 < KT) load_tile((buf + 2) % NST, ck + 2);
        else             asm volatile("cp.async.commit_group;\n");
        asm volatile("cp.async.wait_group 2;\n");
        __syncthreads();

        const uint16_t* as = Asm + buf * SA_ST;
        const uint16_t* bs = Bsm + buf * SA_ST;

        #pragma unroll
        for (int kk = 0; kk < 32; kk += 16) {
            uint32_t afr[4][4];
            #pragma unroll
            for (int i = 0; i < 4; i++) {
                int row = wm + i * 16 + (lane & 15);
                int col = kk + (lane >> 4) * 8;
                uint32_t addr = smem_u32(&as[row * STRIDEg + col]);
                asm volatile("ldmatrix.sync.aligned.m8n8.x4.shared.b16 {%0,%1,%2,%3},[%4];"
                             : "=r"(afr[i][0]), "=r"(afr[i][1]), "=r"(afr[i][2]), "=r"(afr[i][3])
                             : "r"(addr));
            }
            uint32_t bfr[4][2];
            #pragma unroll
            for (int j = 0; j < 2; j++) {
                int grp = lane >> 3;
                int row = wn + j * 16 + (grp >> 1) * 8 + (lane & 7);
                int col = kk + (grp & 1) * 8;
                uint32_t addr = smem_u32(&bs[row * STRIDEg + col]);
                uint32_t r0, r1, r2, r3;
                asm volatile("ldmatrix.sync.aligned.m8n8.x4.shared.b16 {%0,%1,%2,%3},[%4];"
                             : "=r"(r0), "=r"(r1), "=r"(r2), "=r"(r3) : "r"(addr));
                bfr[j * 2][0] = r0; bfr[j * 2][1] = r1;
                bfr[j * 2 + 1][0] = r2; bfr[j * 2 + 1][1] = r3;
            }
            #pragma unroll
            for (int i = 0; i < 4; i++)
                #pragma unroll
                for (int j = 0; j < 4; j++) {
                    asm volatile(
                        "mma.sync.aligned.m16n8k16.row.col.f32.f16.f16.f32 "
                        "{%0,%1,%2,%3},{%4,%5,%6,%7},{%8,%9},{%0,%1,%2,%3};"
                        : "+f"(acc[i][j][0]), "+f"(acc[i][j][1]),
                          "+f"(acc[i][j][2]), "+f"(acc[i][j][3])
                        : "r"(afr[i][0]), "r"(afr[i][1]), "r"(afr[i][2]), "r"(afr[i][3]),
                          "r"(bfr[j][0]), "r"(bfr[j][1]));
                }
        }
        __syncthreads();
        buf = (buf + 1) % NST;
    }

    const int mrow = lane >> 2, nc2 = (lane & 3) * 2;
    #pragma unroll
    for (int i = 0; i < 4; i++) {
        int gm = m0 + wm + i * 16 + mrow;
        float* Crow0 = C + (size_t)gm * N;
        float* Crow1 = C + (size_t)(gm + 8) * N;
        #pragma unroll
        for (int j = 0; j < 4; j++) {
            int gn = n0 + wn + j * 8 + nc2;
            if (gn < N) {
                float bv = bias[gn];
                Crow0[gn] = acc[i][j][0] + bv;
                Crow1[gn] = acc[i][j][2] + bv;
            }
            if (gn + 1 < N) {
                float bv = bias[gn + 1];
                Crow0[gn + 1] = acc[i][j][1] + bv;
                Crow1[gn + 1] = acc[i][j][3] + bv;
            }
        }
    }
}

// ---------------- split / convert kernels ---------------------------------------
// fp16 2-split: DUP==0 -> [hi|lo] (A-side), DUP==1 -> [hi|hi] (B-side)
template<int DUP>
__global__ void split2h(const float* __restrict__ X, __half* __restrict__ Y,
                        int M, int K)
{
    size_t i = (size_t)blockIdx.x * blockDim.x + threadIdx.x;
    size_t total = (size_t)M * K;
    if (i >= total) return;
    int m = (int)(i / K), k = (int)(i % K);
    float x = X[i];
    __half hi = __float2half_rn(x);
    __half* row = Y + (size_t)m * (2 * K);
    row[k] = hi;
    if (DUP) row[K + k] = hi;
    else     row[K + k] = __float2half_rn(x - __half2float(hi));
}

// straight fp32 -> fp16 convert
__global__ void tofp16(const float* __restrict__ X, __half* __restrict__ Y, size_t total)
{
    size_t i = (size_t)blockIdx.x * blockDim.x + threadIdx.x;
    if (i < total) Y[i] = __float2half_rn(X[i]);
}

// ---------------- gather word embeddings into g_seq rows t>=1 -----------------
__global__ void gather_emb(const int* __restrict__ seqs,
                           const float* __restrict__ emb)
{
    int bid = blockIdx.x;
    int t1  = bid / Bb;
    int b   = bid % Bb;
    int word = seqs[b * (Tl - 1) + t1];
    const float4* src = reinterpret_cast<const float4*>(emb + (size_t)word * Ed);
    float4* dst = reinterpret_cast<float4*>(g_seq + (size_t)((t1 + 1) * Bb + b) * Ed);
    for (int i = threadIdx.x; i < Ed / 4; i += blockDim.x) dst[i] = src[i];
}

// ---------------- persistent LSTM recurrence ------------------------------------
__device__ __forceinline__ void grid_sync_128()
{
    __syncthreads();
    if (threadIdx.x == 0) {
        unsigned gen = g_bar_gen;
        __threadfence();
        if (atomicAdd(&g_bar_cnt, 1u) == 127u) {
            g_bar_cnt = 0;
            __threadfence();
            g_bar_gen = gen + 1;
        } else {
            while (g_bar_gen == gen) __nanosleep(32);
            __threadfence();
        }
    }
    __syncthreads();
}

__global__ void __launch_bounds__(256, 1)
lstm_persistent(const float* __restrict__ Whh,   // [4H, H]
                const float* __restrict__ bhh)   // [4H]
{
    __shared__ float As2[32][34];
    __shared__ float Bs2[32][68];
    __shared__ float Gs [32][65];

    const int tid = threadIdx.x;
    const int jt = blockIdx.x;           // 0..31
    const int b0 = blockIdx.y * 32;      // batch origin
    const int tr = tid >> 4, tc = tid & 15;

    #pragma unroll
    for (int it = 0; it < 2; it++) {
        int task = tid + it * 256;
        int bl = task >> 4, jj = task & 15;
        size_t idx = (size_t)(b0 + bl) * Hd + jt * 16 + jj;
        g_c[idx] = 0.0f;
        g_hbuf[0][idx] = 0.0f;
    }
    grid_sync_128();

    for (int t = 0; t < Tl; t++) {
        const float* hin  = g_hbuf[t & 1];
        float*       hout = g_hbuf[(t + 1) & 1];
        const float* xg_t = g_xg + (size_t)t * Bb * H4;

        float acc[2][4];
        #pragma unroll
        for (int i = 0; i < 2; i++)
            #pragma unroll
            for (int j = 0; j < 4; j++) acc[i][j] = 0.0f;

        for (int kc = 0; kc < Hd; kc += 32) {
            {
                int r = tid >> 3, c = tid & 7;
                float4 v = *reinterpret_cast<const float4*>(
                    hin + (size_t)(b0 + r) * Hd + kc + c * 4);
                As2[c * 4 + 0][r] = v.x; As2[c * 4 + 1][r] = v.y;
                As2[c * 4 + 2][r] = v.z; As2[c * 4 + 3][r] = v.w;
            }
            #pragma unroll
            for (int it = 0; it < 2; it++) {
                int task = tid + it * 256;
                int r = task >> 3, c = task & 7;
                int grow = (r >> 4) * Hd + jt * 16 + (r & 15);
                float4 v = *reinterpret_cast<const float4*>(
                    Whh + (size_t)grow * Hd + kc + c * 4);
                Bs2[c * 4 + 0][r] = v.x; Bs2[c * 4 + 1][r] = v.y;
                Bs2[c * 4 + 2][r] = v.z; Bs2[c * 4 + 3][r] = v.w;
            }
            __syncthreads();

            #pragma unroll
            for (int k = 0; k < 32; k++) {
                float2 ra = *reinterpret_cast<const float2*>(&As2[k][tr * 2]);
                float4 rb = *reinterpret_cast<const float4*>(&Bs2[k][tc * 4]);
                acc[0][0] = fmaf(ra.x, rb.x, acc[0][0]);
                acc[0][1] = fmaf(ra.x, rb.y, acc[0][1]);
                acc[0][2] = fmaf(ra.x, rb.z, acc[0][2]);
                acc[0][3] = fmaf(ra.x, rb.w, acc[0][3]);
                acc[1][0] = fmaf(ra.y, rb.x, acc[1][0]);
                acc[1][1] = fmaf(ra.y, rb.y, acc[1][1]);
                acc[1][2] = fmaf(ra.y, rb.z, acc[1][2]);
                acc[1][3] = fmaf(ra.y, rb.w, acc[1][3]);
            }
            __syncthreads();
        }

        #pragma unroll
        for (int i = 0; i < 2; i++) {
            int m = tr * 2 + i;
            #pragma unroll
            for (int j = 0; j < 4; j++) {
                int n = tc * 4 + j;
                int gcol = (n >> 4) * Hd + jt * 16 + (n & 15);
                Gs[m][n] = acc[i][j] + xg_t[(size_t)(b0 + m) * H4 + gcol] + bhh[gcol];
            }
        }
        __syncthreads();

        #pragma unroll
        for (int it = 0; it < 2; it++) {
            int task = tid + it * 256;
            int bl = task >> 4, jj = task & 15;
            float ig = sigmoidf_(Gs[bl][jj]);
            float fg = sigmoidf_(Gs[bl][16 + jj]);
            float gg = tanhf(Gs[bl][32 + jj]);
            float og = sigmoidf_(Gs[bl][48 + jj]);
            size_t idx = (size_t)(b0 + bl) * Hd + jt * 16 + jj;
            float c = fmaf(fg, g_c[idx], ig * gg);
            g_c[idx] = c;
            float h = og * tanhf(c);
            hout[idx] = h;
            // h directly as fp16 into out-GEMM A operand, row r = b*T + t
            s_hid[((size_t)(b0 + bl) * Tl + t) * Hd + jt * 16 + jj] = __float2half_rn(h);
        }
        grid_sync_128();
    }
}

// ---------------- launch --------------------------------------------------------
extern "C" void kernel_launch(void* const* d_in, const int* in_sizes, int n_in,
                              void* d_out, int out_size)
{
    const float* features = (const float*)d_in[0];   // [B,F]
    const int*   seqs     = (const int*)  d_in[1];   // [B,T-1]
    const float* W_in  = (const float*)d_in[3];      // [E,F]
    const float* b_in  = (const float*)d_in[4];      // [E]
    const float* emb   = (const float*)d_in[5];      // [V,E]
    const float* W_ih  = (const float*)d_in[6];      // [4H,E]
    const float* W_hh  = (const float*)d_in[7];      // [4H,H]
    const float* b_ih  = (const float*)d_in[8];      // [4H]
    const float* b_hh  = (const float*)d_in[9];      // [4H]
    const float* W_out = (const float*)d_in[10];     // [V,H]
    const float* b_out = (const float*)d_in[11];     // [V]
    float* out = (float*)d_out;                      // [B,T,V]

    float *p_seq, *p_xg;
    cudaGetSymbolAddress((void**)&p_seq, g_seq);
    cudaGetSymbolAddress((void**)&p_xg,  g_xg);
    __half *p_sseq, *p_Wih, *p_hid, *p_Wout;
    cudaGetSymbolAddress((void**)&p_sseq, s_seq);
    cudaGetSymbolAddress((void**)&p_Wih,  s_Wih);
    cudaGetSymbolAddress((void**)&p_hid,  s_hid);
    cudaGetSymbolAddress((void**)&p_Wout, s_Wout);

    cudaFuncSetAttribute(gemm_mma, cudaFuncAttributeMaxDynamicSharedMemorySize, SMEM_MM);

    const int TPB = 256;
    auto nb = [](size_t n, int t) { return (int)((n + t - 1) / t); };

    // 1) x0 = features @ W_in^T + b_in (exact fp32) -> g_seq rows [0,128)
    {
        dim3 grid(Ed / 32, Bb / 32);   // 64 CTAs
        gemm_tn<32, 32, 8, 2, 2><<<grid, 256>>>(
            features, W_in, b_in, p_seq, Bb, Ed, Fdim);
    }

    // 2) gather embeddings for t = 1..T-1
    gather_emb<<<(Tl - 1) * Bb, 128>>>(seqs, emb);

    // 3) fp16 2-split seq / W_ih, xg GEMM  [5120, 2048] K=1024
    split2h<0><<<nb((size_t)BT * Ed, TPB), TPB>>>(p_seq, p_sseq, BT, Ed);
    split2h<1><<<nb((size_t)H4 * Ed, TPB), TPB>>>(W_ih, p_Wih, H4, Ed);
    {
        dim3 grid(H4 / 128, BT / 128);   // (16,40)
        gemm_mma<<<grid, 256, SMEM_MM>>>(p_sseq, p_Wih, b_ih, p_xg, BT, H4, K2E);
    }

    // 4) persistent recurrence (inits state; writes h as fp16 to s_hid)
    {
        dim3 grid(32, 4);
        lstm_persistent<<<grid, 256>>>(W_hh, b_hh);
    }

    // 5) W_out -> fp16, output GEMM [5120, 10000] K=512 (single fp16)
    tofp16<<<nb((size_t)Vd * Hd, TPB), TPB>>>(W_out, p_Wout, (size_t)Vd * Hd);
    {
        dim3 grid((Vd + 127) / 128, BT / 128);   // (79,40)
        gemm_mma<<<grid, 256, SMEM_MM>>>(p_hid, p_Wout, b_out, out, BT, Vd, Ed);
    }
}

// round 8
// speedup vs baseline: 1.7232x; 1.1936x over previous
#include <cuda_runtime.h>
#include <cuda_bf16.h>
#include <cuda_fp16.h>
#include <cstdint>

// Problem constants
#define Bb   128
#define Fdim 1536
#define Ed   512
#define Hd   512
#define H4   2048
#define Vd   10000
#define Tl   40
#define BT   (Bb*Tl)     // 5120
#define K2E  (2*Ed)      // 1024

// ---------------- scratch (static device memory) -----------------------------
__device__ float g_seq[(size_t)BT * Ed];        // [T*B, E]  row r = t*B + b
__device__ float g_xg[(size_t)BT * H4];         // [T*B, 4H]
__device__ __align__(16) __half g_hfp16[Bb * Hd];  // recurrent h (fp16)

// fp16 operand buffers
__device__ __align__(16) __half s_seq [(size_t)BT * K2E];   // A of xg: [hi|lo]
__device__ __align__(16) __half s_Wih [(size_t)H4 * K2E];   // B of xg: [hi|hi]
__device__ __align__(16) __half s_hid [(size_t)BT * Ed];    // A of out GEMM (written by recurrence)
__device__ __align__(16) __half s_Wout[(size_t)Vd * Ed];    // B of out GEMM

// grid barrier state
__device__ unsigned int g_bar_cnt = 0;
__device__ volatile unsigned int g_bar_gen = 0;

__device__ __forceinline__ float sigmoidf_(float x) { return 1.0f / (1.0f + __expf(-x)); }

__device__ __forceinline__ uint32_t smem_u32(const void* p) {
    return (uint32_t)__cvta_generic_to_shared(p);
}

template<int N>
__device__ __forceinline__ void cp_wait() {
    asm volatile("cp.async.wait_group %0;\n" :: "n"(N));
}

// ---------------- exact fp32 SIMT GEMM (for x0): C = A @ B^T + bias -----------
template<int BM, int BN, int BK, int TM, int TN>
__global__ void gemm_tn(const float* __restrict__ A,
                        const float* __restrict__ Bw,
                        const float* __restrict__ bias,
                        float* __restrict__ C,
                        int M, int N, int K)
{
    constexpr int NT = (BM / TM) * (BN / TN);
    static_assert(NT == 256, "need 256 threads");
    __shared__ float As[BK][BM];
    __shared__ float Bs[BK][BN];

    const int m0 = blockIdx.y * BM;
    const int n0 = blockIdx.x * BN;
    const int tid = threadIdx.x;
    constexpr int NTX = BN / TN;
    const int tc = tid % NTX;
    const int tr = tid / NTX;

    float acc[TM][TN];
    #pragma unroll
    for (int i = 0; i < TM; i++)
        #pragma unroll
        for (int j = 0; j < TN; j++) acc[i][j] = 0.0f;

    constexpr int A_LD4 = BM * BK / 4;
    constexpr int B_LD4 = BN * BK / 4;
    constexpr int K4 = BK / 4;

    for (int k0 = 0; k0 < K; k0 += BK) {
        #pragma unroll
        for (int i = tid; i < A_LD4; i += NT) {
            int row = i / K4;
            int kc  = (i % K4) * 4;
            float4 v = *reinterpret_cast<const float4*>(
                A + (size_t)(m0 + row) * K + k0 + kc);
            As[kc + 0][row] = v.x; As[kc + 1][row] = v.y;
            As[kc + 2][row] = v.z; As[kc + 3][row] = v.w;
        }
        #pragma unroll
        for (int i = tid; i < B_LD4; i += NT) {
            int row = i / K4;
            int kc  = (i % K4) * 4;
            float4 v = *reinterpret_cast<const float4*>(
                Bw + (size_t)(n0 + row) * K + k0 + kc);
            Bs[kc + 0][row] = v.x; Bs[kc + 1][row] = v.y;
            Bs[kc + 2][row] = v.z; Bs[kc + 3][row] = v.w;
        }
        __syncthreads();

        #pragma unroll
        for (int k = 0; k < BK; k++) {
            float ra[TM], rb[TN];
            #pragma unroll
            for (int i = 0; i < TM; i++) ra[i] = As[k][tr * TM + i];
            #pragma unroll
            for (int j = 0; j < TN; j++) rb[j] = Bs[k][tc * TN + j];
            #pragma unroll
            for (int i = 0; i < TM; i++)
                #pragma unroll
                for (int j = 0; j < TN; j++)
                    acc[i][j] = fmaf(ra[i], rb[j], acc[i][j]);
        }
        __syncthreads();
    }

    #pragma unroll
    for (int i = 0; i < TM; i++) {
        int m = m0 + tr * TM + i;
        #pragma unroll
        for (int j = 0; j < TN; j++) {
            int n = n0 + tc * TN + j;
            C[(size_t)m * N + n] = acc[i][j] + bias[n];
        }
    }
}

// ---------------- fp16 HMMA GEMM: C = A @ B^T + bias ---------------------------
// Tile 128x128x32, 256 threads, 3-stage cp.async, dynamic smem, 2 CTAs/SM.
#define STRIDEg 40
#define SA_ST   (128 * STRIDEg)
#define NST     3
#define SMEM_MM (NST * 2 * SA_ST * 2)    // 61440 bytes

__global__ void __launch_bounds__(256, 2)
gemm_mma(const __half* __restrict__ A,
         const __half* __restrict__ B,
         const float* __restrict__ bias,
         float* __restrict__ C,
         int M, int N, int K)
{
    extern __shared__ __align__(16) uint16_t smbuf[];
    uint16_t* Asm = smbuf;
    uint16_t* Bsm = smbuf + NST * SA_ST;

    const int tid  = threadIdx.x;
    const int warp = tid >> 5, lane = tid & 31;
    const int wm = (warp >> 2) * 64;
    const int wn = (warp & 3) * 32;
    const int m0 = blockIdx.y * 128, n0 = blockIdx.x * 128;
    const int KT = K / 32;

    float acc[4][4][4];
    #pragma unroll
    for (int i = 0; i < 4; i++)
        #pragma unroll
        for (int j = 0; j < 4; j++)
            #pragma unroll
            for (int r = 0; r < 4; r++) acc[i][j][r] = 0.0f;

    auto load_tile = [&](int buf, int kt) {
        const int k0 = kt * 32;
        #pragma unroll
        for (int it = 0; it < 2; it++) {
            int task = tid + it * 256;
            int r = task >> 2, c = task & 3;
            uint32_t dst = smem_u32(&Asm[buf * SA_ST + r * STRIDEg + c * 8]);
            const void* src = A + (size_t)(m0 + r) * K + k0 + c * 8;
            asm volatile("cp.async.cg.shared.global [%0],[%1],16;\n" :: "r"(dst), "l"(src));
        }
        #pragma unroll
        for (int it = 0; it < 2; it++) {
            int task = tid + it * 256;
            int r = task >> 2, c = task & 3;
            if (n0 + r < N) {
                uint32_t dst = smem_u32(&Bsm[buf * SA_ST + r * STRIDEg + c * 8]);
                const void* src = B + (size_t)(n0 + r) * K + k0 + c * 8;
                asm volatile("cp.async.cg.shared.global [%0],[%1],16;\n" :: "r"(dst), "l"(src));
            }
        }
        asm volatile("cp.async.commit_group;\n");
    };

    load_tile(0, 0);
    if (KT > 1) load_tile(1, 1);
    else        asm volatile("cp.async.commit_group;\n");

    int buf = 0;
    for (int ck = 0; ck < KT; ck++) {
        if (ck + 2 < KT) load_tile((buf + 2) % NST, ck + 2);
        else             asm volatile("cp.async.commit_group;\n");
        cp_wait<2>();
        __syncthreads();

        const uint16_t* as = Asm + buf * SA_ST;
        const uint16_t* bs = Bsm + buf * SA_ST;

        #pragma unroll
        for (int kk = 0; kk < 32; kk += 16) {
            uint32_t afr[4][4];
            #pragma unroll
            for (int i = 0; i < 4; i++) {
                int row = wm + i * 16 + (lane & 15);
                int col = kk + (lane >> 4) * 8;
                uint32_t addr = smem_u32(&as[row * STRIDEg + col]);
                asm volatile("ldmatrix.sync.aligned.m8n8.x4.shared.b16 {%0,%1,%2,%3},[%4];"
                             : "=r"(afr[i][0]), "=r"(afr[i][1]), "=r"(afr[i][2]), "=r"(afr[i][3])
                             : "r"(addr));
            }
            uint32_t bfr[4][2];
            #pragma unroll
            for (int j = 0; j < 2; j++) {
                int grp = lane >> 3;
                int row = wn + j * 16 + (grp >> 1) * 8 + (lane & 7);
                int col = kk + (grp & 1) * 8;
                uint32_t addr = smem_u32(&bs[row * STRIDEg + col]);
                uint32_t r0, r1, r2, r3;
                asm volatile("ldmatrix.sync.aligned.m8n8.x4.shared.b16 {%0,%1,%2,%3},[%4];"
                             : "=r"(r0), "=r"(r1), "=r"(r2), "=r"(r3) : "r"(addr));
                bfr[j * 2][0] = r0; bfr[j * 2][1] = r1;
                bfr[j * 2 + 1][0] = r2; bfr[j * 2 + 1][1] = r3;
            }
            #pragma unroll
            for (int i = 0; i < 4; i++)
                #pragma unroll
                for (int j = 0; j < 4; j++) {
                    asm volatile(
                        "mma.sync.aligned.m16n8k16.row.col.f32.f16.f16.f32 "
                        "{%0,%1,%2,%3},{%4,%5,%6,%7},{%8,%9},{%0,%1,%2,%3};"
                        : "+f"(acc[i][j][0]), "+f"(acc[i][j][1]),
                          "+f"(acc[i][j][2]), "+f"(acc[i][j][3])
                        : "r"(afr[i][0]), "r"(afr[i][1]), "r"(afr[i][2]), "r"(afr[i][3]),
                          "r"(bfr[j][0]), "r"(bfr[j][1]));
                }
        }
        __syncthreads();
        buf = (buf + 1) % NST;
    }

    const int mrow = lane >> 2, nc2 = (lane & 3) * 2;
    #pragma unroll
    for (int i = 0; i < 4; i++) {
        int gm = m0 + wm + i * 16 + mrow;
        float* Crow0 = C + (size_t)gm * N;
        float* Crow1 = C + (size_t)(gm + 8) * N;
        #pragma unroll
        for (int j = 0; j < 4; j++) {
            int gn = n0 + wn + j * 8 + nc2;
            if (gn < N) {
                float bv = bias[gn];
                Crow0[gn] = acc[i][j][0] + bv;
                Crow1[gn] = acc[i][j][2] + bv;
            }
            if (gn + 1 < N) {
                float bv = bias[gn + 1];
                Crow0[gn + 1] = acc[i][j][1] + bv;
                Crow1[gn + 1] = acc[i][j][3] + bv;
            }
        }
    }
}

// ---------------- split / convert kernels ---------------------------------------
template<int DUP>
__global__ void split2h(const float* __restrict__ X, __half* __restrict__ Y,
                        int M, int K)
{
    size_t i = (size_t)blockIdx.x * blockDim.x + threadIdx.x;
    size_t total = (size_t)M * K;
    if (i >= total) return;
    int m = (int)(i / K), k = (int)(i % K);
    float x = X[i];
    __half hi = __float2half_rn(x);
    __half* row = Y + (size_t)m * (2 * K);
    row[k] = hi;
    if (DUP) row[K + k] = hi;
    else     row[K + k] = __float2half_rn(x - __half2float(hi));
}

__global__ void tofp16(const float* __restrict__ X, __half* __restrict__ Y, size_t total)
{
    size_t i = (size_t)blockIdx.x * blockDim.x + threadIdx.x;
    if (i < total) Y[i] = __float2half_rn(X[i]);
}

// ---------------- gather word embeddings into g_seq rows t>=1 -----------------
__global__ void gather_emb(const int* __restrict__ seqs,
                           const float* __restrict__ emb)
{
    int bid = blockIdx.x;
    int t1  = bid / Bb;
    int b   = bid % Bb;
    int word = seqs[b * (Tl - 1) + t1];
    const float4* src = reinterpret_cast<const float4*>(emb + (size_t)word * Ed);
    float4* dst = reinterpret_cast<float4*>(g_seq + (size_t)((t1 + 1) * Bb + b) * Ed);
    for (int i = threadIdx.x; i < Ed / 4; i += blockDim.x) dst[i] = src[i];
}

// ---------------- persistent tensor-core LSTM recurrence ------------------------
// 32 CTAs (one per 16-wide hidden slice), 256 threads (8 warps, warp tile 32x32).
// W_hh tile (64 gate rows x 512) held in smem fp16 for all 40 steps; h fp16 in
// global, cp.async 3-stage K-chunk pipeline (chunk 3 reuses stage 0); c in
// registers; gates exchanged via smem.
#define LCH   128                      // K per chunk
#define NCH   (Hd / LCH)               // 4
#define TSTR  136                      // chunk tile row stride (halves)
#define W_CH  (64 * TSTR)              // W chunk tile elems
#define H_STG (128 * TSTR)             // h stage elems
#define NHB   3
#define SMEM_LSTM ((NCH * W_CH + NHB * H_STG) * 2 + 128 * 68 * 4)  // 208896 B

__device__ __forceinline__ void grid_sync_n(unsigned int nctas)
{
    __threadfence();
    __syncthreads();
    if (threadIdx.x == 0) {
        unsigned gen = g_bar_gen;
        if (atomicAdd(&g_bar_cnt, 1u) == nctas - 1u) {
            g_bar_cnt = 0;
            __threadfence();
            g_bar_gen = gen + 1;
        } else {
            while (g_bar_gen == gen) __nanosleep(32);
            __threadfence();
        }
    }
    __syncthreads();
}

__global__ void __launch_bounds__(256, 1)
lstm_tc(const float* __restrict__ Whh,   // [4H, H]
        const float* __restrict__ bhh)   // [4H]
{
    extern __shared__ __align__(16) uint16_t lsm[];
    uint16_t* Ws = lsm;                          // NCH x 64 x TSTR
    uint16_t* Hb = lsm + NCH * W_CH;             // NHB x 128 x TSTR
    float*    Gs = (float*)(Hb + NHB * H_STG);   // 128 x 68

    const int tid  = threadIdx.x;
    const int warp = tid >> 5, lane = tid & 31;
    const int wm = (warp >> 1) * 32;   // 0,32,64,96
    const int wn = (warp & 1) * 32;    // 0,32
    const int jt = blockIdx.x;         // hidden slice

    // ---- load W_hh tile to smem as fp16 (once) ----
    // smem row r (0..63) = gate (r>>4), hidden col jt*16 + (r&15)
    #pragma unroll
    for (int it = 0; it < 32; it++) {
        int task = tid + it * 256;     // 0..8191, each = one float4
        int row = task >> 7;           // 64 rows x 128 float4/row
        int c4  = task & 127;
        int grow = (row >> 4) * Hd + jt * 16 + (row & 15);
        float4 v = *reinterpret_cast<const float4*>(Whh + (size_t)grow * Hd + c4 * 4);
        int ck = c4 >> 5;              // K chunk
        int kc = (c4 & 31) * 4;        // col within chunk (halves)
        __half2 h01 = __floats2half2_rn(v.x, v.y);
        __half2 h23 = __floats2half2_rn(v.z, v.w);
        uint16_t* dst = Ws + ck * W_CH + row * TSTR + kc;
        *reinterpret_cast<__half2*>(dst)     = h01;
        *reinterpret_cast<__half2*>(dst + 2) = h23;
    }

    // ---- per-thread cell state (8 cells: bl = tid>>4 + it*16, jj = tid&15) ----
    const int jj = tid & 15;
    float creg[8];
    #pragma unroll
    for (int i = 0; i < 8; i++) creg[i] = 0.0f;
    float bs[4];
    #pragma unroll
    for (int g = 0; g < 4; g++) bs[g] = bhh[g * Hd + jt * 16 + jj];

    // zero this CTA's h slice
    #pragma unroll
    for (int it = 0; it < 8; it++) {
        int bl = (tid >> 4) + it * 16;
        g_hfp16[bl * Hd + jt * 16 + jj] = __float2half_rn(0.0f);
    }
    grid_sync_n(32);

    // FIXED: full 128x128-half chunk = 2048 x 16B tasks (8 iterations)
    auto issue_h = [&](int stage, int ck) {
        #pragma unroll
        for (int it = 0; it < 8; it++) {
            int task = tid + it * 256;     // 0..2047
            int r  = task >> 4;            // 0..127
            int c8 = task & 15;            // 0..15 (x8 halves)
            uint32_t dst = smem_u32(&Hb[stage * H_STG + r * TSTR + c8 * 8]);
            const void* src = g_hfp16 + r * Hd + ck * LCH + c8 * 8;
            asm volatile("cp.async.cg.shared.global [%0],[%1],16;\n" :: "r"(dst), "l"(src));
        }
        asm volatile("cp.async.commit_group;\n");
    };

    for (int t = 0; t < Tl; t++) {
        const float* xg_t = g_xg + (size_t)t * Bb * H4;

        float acc[2][4][4];
        #pragma unroll
        for (int i = 0; i < 2; i++)
            #pragma unroll
            for (int j = 0; j < 4; j++)
                #pragma unroll
                for (int r = 0; r < 4; r++) acc[i][j][r] = 0.0f;

        issue_h(0, 0);
        issue_h(1, 1);
        issue_h(2, 2);

        #pragma unroll
        for (int ck = 0; ck < NCH; ck++) {
            // FIXED wait sequence: after chunk3 is issued inside ck==0,
            // pending groups at each wait are exactly {later stages}.
            if (ck == 0)      cp_wait<2>();
            else if (ck == 1) cp_wait<2>();
            else if (ck == 2) cp_wait<1>();
            else              cp_wait<0>();
            __syncthreads();

            const int stage = (ck == 3) ? 0 : ck;
            const uint16_t* hs = Hb + stage * H_STG;
            const uint16_t* ws = Ws + ck * W_CH;

            #pragma unroll
            for (int kk = 0; kk < LCH; kk += 16) {
                uint32_t afr[2][4];
                #pragma unroll
                for (int i = 0; i < 2; i++) {
                    int row = wm + i * 16 + (lane & 15);
                    int col = kk + (lane >> 4) * 8;
                    uint32_t addr = smem_u32(&hs[row * TSTR + col]);
                    asm volatile("ldmatrix.sync.aligned.m8n8.x4.shared.b16 {%0,%1,%2,%3},[%4];"
                                 : "=r"(afr[i][0]), "=r"(afr[i][1]), "=r"(afr[i][2]), "=r"(afr[i][3])
                                 : "r"(addr));
                }
                uint32_t bfr[4][2];
                #pragma unroll
                for (int j = 0; j < 2; j++) {
                    int grp = lane >> 3;
                    int row = wn + j * 16 + (grp >> 1) * 8 + (lane & 7);
                    int col = kk + (grp & 1) * 8;
                    uint32_t addr = smem_u32(&ws[row * TSTR + col]);
                    uint32_t r0, r1, r2, r3;
                    asm volatile("ldmatrix.sync.aligned.m8n8.x4.shared.b16 {%0,%1,%2,%3},[%4];"
                                 : "=r"(r0), "=r"(r1), "=r"(r2), "=r"(r3) : "r"(addr));
                    bfr[j * 2][0] = r0; bfr[j * 2][1] = r1;
                    bfr[j * 2 + 1][0] = r2; bfr[j * 2 + 1][1] = r3;
                }
                #pragma unroll
                for (int i = 0; i < 2; i++)
                    #pragma unroll
                    for (int j = 0; j < 4; j++) {
                        asm volatile(
                            "mma.sync.aligned.m16n8k16.row.col.f32.f16.f16.f32 "
                            "{%0,%1,%2,%3},{%4,%5,%6,%7},{%8,%9},{%0,%1,%2,%3};"
                            : "+f"(acc[i][j][0]), "+f"(acc[i][j][1]),
                              "+f"(acc[i][j][2]), "+f"(acc[i][j][3])
                            : "r"(afr[i][0]), "r"(afr[i][1]), "r"(afr[i][2]), "r"(afr[i][3]),
                              "r"(bfr[j][0]), "r"(bfr[j][1]));
                    }
            }
            __syncthreads();

            // FIXED: issue chunk 3 into stage 0 once stage 0 is fully consumed
            if (ck == 0) issue_h(0, 3);
        }

        // write gate pre-activations (h@W^T part) to smem
        const int mrow = lane >> 2, nc2 = (lane & 3) * 2;
        #pragma unroll
        for (int i = 0; i < 2; i++) {
            int r0 = wm + i * 16 + mrow;
            #pragma unroll
            for (int j = 0; j < 4; j++) {
                int col = wn + j * 8 + nc2;
                Gs[r0 * 68 + col]       = acc[i][j][0];
                Gs[r0 * 68 + col + 1]   = acc[i][j][1];
                Gs[(r0 + 8) * 68 + col]     = acc[i][j][2];
                Gs[(r0 + 8) * 68 + col + 1] = acc[i][j][3];
            }
        }
        __syncthreads();

        // cell update: 8 cells per thread
        #pragma unroll
        for (int it = 0; it < 8; it++) {
            int bl = (tid >> 4) + it * 16;
            const float* xr = xg_t + (size_t)bl * H4 + jt * 16 + jj;
            float gi = sigmoidf_(Gs[bl * 68 +  0 + jj] + xr[0 * Hd] + bs[0]);
            float gf = sigmoidf_(Gs[bl * 68 + 16 + jj] + xr[1 * Hd] + bs[1]);
            float gg = tanhf    (Gs[bl * 68 + 32 + jj] + xr[2 * Hd] + bs[2]);
            float go = sigmoidf_(Gs[bl * 68 + 48 + jj] + xr[3 * Hd] + bs[3]);
            float c = fmaf(gf, creg[it], gi * gg);
            creg[it] = c;
            __half h16 = __float2half_rn(go * tanhf(c));
            g_hfp16[bl * Hd + jt * 16 + jj] = h16;
            s_hid[((size_t)bl * Tl + t) * Hd + jt * 16 + jj] = h16;
        }
        grid_sync_n(32);
    }
}

// ---------------- launch --------------------------------------------------------
extern "C" void kernel_launch(void* const* d_in, const int* in_sizes, int n_in,
                              void* d_out, int out_size)
{
    const float* features = (const float*)d_in[0];   // [B,F]
    const int*   seqs     = (const int*)  d_in[1];   // [B,T-1]
    const float* W_in  = (const float*)d_in[3];      // [E,F]
    const float* b_in  = (const float*)d_in[4];      // [E]
    const float* emb   = (const float*)d_in[5];      // [V,E]
    const float* W_ih  = (const float*)d_in[6];      // [4H,E]
    const float* W_hh  = (const float*)d_in[7];      // [4H,H]
    const float* b_ih  = (const float*)d_in[8];      // [4H]
    const float* b_hh  = (const float*)d_in[9];      // [4H]
    const float* W_out = (const float*)d_in[10];     // [V,H]
    const float* b_out = (const float*)d_in[11];     // [V]
    float* out = (float*)d_out;                      // [B,T,V]

    float *p_seq, *p_xg;
    cudaGetSymbolAddress((void**)&p_seq, g_seq);
    cudaGetSymbolAddress((void**)&p_xg,  g_xg);
    __half *p_sseq, *p_Wih, *p_hid, *p_Wout;
    cudaGetSymbolAddress((void**)&p_sseq, s_seq);
    cudaGetSymbolAddress((void**)&p_Wih,  s_Wih);
    cudaGetSymbolAddress((void**)&p_hid,  s_hid);
    cudaGetSymbolAddress((void**)&p_Wout, s_Wout);

    cudaFuncSetAttribute(gemm_mma, cudaFuncAttributeMaxDynamicSharedMemorySize, SMEM_MM);
    cudaFuncSetAttribute(lstm_tc,  cudaFuncAttributeMaxDynamicSharedMemorySize, SMEM_LSTM);

    const int TPB = 256;
    auto nb = [](size_t n, int t) { return (int)((n + t - 1) / t); };

    // 1) x0 = features @ W_in^T + b_in (exact fp32) -> g_seq rows [0,128)
    {
        dim3 grid(Ed / 32, Bb / 32);   // 64 CTAs
        gemm_tn<32, 32, 8, 2, 2><<<grid, 256>>>(
            features, W_in, b_in, p_seq, Bb, Ed, Fdim);
    }

    // 2) gather embeddings for t = 1..T-1
    gather_emb<<<(Tl - 1) * Bb, 128>>>(seqs, emb);

    // 3) fp16 2-split seq / W_ih, xg GEMM  [5120, 2048] K=1024
    split2h<0><<<nb((size_t)BT * Ed, TPB), TPB>>>(p_seq, p_sseq, BT, Ed);
    split2h<1><<<nb((size_t)H4 * Ed, TPB), TPB>>>(W_ih, p_Wih, H4, Ed);
    {
        dim3 grid(H4 / 128, BT / 128);   // (16,40)
        gemm_mma<<<grid, 256, SMEM_MM>>>(p_sseq, p_Wih, b_ih, p_xg, BT, H4, K2E);
    }

    // 4) persistent tensor-core recurrence (writes h fp16 into s_hid)
    lstm_tc<<<32, 256, SMEM_LSTM>>>(W_hh, b_hh);

    // 5) W_out -> fp16, output GEMM [5120, 10000] K=512 (single fp16)
    tofp16<<<nb((size_t)Vd * Hd, TPB), TPB>>>(W_out, p_Wout, (size_t)Vd * Hd);
    {
        dim3 grid((Vd + 127) / 128, BT / 128);   // (79,40)
        gemm_mma<<<grid, 256, SMEM_MM>>>(p_hid, p_Wout, b_out, out, BT, Vd, Ed);
    }
}

// round 9
// speedup vs baseline: 2.4587x; 1.4269x over previous
#include <cuda_runtime.h>
#include <cuda_bf16.h>
#include <cuda_fp16.h>
#include <cstdint>

// Problem constants
#define Bb   128
#define Fdim 1536
#define Ed   512
#define Hd   512
#define H4   2048
#define Vd   10000
#define Tl   40
#define BT   (Bb*Tl)     // 5120
#define K2E  (2*Ed)      // 1024

// ---------------- scratch (static device memory) -----------------------------
__device__ float g_seq[(size_t)BT * Ed];        // [T*B, E]  row r = t*B + b
__device__ float g_xg[(size_t)BT * H4];         // [T*B, 4H]
__device__ __align__(16) __half g_hfp16[Bb * Hd];  // recurrent h (fp16)

// fp16 operand buffers
__device__ __align__(16) __half s_seq [(size_t)BT * K2E];   // A of xg: [hi|lo]
__device__ __align__(16) __half s_Wih [(size_t)H4 * K2E];   // B of xg: [hi|hi]
__device__ __align__(16) __half s_hid [(size_t)BT * Ed];    // A of out GEMM
__device__ __align__(16) __half s_Wout[(size_t)Vd * Ed];    // B of out GEMM

// grid barrier state
__device__ unsigned int g_bar_cnt = 0;
__device__ volatile unsigned int g_bar_gen = 0;

// fast MUFU-only activations (EX2 + RCP; ~2ulp)
__device__ __forceinline__ float fsig(float x) {
    return __fdividef(1.0f, 1.0f + __expf(-x));
}
__device__ __forceinline__ float ftanh(float x) {
    return fmaf(-2.0f, __fdividef(1.0f, 1.0f + __expf(2.0f * x)), 1.0f);
}

__device__ __forceinline__ uint32_t smem_u32(const void* p) {
    return (uint32_t)__cvta_generic_to_shared(p);
}

template<int N>
__device__ __forceinline__ void cp_wait() {
    asm volatile("cp.async.wait_group %0;\n" :: "n"(N));
}

// ---------------- exact fp32 SIMT GEMM (for x0): C = A @ B^T + bias -----------
template<int BM, int BN, int BK, int TM, int TN>
__global__ void gemm_tn(const float* __restrict__ A,
                        const float* __restrict__ Bw,
                        const float* __restrict__ bias,
                        float* __restrict__ C,
                        int M, int N, int K)
{
    constexpr int NT = (BM / TM) * (BN / TN);
    static_assert(NT == 256, "need 256 threads");
    __shared__ float As[BK][BM];
    __shared__ float Bs[BK][BN];

    const int m0 = blockIdx.y * BM;
    const int n0 = blockIdx.x * BN;
    const int tid = threadIdx.x;
    constexpr int NTX = BN / TN;
    const int tc = tid % NTX;
    const int tr = tid / NTX;

    float acc[TM][TN];
    #pragma unroll
    for (int i = 0; i < TM; i++)
        #pragma unroll
        for (int j = 0; j < TN; j++) acc[i][j] = 0.0f;

    constexpr int A_LD4 = BM * BK / 4;
    constexpr int B_LD4 = BN * BK / 4;
    constexpr int K4 = BK / 4;

    for (int k0 = 0; k0 < K; k0 += BK) {
        #pragma unroll
        for (int i = tid; i < A_LD4; i += NT) {
            int row = i / K4;
            int kc  = (i % K4) * 4;
            float4 v = *reinterpret_cast<const float4*>(
                A + (size_t)(m0 + row) * K + k0 + kc);
            As[kc + 0][row] = v.x; As[kc + 1][row] = v.y;
            As[kc + 2][row] = v.z; As[kc + 3][row] = v.w;
        }
        #pragma unroll
        for (int i = tid; i < B_LD4; i += NT) {
            int row = i / K4;
            int kc  = (i % K4) * 4;
            float4 v = *reinterpret_cast<const float4*>(
                Bw + (size_t)(n0 + row) * K + k0 + kc);
            Bs[kc + 0][row] = v.x; Bs[kc + 1][row] = v.y;
            Bs[kc + 2][row] = v.z; Bs[kc + 3][row] = v.w;
        }
        __syncthreads();

        #pragma unroll
        for (int k = 0; k < BK; k++) {
            float ra[TM], rb[TN];
            #pragma unroll
            for (int i = 0; i < TM; i++) ra[i] = As[k][tr * TM + i];
            #pragma unroll
            for (int j = 0; j < TN; j++) rb[j] = Bs[k][tc * TN + j];
            #pragma unroll
            for (int i = 0; i < TM; i++)
                #pragma unroll
                for (int j = 0; j < TN; j++)
                    acc[i][j] = fmaf(ra[i], rb[j], acc[i][j]);
        }
        __syncthreads();
    }

    #pragma unroll
    for (int i = 0; i < TM; i++) {
        int m = m0 + tr * TM + i;
        #pragma unroll
        for (int j = 0; j < TN; j++) {
            int n = n0 + tc * TN + j;
            C[(size_t)m * N + n] = acc[i][j] + bias[n];
        }
    }
}

// ---------------- fp16 HMMA GEMM: C = A @ B^T + bias ---------------------------
// Tile 128x128x32, 256 threads, 4-stage cp.async, dynamic smem, 2 CTAs/SM.
#define STRIDEg 40
#define SA_ST   (128 * STRIDEg)
#define NST     4
#define SMEM_MM (NST * 2 * SA_ST * 2)    // 81920 bytes

__global__ void __launch_bounds__(256, 2)
gemm_mma(const __half* __restrict__ A,
         const __half* __restrict__ B,
         const float* __restrict__ bias,
         float* __restrict__ C,
         int M, int N, int K)
{
    extern __shared__ __align__(16) uint16_t smbuf[];
    uint16_t* Asm = smbuf;
    uint16_t* Bsm = smbuf + NST * SA_ST;

    const int tid  = threadIdx.x;
    const int warp = tid >> 5, lane = tid & 31;
    const int wm = (warp >> 2) * 64;
    const int wn = (warp & 3) * 32;
    const int m0 = blockIdx.y * 128, n0 = blockIdx.x * 128;
    const int KT = K / 32;

    float acc[4][4][4];
    #pragma unroll
    for (int i = 0; i < 4; i++)
        #pragma unroll
        for (int j = 0; j < 4; j++)
            #pragma unroll
            for (int r = 0; r < 4; r++) acc[i][j][r] = 0.0f;

    auto load_tile = [&](int buf, int kt) {
        const int k0 = kt * 32;
        #pragma unroll
        for (int it = 0; it < 2; it++) {
            int task = tid + it * 256;
            int r = task >> 2, c = task & 3;
            uint32_t dst = smem_u32(&Asm[buf * SA_ST + r * STRIDEg + c * 8]);
            const void* src = A + (size_t)(m0 + r) * K + k0 + c * 8;
            asm volatile("cp.async.cg.shared.global [%0],[%1],16;\n" :: "r"(dst), "l"(src));
        }
        #pragma unroll
        for (int it = 0; it < 2; it++) {
            int task = tid + it * 256;
            int r = task >> 2, c = task & 3;
            if (n0 + r < N) {
                uint32_t dst = smem_u32(&Bsm[buf * SA_ST + r * STRIDEg + c * 8]);
                const void* src = B + (size_t)(n0 + r) * K + k0 + c * 8;
                asm volatile("cp.async.cg.shared.global [%0],[%1],16;\n" :: "r"(dst), "l"(src));
            }
        }
        asm volatile("cp.async.commit_group;\n");
    };

    // prefetch 3 stages
    load_tile(0, 0);
    if (KT > 1) load_tile(1, 1); else asm volatile("cp.async.commit_group;\n");
    if (KT > 2) load_tile(2, 2); else asm volatile("cp.async.commit_group;\n");

    for (int ck = 0; ck < KT; ck++) {
        if (ck + 3 < KT) load_tile((ck + 3) & 3, ck + 3);
        else             asm volatile("cp.async.commit_group;\n");
        cp_wait<3>();
        __syncthreads();

        const int buf = ck & 3;
        const uint16_t* as = Asm + buf * SA_ST;
        const uint16_t* bs = Bsm + buf * SA_ST;

        #pragma unroll
        for (int kk = 0; kk < 32; kk += 16) {
            uint32_t afr[4][4];
            #pragma unroll
            for (int i = 0; i < 4; i++) {
                int row = wm + i * 16 + (lane & 15);
                int col = kk + (lane >> 4) * 8;
                uint32_t addr = smem_u32(&as[row * STRIDEg + col]);
                asm volatile("ldmatrix.sync.aligned.m8n8.x4.shared.b16 {%0,%1,%2,%3},[%4];"
                             : "=r"(afr[i][0]), "=r"(afr[i][1]), "=r"(afr[i][2]), "=r"(afr[i][3])
                             : "r"(addr));
            }
            uint32_t bfr[4][2];
            #pragma unroll
            for (int j = 0; j < 2; j++) {
                int grp = lane >> 3;
                int row = wn + j * 16 + (grp >> 1) * 8 + (lane & 7);
                int col = kk + (grp & 1) * 8;
                uint32_t addr = smem_u32(&bs[row * STRIDEg + col]);
                uint32_t r0, r1, r2, r3;
                asm volatile("ldmatrix.sync.aligned.m8n8.x4.shared.b16 {%0,%1,%2,%3},[%4];"
                             : "=r"(r0), "=r"(r1), "=r"(r2), "=r"(r3) : "r"(addr));
                bfr[j * 2][0] = r0; bfr[j * 2][1] = r1;
                bfr[j * 2 + 1][0] = r2; bfr[j * 2 + 1][1] = r3;
            }
            #pragma unroll
            for (int i = 0; i < 4; i++)
                #pragma unroll
                for (int j = 0; j < 4; j++) {
                    asm volatile(
                        "mma.sync.aligned.m16n8k16.row.col.f32.f16.f16.f32 "
                        "{%0,%1,%2,%3},{%4,%5,%6,%7},{%8,%9},{%0,%1,%2,%3};"
                        : "+f"(acc[i][j][0]), "+f"(acc[i][j][1]),
                          "+f"(acc[i][j][2]), "+f"(acc[i][j][3])
                        : "r"(afr[i][0]), "r"(afr[i][1]), "r"(afr[i][2]), "r"(afr[i][3]),
                          "r"(bfr[j][0]), "r"(bfr[j][1]));
                }
        }
        __syncthreads();
    }

    const int mrow = lane >> 2, nc2 = (lane & 3) * 2;
    #pragma unroll
    for (int i = 0; i < 4; i++) {
        int gm = m0 + wm + i * 16 + mrow;
        float* Crow0 = C + (size_t)gm * N;
        float* Crow1 = C + (size_t)(gm + 8) * N;
        #pragma unroll
        for (int j = 0; j < 4; j++) {
            int gn = n0 + wn + j * 8 + nc2;
            if (gn < N) {
                float bv = bias[gn];
                Crow0[gn] = acc[i][j][0] + bv;
                Crow1[gn] = acc[i][j][2] + bv;
            }
            if (gn + 1 < N) {
                float bv = bias[gn + 1];
                Crow0[gn + 1] = acc[i][j][1] + bv;
                Crow1[gn + 1] = acc[i][j][3] + bv;
            }
        }
    }
}

// ---------------- split / convert kernels ---------------------------------------
template<int DUP>
__global__ void split2h(const float* __restrict__ X, __half* __restrict__ Y,
                        int M, int K)
{
    size_t i = (size_t)blockIdx.x * blockDim.x + threadIdx.x;
    size_t total = (size_t)M * K;
    if (i >= total) return;
    int m = (int)(i / K), k = (int)(i % K);
    float x = X[i];
    __half hi = __float2half_rn(x);
    __half* row = Y + (size_t)m * (2 * K);
    row[k] = hi;
    if (DUP) row[K + k] = hi;
    else     row[K + k] = __float2half_rn(x - __half2float(hi));
}

__global__ void tofp16(const float* __restrict__ X, __half* __restrict__ Y, size_t total)
{
    size_t i = (size_t)blockIdx.x * blockDim.x + threadIdx.x;
    if (i < total) Y[i] = __float2half_rn(X[i]);
}

// ---------------- gather word embeddings into g_seq rows t>=1 -----------------
__global__ void gather_emb(const int* __restrict__ seqs,
                           const float* __restrict__ emb)
{
    int bid = blockIdx.x;
    int t1  = bid / Bb;
    int b   = bid % Bb;
    int word = seqs[b * (Tl - 1) + t1];
    const float4* src = reinterpret_cast<const float4*>(emb + (size_t)word * Ed);
    float4* dst = reinterpret_cast<float4*>(g_seq + (size_t)((t1 + 1) * Bb + b) * Ed);
    for (int i = threadIdx.x; i < Ed / 4; i += blockDim.x) dst[i] = src[i];
}

// ---------------- persistent tensor-core LSTM recurrence ------------------------
// 32 CTAs (one per 16-wide hidden slice), 256 threads (8 warps, warp tile 32x32).
// W_hh fp16 in smem for all 40 steps; h fp16 via 2-stage cp.async pipeline;
// xg slice prefetched into smem per step (overlaps MMA); c in registers.
#define LCH   128                      // K per chunk
#define NCH   (Hd / LCH)               // 4
#define TSTR  136                      // chunk tile row stride (halves)
#define W_CH  (64 * TSTR)
#define H_STG (128 * TSTR)
#define SMEM_LSTM ((NCH * W_CH + 2 * H_STG) * 2 + 2 * 128 * 68 * 4)  // 208896 B

__device__ __forceinline__ void grid_sync_n(unsigned int nctas)
{
    __threadfence();
    __syncthreads();
    if (threadIdx.x == 0) {
        unsigned gen = g_bar_gen;
        if (atomicAdd(&g_bar_cnt, 1u) == nctas - 1u) {
            g_bar_cnt = 0;
            __threadfence();
            g_bar_gen = gen + 1;
        } else {
            while (g_bar_gen == gen) __nanosleep(16);
            __threadfence();
        }
    }
    __syncthreads();
}

__global__ void __launch_bounds__(256, 1)
lstm_tc(const float* __restrict__ Whh,   // [4H, H]
        const float* __restrict__ bhh)   // [4H]
{
    extern __shared__ __align__(16) uint16_t lsm[];
    uint16_t* Ws = lsm;                          // NCH x 64 x TSTR
    uint16_t* Hb = lsm + NCH * W_CH;             // 2 x 128 x TSTR
    float*    Gs = (float*)(Hb + 2 * H_STG);     // 128 x 68
    float*    Xs = Gs + 128 * 68;                // 128 x 68 (xg slice)

    const int tid  = threadIdx.x;
    const int warp = tid >> 5, lane = tid & 31;
    const int wm = (warp >> 1) * 32;   // 0,32,64,96
    const int wn = (warp & 1) * 32;    // 0,32
    const int jt = blockIdx.x;         // hidden slice

    // ---- load W_hh tile to smem as fp16 (once) ----
    #pragma unroll
    for (int it = 0; it < 32; it++) {
        int task = tid + it * 256;
        int row = task >> 7;
        int c4  = task & 127;
        int grow = (row >> 4) * Hd + jt * 16 + (row & 15);
        float4 v = *reinterpret_cast<const float4*>(Whh + (size_t)grow * Hd + c4 * 4);
        int ck = c4 >> 5;
        int kc = (c4 & 31) * 4;
        __half2 h01 = __floats2half2_rn(v.x, v.y);
        __half2 h23 = __floats2half2_rn(v.z, v.w);
        uint16_t* dst = Ws + ck * W_CH + row * TSTR + kc;
        *reinterpret_cast<__half2*>(dst)     = h01;
        *reinterpret_cast<__half2*>(dst + 2) = h23;
    }

    const int jj = tid & 15;
    float creg[8];
    #pragma unroll
    for (int i = 0; i < 8; i++) creg[i] = 0.0f;
    float bs[4];
    #pragma unroll
    for (int g = 0; g < 4; g++) bs[g] = bhh[g * Hd + jt * 16 + jj];

    // zero this CTA's h slice
    #pragma unroll
    for (int it = 0; it < 8; it++) {
        int bl = (tid >> 4) + it * 16;
        g_hfp16[bl * Hd + jt * 16 + jj] = __float2half_rn(0.0f);
    }
    grid_sync_n(32);

    // xg slice prefetch: 128 bl x 4 gates x 16 floats = 2048 x 16B tasks
    auto issue_xg = [&](const float* xg_t) {
        #pragma unroll
        for (int it = 0; it < 8; it++) {
            int task = tid + it * 256;
            int bl  = task >> 4;
            int rem = task & 15;
            int g = rem >> 2, q = rem & 3;
            uint32_t dst = smem_u32(&Xs[bl * 68 + g * 16 + q * 4]);
            const void* src = xg_t + (size_t)bl * H4 + g * Hd + jt * 16 + q * 4;
            asm volatile("cp.async.cg.shared.global [%0],[%1],16;\n" :: "r"(dst), "l"(src));
        }
        asm volatile("cp.async.commit_group;\n");
    };

    // h chunk: 128 rows x 128 halves = 2048 x 16B tasks
    auto issue_h = [&](int stage, int ck) {
        #pragma unroll
        for (int it = 0; it < 8; it++) {
            int task = tid + it * 256;
            int r  = task >> 4;
            int c8 = task & 15;
            uint32_t dst = smem_u32(&Hb[stage * H_STG + r * TSTR + c8 * 8]);
            const void* src = g_hfp16 + r * Hd + ck * LCH + c8 * 8;
            asm volatile("cp.async.cg.shared.global [%0],[%1],16;\n" :: "r"(dst), "l"(src));
        }
        asm volatile("cp.async.commit_group;\n");
    };

    for (int t = 0; t < Tl; t++) {
        const float* xg_t = g_xg + (size_t)t * Bb * H4;

        float acc[2][4][4];
        #pragma unroll
        for (int i = 0; i < 2; i++)
            #pragma unroll
            for (int j = 0; j < 4; j++)
                #pragma unroll
                for (int r = 0; r < 4; r++) acc[i][j][r] = 0.0f;

        issue_xg(xg_t);    // group: xg
        issue_h(0, 0);     // group: h0
        issue_h(1, 1);     // group: h1

        #pragma unroll
        for (int ck = 0; ck < NCH; ck++) {
            // waits: ck0 needs {xg,h0} -> pending {h1}; ck1 needs h1 ->
            // pending {h2}; ck2 needs h2 -> pending {h3}; ck3 needs h3.
            if (ck < 3) cp_wait<1>();
            else        cp_wait<0>();
            __syncthreads();

            const int stage = ck & 1;
            const uint16_t* hs = Hb + stage * H_STG;
            const uint16_t* ws = Ws + ck * W_CH;

            #pragma unroll
            for (int kk = 0; kk < LCH; kk += 16) {
                uint32_t afr[2][4];
                #pragma unroll
                for (int i = 0; i < 2; i++) {
                    int row = wm + i * 16 + (lane & 15);
                    int col = kk + (lane >> 4) * 8;
                    uint32_t addr = smem_u32(&hs[row * TSTR + col]);
                    asm volatile("ldmatrix.sync.aligned.m8n8.x4.shared.b16 {%0,%1,%2,%3},[%4];"
                                 : "=r"(afr[i][0]), "=r"(afr[i][1]), "=r"(afr[i][2]), "=r"(afr[i][3])
                                 : "r"(addr));
                }
                uint32_t bfr[4][2];
                #pragma unroll
                for (int j = 0; j < 2; j++) {
                    int grp = lane >> 3;
                    int row = wn + j * 16 + (grp >> 1) * 8 + (lane & 7);
                    int col = kk + (grp & 1) * 8;
                    uint32_t addr = smem_u32(&ws[row * TSTR + col]);
                    uint32_t r0, r1, r2, r3;
                    asm volatile("ldmatrix.sync.aligned.m8n8.x4.shared.b16 {%0,%1,%2,%3},[%4];"
                                 : "=r"(r0), "=r"(r1), "=r"(r2), "=r"(r3) : "r"(addr));
                    bfr[j * 2][0] = r0; bfr[j * 2][1] = r1;
                    bfr[j * 2 + 1][0] = r2; bfr[j * 2 + 1][1] = r3;
                }
                #pragma unroll
                for (int i = 0; i < 2; i++)
                    #pragma unroll
                    for (int j = 0; j < 4; j++) {
                        asm volatile(
                            "mma.sync.aligned.m16n8k16.row.col.f32.f16.f16.f32 "
                            "{%0,%1,%2,%3},{%4,%5,%6,%7},{%8,%9},{%0,%1,%2,%3};"
                            : "+f"(acc[i][j][0]), "+f"(acc[i][j][1]),
                              "+f"(acc[i][j][2]), "+f"(acc[i][j][3])
                            : "r"(afr[i][0]), "r"(afr[i][1]), "r"(afr[i][2]), "r"(afr[i][3]),
                              "r"(bfr[j][0]), "r"(bfr[j][1]));
                    }
            }
            __syncthreads();

            if (ck == 0) issue_h(0, 2);       // group: h2 (stage 0 consumed)
            else if (ck == 1) issue_h(1, 3);  // group: h3 (stage 1 consumed)
        }

        // write gate pre-activations (h@W^T part) to smem
        const int mrow = lane >> 2, nc2 = (lane & 3) * 2;
        #pragma unroll
        for (int i = 0; i < 2; i++) {
            int r0 = wm + i * 16 + mrow;
            #pragma unroll
            for (int j = 0; j < 4; j++) {
                int col = wn + j * 8 + nc2;
                Gs[r0 * 68 + col]       = acc[i][j][0];
                Gs[r0 * 68 + col + 1]   = acc[i][j][1];
                Gs[(r0 + 8) * 68 + col]     = acc[i][j][2];
                Gs[(r0 + 8) * 68 + col + 1] = acc[i][j][3];
            }
        }
        __syncthreads();

        // cell update: 8 cells per thread, all operands in smem
        #pragma unroll
        for (int it = 0; it < 8; it++) {
            int bl = (tid >> 4) + it * 16;
            float gi = fsig (Gs[bl * 68 +  0 + jj] + Xs[bl * 68 +  0 + jj] + bs[0]);
            float gf = fsig (Gs[bl * 68 + 16 + jj] + Xs[bl * 68 + 16 + jj] + bs[1]);
            float gg = ftanh(Gs[bl * 68 + 32 + jj] + Xs[bl * 68 + 32 + jj] + bs[2]);
            float go = fsig (Gs[bl * 68 + 48 + jj] + Xs[bl * 68 + 48 + jj] + bs[3]);
            float c = fmaf(gf, creg[it], gi * gg);
            creg[it] = c;
            __half h16 = __float2half_rn(go * ftanh(c));
            g_hfp16[bl * Hd + jt * 16 + jj] = h16;
            s_hid[((size_t)bl * Tl + t) * Hd + jt * 16 + jj] = h16;
        }
        grid_sync_n(32);
    }
}

// ---------------- launch --------------------------------------------------------
extern "C" void kernel_launch(void* const* d_in, const int* in_sizes, int n_in,
                              void* d_out, int out_size)
{
    const float* features = (const float*)d_in[0];   // [B,F]
    const int*   seqs     = (const int*)  d_in[1];   // [B,T-1]
    const float* W_in  = (const float*)d_in[3];      // [E,F]
    const float* b_in  = (const float*)d_in[4];      // [E]
    const float* emb   = (const float*)d_in[5];      // [V,E]
    const float* W_ih  = (const float*)d_in[6];      // [4H,E]
    const float* W_hh  = (const float*)d_in[7];      // [4H,H]
    const float* b_ih  = (const float*)d_in[8];      // [4H]
    const float* b_hh  = (const float*)d_in[9];      // [4H]
    const float* W_out = (const float*)d_in[10];     // [V,H]
    const float* b_out = (const float*)d_in[11];     // [V]
    float* out = (float*)d_out;                      // [B,T,V]

    float *p_seq, *p_xg;
    cudaGetSymbolAddress((void**)&p_seq, g_seq);
    cudaGetSymbolAddress((void**)&p_xg,  g_xg);
    __half *p_sseq, *p_Wih, *p_hid, *p_Wout;
    cudaGetSymbolAddress((void**)&p_sseq, s_seq);
    cudaGetSymbolAddress((void**)&p_Wih,  s_Wih);
    cudaGetSymbolAddress((void**)&p_hid,  s_hid);
    cudaGetSymbolAddress((void**)&p_Wout, s_Wout);

    cudaFuncSetAttribute(gemm_mma, cudaFuncAttributeMaxDynamicSharedMemorySize, SMEM_MM);
    cudaFuncSetAttribute(lstm_tc,  cudaFuncAttributeMaxDynamicSharedMemorySize, SMEM_LSTM);

    const int TPB = 256;
    auto nb = [](size_t n, int t) { return (int)((n + t - 1) / t); };

    // 1) x0 = features @ W_in^T + b_in (exact fp32) -> g_seq rows [0,128)
    {
        dim3 grid(Ed / 32, Bb / 32);   // 64 CTAs
        gemm_tn<32, 32, 8, 2, 2><<<grid, 256>>>(
            features, W_in, b_in, p_seq, Bb, Ed, Fdim);
    }

    // 2) gather embeddings for t = 1..T-1
    gather_emb<<<(Tl - 1) * Bb, 128>>>(seqs, emb);

    // 3) fp16 2-split seq / W_ih, xg GEMM  [5120, 2048] K=1024
    split2h<0><<<nb((size_t)BT * Ed, TPB), TPB>>>(p_seq, p_sseq, BT, Ed);
    split2h<1><<<nb((size_t)H4 * Ed, TPB), TPB>>>(W_ih, p_Wih, H4, Ed);
    {
        dim3 grid(H4 / 128, BT / 128);   // (16,40)
        gemm_mma<<<grid, 256, SMEM_MM>>>(p_sseq, p_Wih, b_ih, p_xg, BT, H4, K2E);
    }

    // 4) persistent tensor-core recurrence (writes h fp16 into s_hid)
    lstm_tc<<<32, 256, SMEM_LSTM>>>(W_hh, b_hh);

    // 5) W_out -> fp16, output GEMM [5120, 10000] K=512 (single fp16)
    tofp16<<<nb((size_t)Vd * Hd, TPB), TPB>>>(W_out, p_Wout, (size_t)Vd * Hd);
    {
        dim3 grid((Vd + 127) / 128, BT / 128);   // (79,40)
        gemm_mma<<<grid, 256, SMEM_MM>>>(p_hid, p_Wout, b_out, out, BT, Vd, Ed);
    }
}

// round 10
// speedup vs baseline: 2.6193x; 1.0653x over previous
#include <cuda_runtime.h>
#include <cuda_bf16.h>
#include <cuda_fp16.h>
#include <cstdint>

// Problem constants
#define Bb   128
#define Fdim 1536
#define Ed   512
#define Hd   512
#define H4   2048
#define Vd   10000
#define Tl   40
#define BT   (Bb*Tl)     // 5120

// ---------------- scratch (static device memory) -----------------------------
__device__ float g_xg[(size_t)BT * H4];            // [T*B, 4H]
__device__ __align__(16) __half g_hfp16[Bb * Hd];  // recurrent h (fp16)

// fp16 operand buffers
__device__ __align__(16) __half s_seq [(size_t)BT * Ed];    // A of xg (fp16 seq)
__device__ __align__(16) __half s_Wih [(size_t)H4 * Ed];    // B of xg
__device__ __align__(16) __half s_hid [(size_t)BT * Ed];    // A of out GEMM
__device__ __align__(16) __half s_Wout[(size_t)Vd * Ed];    // B of out GEMM

// grid barrier state
__device__ unsigned int g_bar_cnt = 0;
__device__ volatile unsigned int g_bar_gen = 0;

// fast MUFU-only activations (EX2 + RCP; ~2ulp)
__device__ __forceinline__ float fsig(float x) {
    return __fdividef(1.0f, 1.0f + __expf(-x));
}
__device__ __forceinline__ float ftanh(float x) {
    return fmaf(-2.0f, __fdividef(1.0f, 1.0f + __expf(2.0f * x)), 1.0f);
}

__device__ __forceinline__ uint32_t smem_u32(const void* p) {
    return (uint32_t)__cvta_generic_to_shared(p);
}

template<int N>
__device__ __forceinline__ void cp_wait() {
    asm volatile("cp.async.wait_group %0;\n" :: "n"(N));
}

// ---------------- fp32 SIMT GEMM for x0, fp16 output: C = A @ B^T + bias ------
template<int BM, int BN, int BK, int TM, int TN>
__global__ void gemm_tn_h(const float* __restrict__ A,
                          const float* __restrict__ Bw,
                          const float* __restrict__ bias,
                          __half* __restrict__ C,
                          int M, int N, int K)
{
    constexpr int NT = (BM / TM) * (BN / TN);
    static_assert(NT == 256, "need 256 threads");
    __shared__ float As[BK][BM];
    __shared__ float Bs[BK][BN];

    const int m0 = blockIdx.y * BM;
    const int n0 = blockIdx.x * BN;
    const int tid = threadIdx.x;
    constexpr int NTX = BN / TN;
    const int tc = tid % NTX;
    const int tr = tid / NTX;

    float acc[TM][TN];
    #pragma unroll
    for (int i = 0; i < TM; i++)
        #pragma unroll
        for (int j = 0; j < TN; j++) acc[i][j] = 0.0f;

    constexpr int A_LD4 = BM * BK / 4;
    constexpr int B_LD4 = BN * BK / 4;
    constexpr int K4 = BK / 4;

    for (int k0 = 0; k0 < K; k0 += BK) {
        #pragma unroll
        for (int i = tid; i < A_LD4; i += NT) {
            int row = i / K4;
            int kc  = (i % K4) * 4;
            float4 v = *reinterpret_cast<const float4*>(
                A + (size_t)(m0 + row) * K + k0 + kc);
            As[kc + 0][row] = v.x; As[kc + 1][row] = v.y;
            As[kc + 2][row] = v.z; As[kc + 3][row] = v.w;
        }
        #pragma unroll
        for (int i = tid; i < B_LD4; i += NT) {
            int row = i / K4;
            int kc  = (i % K4) * 4;
            float4 v = *reinterpret_cast<const float4*>(
                Bw + (size_t)(n0 + row) * K + k0 + kc);
            Bs[kc + 0][row] = v.x; Bs[kc + 1][row] = v.y;
            Bs[kc + 2][row] = v.z; Bs[kc + 3][row] = v.w;
        }
        __syncthreads();

        #pragma unroll
        for (int k = 0; k < BK; k++) {
            float ra[TM], rb[TN];
            #pragma unroll
            for (int i = 0; i < TM; i++) ra[i] = As[k][tr * TM + i];
            #pragma unroll
            for (int j = 0; j < TN; j++) rb[j] = Bs[k][tc * TN + j];
            #pragma unroll
            for (int i = 0; i < TM; i++)
                #pragma unroll
                for (int j = 0; j < TN; j++)
                    acc[i][j] = fmaf(ra[i], rb[j], acc[i][j]);
        }
        __syncthreads();
    }

    #pragma unroll
    for (int i = 0; i < TM; i++) {
        int m = m0 + tr * TM + i;
        #pragma unroll
        for (int j = 0; j < TN; j++) {
            int n = n0 + tc * TN + j;
            C[(size_t)m * N + n] = __float2half_rn(acc[i][j] + bias[n]);
        }
    }
}

// ---------------- fp16 HMMA GEMM: C = A @ B^T + bias ---------------------------
// Tile 128x128x32, 256 threads, 4-stage cp.async, dynamic smem, 2 CTAs/SM.
#define STRIDEg 40
#define SA_ST   (128 * STRIDEg)
#define NST     4
#define SMEM_MM (NST * 2 * SA_ST * 2)    // 81920 bytes

__global__ void __launch_bounds__(256, 2)
gemm_mma(const __half* __restrict__ A,
         const __half* __restrict__ B,
         const float* __restrict__ bias,
         float* __restrict__ C,
         int M, int N, int K)
{
    extern __shared__ __align__(16) uint16_t smbuf[];
    uint16_t* Asm = smbuf;
    uint16_t* Bsm = smbuf + NST * SA_ST;

    const int tid  = threadIdx.x;
    const int warp = tid >> 5, lane = tid & 31;
    const int wm = (warp >> 2) * 64;
    const int wn = (warp & 3) * 32;
    const int m0 = blockIdx.y * 128, n0 = blockIdx.x * 128;
    const int KT = K / 32;

    float acc[4][4][4];
    #pragma unroll
    for (int i = 0; i < 4; i++)
        #pragma unroll
        for (int j = 0; j < 4; j++)
            #pragma unroll
            for (int r = 0; r < 4; r++) acc[i][j][r] = 0.0f;

    auto load_tile = [&](int buf, int kt) {
        const int k0 = kt * 32;
        #pragma unroll
        for (int it = 0; it < 2; it++) {
            int task = tid + it * 256;
            int r = task >> 2, c = task & 3;
            uint32_t dst = smem_u32(&Asm[buf * SA_ST + r * STRIDEg + c * 8]);
            const void* src = A + (size_t)(m0 + r) * K + k0 + c * 8;
            asm volatile("cp.async.cg.shared.global [%0],[%1],16;\n" :: "r"(dst), "l"(src));
        }
        #pragma unroll
        for (int it = 0; it < 2; it++) {
            int task = tid + it * 256;
            int r = task >> 2, c = task & 3;
            if (n0 + r < N) {
                uint32_t dst = smem_u32(&Bsm[buf * SA_ST + r * STRIDEg + c * 8]);
                const void* src = B + (size_t)(n0 + r) * K + k0 + c * 8;
                asm volatile("cp.async.cg.shared.global [%0],[%1],16;\n" :: "r"(dst), "l"(src));
            }
        }
        asm volatile("cp.async.commit_group;\n");
    };

    // prefetch 3 stages
    load_tile(0, 0);
    if (KT > 1) load_tile(1, 1); else asm volatile("cp.async.commit_group;\n");
    if (KT > 2) load_tile(2, 2); else asm volatile("cp.async.commit_group;\n");

    for (int ck = 0; ck < KT; ck++) {
        if (ck + 3 < KT) load_tile((ck + 3) & 3, ck + 3);
        else             asm volatile("cp.async.commit_group;\n");
        cp_wait<3>();
        __syncthreads();

        const int buf = ck & 3;
        const uint16_t* as = Asm + buf * SA_ST;
        const uint16_t* bs = Bsm + buf * SA_ST;

        #pragma unroll
        for (int kk = 0; kk < 32; kk += 16) {
            uint32_t afr[4][4];
            #pragma unroll
            for (int i = 0; i < 4; i++) {
                int row = wm + i * 16 + (lane & 15);
                int col = kk + (lane >> 4) * 8;
                uint32_t addr = smem_u32(&as[row * STRIDEg + col]);
                asm volatile("ldmatrix.sync.aligned.m8n8.x4.shared.b16 {%0,%1,%2,%3},[%4];"
                             : "=r"(afr[i][0]), "=r"(afr[i][1]), "=r"(afr[i][2]), "=r"(afr[i][3])
                             : "r"(addr));
            }
            uint32_t bfr[4][2];
            #pragma unroll
            for (int j = 0; j < 2; j++) {
                int grp = lane >> 3;
                int row = wn + j * 16 + (grp >> 1) * 8 + (lane & 7);
                int col = kk + (grp & 1) * 8;
                uint32_t addr = smem_u32(&bs[row * STRIDEg + col]);
                uint32_t r0, r1, r2, r3;
                asm volatile("ldmatrix.sync.aligned.m8n8.x4.shared.b16 {%0,%1,%2,%3},[%4];"
                             : "=r"(r0), "=r"(r1), "=r"(r2), "=r"(r3) : "r"(addr));
                bfr[j * 2][0] = r0; bfr[j * 2][1] = r1;
                bfr[j * 2 + 1][0] = r2; bfr[j * 2 + 1][1] = r3;
            }
            #pragma unroll
            for (int i = 0; i < 4; i++)
                #pragma unroll
                for (int j = 0; j < 4; j++) {
                    asm volatile(
                        "mma.sync.aligned.m16n8k16.row.col.f32.f16.f16.f32 "
                        "{%0,%1,%2,%3},{%4,%5,%6,%7},{%8,%9},{%0,%1,%2,%3};"
                        : "+f"(acc[i][j][0]), "+f"(acc[i][j][1]),
                          "+f"(acc[i][j][2]), "+f"(acc[i][j][3])
                        : "r"(afr[i][0]), "r"(afr[i][1]), "r"(afr[i][2]), "r"(afr[i][3]),
                          "r"(bfr[j][0]), "r"(bfr[j][1]));
                }
        }
        __syncthreads();
    }

    const int mrow = lane >> 2, nc2 = (lane & 3) * 2;
    #pragma unroll
    for (int i = 0; i < 4; i++) {
        int gm = m0 + wm + i * 16 + mrow;
        float* Crow0 = C + (size_t)gm * N;
        float* Crow1 = C + (size_t)(gm + 8) * N;
        #pragma unroll
        for (int j = 0; j < 4; j++) {
            int gn = n0 + wn + j * 8 + nc2;
            if (gn < N) {
                float bv = bias[gn];
                Crow0[gn] = acc[i][j][0] + bv;
                Crow1[gn] = acc[i][j][2] + bv;
            }
            if (gn + 1 < N) {
                float bv = bias[gn + 1];
                Crow0[gn + 1] = acc[i][j][1] + bv;
                Crow1[gn + 1] = acc[i][j][3] + bv;
            }
        }
    }
}

// ---------------- convert kernel -------------------------------------------------
__global__ void tofp16(const float* __restrict__ X, __half* __restrict__ Y, size_t total)
{
    size_t i = (size_t)blockIdx.x * blockDim.x + threadIdx.x;
    if (i < total) Y[i] = __float2half_rn(X[i]);
}

// ---------------- gather word embeddings (fp32 -> fp16) into s_seq rows t>=1 ---
__global__ void gather_emb(const int* __restrict__ seqs,
                           const float* __restrict__ emb)
{
    int bid = blockIdx.x;
    int t1  = bid / Bb;
    int b   = bid % Bb;
    int word = seqs[b * (Tl - 1) + t1];
    const float4* src = reinterpret_cast<const float4*>(emb + (size_t)word * Ed);
    __half* dst = s_seq + (size_t)((t1 + 1) * Bb + b) * Ed;
    for (int i = threadIdx.x; i < Ed / 4; i += blockDim.x) {
        float4 v = src[i];
        __half2 h01 = __floats2half2_rn(v.x, v.y);
        __half2 h23 = __floats2half2_rn(v.z, v.w);
        *reinterpret_cast<__half2*>(dst + i * 4)     = h01;
        *reinterpret_cast<__half2*>(dst + i * 4 + 2) = h23;
    }
}

// ---------------- persistent tensor-core LSTM recurrence ------------------------
#define LCH   128                      // K per chunk
#define NCH   (Hd / LCH)               // 4
#define TSTR  136                      // chunk tile row stride (halves)
#define W_CH  (64 * TSTR)
#define H_STG (128 * TSTR)
#define SMEM_LSTM ((NCH * W_CH + 2 * H_STG) * 2 + 2 * 128 * 68 * 4)  // 208896 B

__device__ __forceinline__ void grid_sync_n(unsigned int nctas)
{
    __threadfence();
    __syncthreads();
    if (threadIdx.x == 0) {
        unsigned gen = g_bar_gen;
        if (atomicAdd(&g_bar_cnt, 1u) == nctas - 1u) {
            g_bar_cnt = 0;
            __threadfence();
            g_bar_gen = gen + 1;
        } else {
            while (g_bar_gen == gen) __nanosleep(16);
            __threadfence();
        }
    }
    __syncthreads();
}

__global__ void __launch_bounds__(256, 1)
lstm_tc(const float* __restrict__ Whh,   // [4H, H]
        const float* __restrict__ bhh)   // [4H]
{
    extern __shared__ __align__(16) uint16_t lsm[];
    uint16_t* Ws = lsm;                          // NCH x 64 x TSTR
    uint16_t* Hb = lsm + NCH * W_CH;             // 2 x 128 x TSTR
    float*    Gs = (float*)(Hb + 2 * H_STG);     // 128 x 68
    float*    Xs = Gs + 128 * 68;                // 128 x 68 (xg slice)

    const int tid  = threadIdx.x;
    const int warp = tid >> 5, lane = tid & 31;
    const int wm = (warp >> 1) * 32;   // 0,32,64,96
    const int wn = (warp & 1) * 32;    // 0,32
    const int jt = blockIdx.x;         // hidden slice

    // ---- load W_hh tile to smem as fp16 (once) ----
    #pragma unroll
    for (int it = 0; it < 32; it++) {
        int task = tid + it * 256;
        int row = task >> 7;
        int c4  = task & 127;
        int grow = (row >> 4) * Hd + jt * 16 + (row & 15);
        float4 v = *reinterpret_cast<const float4*>(Whh + (size_t)grow * Hd + c4 * 4);
        int ck = c4 >> 5;
        int kc = (c4 & 31) * 4;
        __half2 h01 = __floats2half2_rn(v.x, v.y);
        __half2 h23 = __floats2half2_rn(v.z, v.w);
        uint16_t* dst = Ws + ck * W_CH + row * TSTR + kc;
        *reinterpret_cast<__half2*>(dst)     = h01;
        *reinterpret_cast<__half2*>(dst + 2) = h23;
    }

    const int jj = tid & 15;
    float creg[8];
    #pragma unroll
    for (int i = 0; i < 8; i++) creg[i] = 0.0f;
    float bs[4];
    #pragma unroll
    for (int g = 0; g < 4; g++) bs[g] = bhh[g * Hd + jt * 16 + jj];

    // zero this CTA's h slice
    #pragma unroll
    for (int it = 0; it < 8; it++) {
        int bl = (tid >> 4) + it * 16;
        g_hfp16[bl * Hd + jt * 16 + jj] = __float2half_rn(0.0f);
    }
    grid_sync_n(32);

    // xg slice prefetch: 128 bl x 4 gates x 16 floats = 2048 x 16B tasks
    auto issue_xg = [&](const float* xg_t) {
        #pragma unroll
        for (int it = 0; it < 8; it++) {
            int task = tid + it * 256;
            int bl  = task >> 4;
            int rem = task & 15;
            int g = rem >> 2, q = rem & 3;
            uint32_t dst = smem_u32(&Xs[bl * 68 + g * 16 + q * 4]);
            const void* src = xg_t + (size_t)bl * H4 + g * Hd + jt * 16 + q * 4;
            asm volatile("cp.async.cg.shared.global [%0],[%1],16;\n" :: "r"(dst), "l"(src));
        }
        asm volatile("cp.async.commit_group;\n");
    };

    // h chunk: 128 rows x 128 halves = 2048 x 16B tasks
    auto issue_h = [&](int stage, int ck) {
        #pragma unroll
        for (int it = 0; it < 8; it++) {
            int task = tid + it * 256;
            int r  = task >> 4;
            int c8 = task & 15;
            uint32_t dst = smem_u32(&Hb[stage * H_STG + r * TSTR + c8 * 8]);
            const void* src = g_hfp16 + r * Hd + ck * LCH + c8 * 8;
            asm volatile("cp.async.cg.shared.global [%0],[%1],16;\n" :: "r"(dst), "l"(src));
        }
        asm volatile("cp.async.commit_group;\n");
    };

    for (int t = 0; t < Tl; t++) {
        const float* xg_t = g_xg + (size_t)t * Bb * H4;

        float acc[2][4][4];
        #pragma unroll
        for (int i = 0; i < 2; i++)
            #pragma unroll
            for (int j = 0; j < 4; j++)
                #pragma unroll
                for (int r = 0; r < 4; r++) acc[i][j][r] = 0.0f;

        issue_xg(xg_t);    // group: xg
        issue_h(0, 0);     // group: h0
        issue_h(1, 1);     // group: h1

        #pragma unroll
        for (int ck = 0; ck < NCH; ck++) {
            if (ck < 3) cp_wait<1>();
            else        cp_wait<0>();
            __syncthreads();

            const int stage = ck & 1;
            const uint16_t* hs = Hb + stage * H_STG;
            const uint16_t* ws = Ws + ck * W_CH;

            #pragma unroll
            for (int kk = 0; kk < LCH; kk += 16) {
                uint32_t afr[2][4];
                #pragma unroll
                for (int i = 0; i < 2; i++) {
                    int row = wm + i * 16 + (lane & 15);
                    int col = kk + (lane >> 4) * 8;
                    uint32_t addr = smem_u32(&hs[row * TSTR + col]);
                    asm volatile("ldmatrix.sync.aligned.m8n8.x4.shared.b16 {%0,%1,%2,%3},[%4];"
                                 : "=r"(afr[i][0]), "=r"(afr[i][1]), "=r"(afr[i][2]), "=r"(afr[i][3])
                                 : "r"(addr));
                }
                uint32_t bfr[4][2];
                #pragma unroll
                for (int j = 0; j < 2; j++) {
                    int grp = lane >> 3;
                    int row = wn + j * 16 + (grp >> 1) * 8 + (lane & 7);
                    int col = kk + (grp & 1) * 8;
                    uint32_t addr = smem_u32(&ws[row * TSTR + col]);
                    uint32_t r0, r1, r2, r3;
                    asm volatile("ldmatrix.sync.aligned.m8n8.x4.shared.b16 {%0,%1,%2,%3},[%4];"
                                 : "=r"(r0), "=r"(r1), "=r"(r2), "=r"(r3) : "r"(addr));
                    bfr[j * 2][0] = r0; bfr[j * 2][1] = r1;
                    bfr[j * 2 + 1][0] = r2; bfr[j * 2 + 1][1] = r3;
                }
                #pragma unroll
                for (int i = 0; i < 2; i++)
                    #pragma unroll
                    for (int j = 0; j < 4; j++) {
                        asm volatile(
                            "mma.sync.aligned.m16n8k16.row.col.f32.f16.f16.f32 "
                            "{%0,%1,%2,%3},{%4,%5,%6,%7},{%8,%9},{%0,%1,%2,%3};"
                            : "+f"(acc[i][j][0]), "+f"(acc[i][j][1]),
                              "+f"(acc[i][j][2]), "+f"(acc[i][j][3])
                            : "r"(afr[i][0]), "r"(afr[i][1]), "r"(afr[i][2]), "r"(afr[i][3]),
                              "r"(bfr[j][0]), "r"(bfr[j][1]));
                    }
            }
            __syncthreads();

            if (ck == 0) issue_h(0, 2);
            else if (ck == 1) issue_h(1, 3);
        }

        // write gate pre-activations (h@W^T part) to smem
        const int mrow = lane >> 2, nc2 = (lane & 3) * 2;
        #pragma unroll
        for (int i = 0; i < 2; i++) {
            int r0 = wm + i * 16 + mrow;
            #pragma unroll
            for (int j = 0; j < 4; j++) {
                int col = wn + j * 8 + nc2;
                Gs[r0 * 68 + col]       = acc[i][j][0];
                Gs[r0 * 68 + col + 1]   = acc[i][j][1];
                Gs[(r0 + 8) * 68 + col]     = acc[i][j][2];
                Gs[(r0 + 8) * 68 + col + 1] = acc[i][j][3];
            }
        }
        __syncthreads();

        // cell update: 8 cells per thread, all operands in smem
        #pragma unroll
        for (int it = 0; it < 8; it++) {
            int bl = (tid >> 4) + it * 16;
            float gi = fsig (Gs[bl * 68 +  0 + jj] + Xs[bl * 68 +  0 + jj] + bs[0]);
            float gf = fsig (Gs[bl * 68 + 16 + jj] + Xs[bl * 68 + 16 + jj] + bs[1]);
            float gg = ftanh(Gs[bl * 68 + 32 + jj] + Xs[bl * 68 + 32 + jj] + bs[2]);
            float go = fsig (Gs[bl * 68 + 48 + jj] + Xs[bl * 68 + 48 + jj] + bs[3]);
            float c = fmaf(gf, creg[it], gi * gg);
            creg[it] = c;
            __half h16 = __float2half_rn(go * ftanh(c));
            g_hfp16[bl * Hd + jt * 16 + jj] = h16;
            s_hid[((size_t)bl * Tl + t) * Hd + jt * 16 + jj] = h16;
        }
        grid_sync_n(32);
    }
}

// ---------------- launch --------------------------------------------------------
extern "C" void kernel_launch(void* const* d_in, const int* in_sizes, int n_in,
                              void* d_out, int out_size)
{
    const float* features = (const float*)d_in[0];   // [B,F]
    const int*   seqs     = (const int*)  d_in[1];   // [B,T-1]
    const float* W_in  = (const float*)d_in[3];      // [E,F]
    const float* b_in  = (const float*)d_in[4];      // [E]
    const float* emb   = (const float*)d_in[5];      // [V,E]
    const float* W_ih  = (const float*)d_in[6];      // [4H,E]
    const float* W_hh  = (const float*)d_in[7];      // [4H,H]
    const float* b_ih  = (const float*)d_in[8];      // [4H]
    const float* b_hh  = (const float*)d_in[9];      // [4H]
    const float* W_out = (const float*)d_in[10];     // [V,H]
    const float* b_out = (const float*)d_in[11];     // [V]
    float* out = (float*)d_out;                      // [B,T,V]

    float* p_xg;
    cudaGetSymbolAddress((void**)&p_xg, g_xg);
    __half *p_sseq, *p_Wih, *p_hid, *p_Wout;
    cudaGetSymbolAddress((void**)&p_sseq, s_seq);
    cudaGetSymbolAddress((void**)&p_Wih,  s_Wih);
    cudaGetSymbolAddress((void**)&p_hid,  s_hid);
    cudaGetSymbolAddress((void**)&p_Wout, s_Wout);

    cudaFuncSetAttribute(gemm_mma, cudaFuncAttributeMaxDynamicSharedMemorySize, SMEM_MM);
    cudaFuncSetAttribute(lstm_tc,  cudaFuncAttributeMaxDynamicSharedMemorySize, SMEM_LSTM);

    const int TPB = 256;
    auto nb = [](size_t n, int t) { return (int)((n + t - 1) / t); };

    // 1) x0 = features @ W_in^T + b_in (fp32 accum) -> s_seq rows [0,128) fp16
    {
        dim3 grid(Ed / 32, Bb / 32);   // 64 CTAs
        gemm_tn_h<32, 32, 8, 2, 2><<<grid, 256>>>(
            features, W_in, b_in, p_sseq, Bb, Ed, Fdim);
    }

    // 2) gather embeddings (fp16) for t = 1..T-1
    gather_emb<<<(Tl - 1) * Bb, 128>>>(seqs, emb);

    // 3) W_ih -> fp16, xg GEMM  [5120, 2048] K=512 (single fp16)
    tofp16<<<nb((size_t)H4 * Ed, TPB), TPB>>>(W_ih, p_Wih, (size_t)H4 * Ed);
    {
        dim3 grid(H4 / 128, BT / 128);   // (16,40)
        gemm_mma<<<grid, 256, SMEM_MM>>>(p_sseq, p_Wih, b_ih, p_xg, BT, H4, Ed);
    }

    // 4) persistent tensor-core recurrence (writes h fp16 into s_hid)
    lstm_tc<<<32, 256, SMEM_LSTM>>>(W_hh, b_hh);

    // 5) W_out -> fp16, output GEMM [5120, 10000] K=512 (single fp16)
    tofp16<<<nb((size_t)Vd * Hd, TPB), TPB>>>(W_out, p_Wout, (size_t)Vd * Hd);
    {
        dim3 grid((Vd + 127) / 128, BT / 128);   // (79,40)
        gemm_mma<<<grid, 256, SMEM_MM>>>(p_hid, p_Wout, b_out, out, BT, Vd, Ed);
    }
}

// round 11
// speedup vs baseline: 2.7061x; 1.0331x over previous
#include <cuda_runtime.h>
#include <cuda_bf16.h>
#include <cuda_fp16.h>
#include <cstdint>

// Problem constants
#define Bb   128
#define Fdim 1536
#define Ed   512
#define Hd   512
#define H4   2048
#define Vd   10000
#define Tl   40
#define BT   (Bb*Tl)     // 5120

// ---------------- scratch (static device memory) -----------------------------
__device__ float g_xg[(size_t)BT * H4];            // [T*B, 4H]
__device__ __align__(16) __half g_hfp16[Bb * Hd];  // recurrent h (fp16)

// fp16 operand buffers
__device__ __align__(16) __half s_seq [(size_t)BT * Ed];    // A of xg (fp16 seq)
__device__ __align__(16) __half s_Wih [(size_t)H4 * Ed];    // B of xg
__device__ __align__(16) __half s_hid [(size_t)BT * Ed];    // A of out GEMM
__device__ __align__(16) __half s_Wout[(size_t)Vd * Ed];    // B of out GEMM

// grid barrier state
__device__ unsigned int g_bar_cnt = 0;
__device__ volatile unsigned int g_bar_gen = 0;

// fast MUFU-only activations (EX2 + RCP; ~2ulp)
__device__ __forceinline__ float fsig(float x) {
    return __fdividef(1.0f, 1.0f + __expf(-x));
}
__device__ __forceinline__ float ftanh(float x) {
    return fmaf(-2.0f, __fdividef(1.0f, 1.0f + __expf(2.0f * x)), 1.0f);
}

__device__ __forceinline__ uint32_t smem_u32(const void* p) {
    return (uint32_t)__cvta_generic_to_shared(p);
}

template<int N>
__device__ __forceinline__ void cp_wait() {
    asm volatile("cp.async.wait_group %0;\n" :: "n"(N));
}

// ---------------- fp32 SIMT GEMM for x0, fp16 output: C = A @ B^T + bias ------
template<int BM, int BN, int BK, int TM, int TN>
__global__ void gemm_tn_h(const float* __restrict__ A,
                          const float* __restrict__ Bw,
                          const float* __restrict__ bias,
                          __half* __restrict__ C,
                          int M, int N, int K)
{
    constexpr int NT = (BM / TM) * (BN / TN);
    static_assert(NT == 256, "need 256 threads");
    __shared__ float As[BK][BM];
    __shared__ float Bs[BK][BN];

    const int m0 = blockIdx.y * BM;
    const int n0 = blockIdx.x * BN;
    const int tid = threadIdx.x;
    constexpr int NTX = BN / TN;
    const int tc = tid % NTX;
    const int tr = tid / NTX;

    float acc[TM][TN];
    #pragma unroll
    for (int i = 0; i < TM; i++)
        #pragma unroll
        for (int j = 0; j < TN; j++) acc[i][j] = 0.0f;

    constexpr int A_LD4 = BM * BK / 4;
    constexpr int B_LD4 = BN * BK / 4;
    constexpr int K4 = BK / 4;

    for (int k0 = 0; k0 < K; k0 += BK) {
        #pragma unroll
        for (int i = tid; i < A_LD4; i += NT) {
            int row = i / K4;
            int kc  = (i % K4) * 4;
            float4 v = *reinterpret_cast<const float4*>(
                A + (size_t)(m0 + row) * K + k0 + kc);
            As[kc + 0][row] = v.x; As[kc + 1][row] = v.y;
            As[kc + 2][row] = v.z; As[kc + 3][row] = v.w;
        }
        #pragma unroll
        for (int i = tid; i < B_LD4; i += NT) {
            int row = i / K4;
            int kc  = (i % K4) * 4;
            float4 v = *reinterpret_cast<const float4*>(
                Bw + (size_t)(n0 + row) * K + k0 + kc);
            Bs[kc + 0][row] = v.x; Bs[kc + 1][row] = v.y;
            Bs[kc + 2][row] = v.z; Bs[kc + 3][row] = v.w;
        }
        __syncthreads();

        #pragma unroll
        for (int k = 0; k < BK; k++) {
            float ra[TM], rb[TN];
            #pragma unroll
            for (int i = 0; i < TM; i++) ra[i] = As[k][tr * TM + i];
            #pragma unroll
            for (int j = 0; j < TN; j++) rb[j] = Bs[k][tc * TN + j];
            #pragma unroll
            for (int i = 0; i < TM; i++)
                #pragma unroll
                for (int j = 0; j < TN; j++)
                    acc[i][j] = fmaf(ra[i], rb[j], acc[i][j]);
        }
        __syncthreads();
    }

    #pragma unroll
    for (int i = 0; i < TM; i++) {
        int m = m0 + tr * TM + i;
        #pragma unroll
        for (int j = 0; j < TN; j++) {
            int n = n0 + tc * TN + j;
            C[(size_t)m * N + n] = __float2half_rn(acc[i][j] + bias[n]);
        }
    }
}

// ---------------- fp16 HMMA GEMM: C = A @ B^T + bias ---------------------------
// Tile 128x128x32, 256 threads, 5-stage cp.async with prefetch distance 3:
// the stage written at iter ck was consumed at iter ck-2 (readers already past
// iter (ck-1)'s barrier) -> ONE __syncthreads per chunk. 2 CTAs/SM.
#define STRIDEg 40
#define SA_ST   (128 * STRIDEg)
#define NST     5
#define SMEM_MM (NST * 2 * SA_ST * 2)    // 102400 bytes

__global__ void __launch_bounds__(256, 2)
gemm_mma(const __half* __restrict__ A,
         const __half* __restrict__ B,
         const float* __restrict__ bias,
         float* __restrict__ C,
         int M, int N, int K)
{
    extern __shared__ __align__(16) uint16_t smbuf[];
    uint16_t* Asm = smbuf;
    uint16_t* Bsm = smbuf + NST * SA_ST;

    const int tid  = threadIdx.x;
    const int warp = tid >> 5, lane = tid & 31;
    const int wm = (warp >> 2) * 64;
    const int wn = (warp & 3) * 32;
    const int m0 = blockIdx.y * 128, n0 = blockIdx.x * 128;
    const int KT = K / 32;

    float acc[4][4][4];
    #pragma unroll
    for (int i = 0; i < 4; i++)
        #pragma unroll
        for (int j = 0; j < 4; j++)
            #pragma unroll
            for (int r = 0; r < 4; r++) acc[i][j][r] = 0.0f;

    auto load_tile = [&](int buf, int kt) {
        const int k0 = kt * 32;
        #pragma unroll
        for (int it = 0; it < 2; it++) {
            int task = tid + it * 256;
            int r = task >> 2, c = task & 3;
            uint32_t dst = smem_u32(&Asm[buf * SA_ST + r * STRIDEg + c * 8]);
            const void* src = A + (size_t)(m0 + r) * K + k0 + c * 8;
            asm volatile("cp.async.cg.shared.global [%0],[%1],16;\n" :: "r"(dst), "l"(src));
        }
        #pragma unroll
        for (int it = 0; it < 2; it++) {
            int task = tid + it * 256;
            int r = task >> 2, c = task & 3;
            if (n0 + r < N) {
                uint32_t dst = smem_u32(&Bsm[buf * SA_ST + r * STRIDEg + c * 8]);
                const void* src = B + (size_t)(n0 + r) * K + k0 + c * 8;
                asm volatile("cp.async.cg.shared.global [%0],[%1],16;\n" :: "r"(dst), "l"(src));
            }
        }
        asm volatile("cp.async.commit_group;\n");
    };

    // prefetch 3 stages
    load_tile(0, 0);
    if (KT > 1) load_tile(1, 1); else asm volatile("cp.async.commit_group;\n");
    if (KT > 2) load_tile(2, 2); else asm volatile("cp.async.commit_group;\n");

    int buf = 0, pbuf = 3;
    for (int ck = 0; ck < KT; ck++) {
        if (ck + 3 < KT) load_tile(pbuf, ck + 3);
        else             asm volatile("cp.async.commit_group;\n");
        cp_wait<3>();
        __syncthreads();   // single barrier per chunk

        const uint16_t* as = Asm + buf * SA_ST;
        const uint16_t* bs = Bsm + buf * SA_ST;

        #pragma unroll
        for (int kk = 0; kk < 32; kk += 16) {
            uint32_t afr[4][4];
            #pragma unroll
            for (int i = 0; i < 4; i++) {
                int row = wm + i * 16 + (lane & 15);
                int col = kk + (lane >> 4) * 8;
                uint32_t addr = smem_u32(&as[row * STRIDEg + col]);
                asm volatile("ldmatrix.sync.aligned.m8n8.x4.shared.b16 {%0,%1,%2,%3},[%4];"
                             : "=r"(afr[i][0]), "=r"(afr[i][1]), "=r"(afr[i][2]), "=r"(afr[i][3])
                             : "r"(addr));
            }
            uint32_t bfr[4][2];
            #pragma unroll
            for (int j = 0; j < 2; j++) {
                int grp = lane >> 3;
                int row = wn + j * 16 + (grp >> 1) * 8 + (lane & 7);
                int col = kk + (grp & 1) * 8;
                uint32_t addr = smem_u32(&bs[row * STRIDEg + col]);
                uint32_t r0, r1, r2, r3;
                asm volatile("ldmatrix.sync.aligned.m8n8.x4.shared.b16 {%0,%1,%2,%3},[%4];"
                             : "=r"(r0), "=r"(r1), "=r"(r2), "=r"(r3) : "r"(addr));
                bfr[j * 2][0] = r0; bfr[j * 2][1] = r1;
                bfr[j * 2 + 1][0] = r2; bfr[j * 2 + 1][1] = r3;
            }
            #pragma unroll
            for (int i = 0; i < 4; i++)
                #pragma unroll
                for (int j = 0; j < 4; j++) {
                    asm volatile(
                        "mma.sync.aligned.m16n8k16.row.col.f32.f16.f16.f32 "
                        "{%0,%1,%2,%3},{%4,%5,%6,%7},{%8,%9},{%0,%1,%2,%3};"
                        : "+f"(acc[i][j][0]), "+f"(acc[i][j][1]),
                          "+f"(acc[i][j][2]), "+f"(acc[i][j][3])
                        : "r"(afr[i][0]), "r"(afr[i][1]), "r"(afr[i][2]), "r"(afr[i][3]),
                          "r"(bfr[j][0]), "r"(bfr[j][1]));
                }
        }
        buf  = (buf  + 1 == NST) ? 0 : buf + 1;
        pbuf = (pbuf + 1 == NST) ? 0 : pbuf + 1;
    }

    const int mrow = lane >> 2, nc2 = (lane & 3) * 2;
    #pragma unroll
    for (int i = 0; i < 4; i++) {
        int gm = m0 + wm + i * 16 + mrow;
        float* Crow0 = C + (size_t)gm * N;
        float* Crow1 = C + (size_t)(gm + 8) * N;
        #pragma unroll
        for (int j = 0; j < 4; j++) {
            int gn = n0 + wn + j * 8 + nc2;
            if (gn < N) {
                float bv = bias[gn];
                Crow0[gn] = acc[i][j][0] + bv;
                Crow1[gn] = acc[i][j][2] + bv;
            }
            if (gn + 1 < N) {
                float bv = bias[gn + 1];
                Crow0[gn + 1] = acc[i][j][1] + bv;
                Crow1[gn + 1] = acc[i][j][3] + bv;
            }
        }
    }
}

// ---------------- convert kernel -------------------------------------------------
__global__ void tofp16(const float* __restrict__ X, __half* __restrict__ Y, size_t total)
{
    size_t i = (size_t)blockIdx.x * blockDim.x + threadIdx.x;
    if (i < total) Y[i] = __float2half_rn(X[i]);
}

// ---------------- gather word embeddings (fp32 -> fp16) into s_seq rows t>=1 ---
__global__ void gather_emb(const int* __restrict__ seqs,
                           const float* __restrict__ emb)
{
    int bid = blockIdx.x;
    int t1  = bid / Bb;
    int b   = bid % Bb;
    int word = seqs[b * (Tl - 1) + t1];
    const float4* src = reinterpret_cast<const float4*>(emb + (size_t)word * Ed);
    __half* dst = s_seq + (size_t)((t1 + 1) * Bb + b) * Ed;
    for (int i = threadIdx.x; i < Ed / 4; i += blockDim.x) {
        float4 v = src[i];
        __half2 h01 = __floats2half2_rn(v.x, v.y);
        __half2 h23 = __floats2half2_rn(v.z, v.w);
        *reinterpret_cast<__half2*>(dst + i * 4)     = h01;
        *reinterpret_cast<__half2*>(dst + i * 4 + 2) = h23;
    }
}

// ---------------- persistent tensor-core LSTM recurrence ------------------------
#define LCH   128                      // K per chunk
#define NCH   (Hd / LCH)               // 4
#define TSTR  136                      // chunk tile row stride (halves)
#define W_CH  (64 * TSTR)
#define H_STG (128 * TSTR)
#define SMEM_LSTM ((NCH * W_CH + 2 * H_STG) * 2 + 2 * 128 * 68 * 4)  // 208896 B

__device__ __forceinline__ void grid_sync_n(unsigned int nctas)
{
    __threadfence();
    __syncthreads();
    if (threadIdx.x == 0) {
        unsigned gen = g_bar_gen;
        if (atomicAdd(&g_bar_cnt, 1u) == nctas - 1u) {
            g_bar_cnt = 0;
            __threadfence();
            g_bar_gen = gen + 1;
        } else {
            while (g_bar_gen == gen) __nanosleep(16);
            __threadfence();
        }
    }
    __syncthreads();
}

__global__ void __launch_bounds__(256, 1)
lstm_tc(const float* __restrict__ Whh,   // [4H, H]
        const float* __restrict__ bhh)   // [4H]
{
    extern __shared__ __align__(16) uint16_t lsm[];
    uint16_t* Ws = lsm;                          // NCH x 64 x TSTR
    uint16_t* Hb = lsm + NCH * W_CH;             // 2 x 128 x TSTR
    float*    Gs = (float*)(Hb + 2 * H_STG);     // 128 x 68
    float*    Xs = Gs + 128 * 68;                // 128 x 68 (xg slice)

    const int tid  = threadIdx.x;
    const int warp = tid >> 5, lane = tid & 31;
    const int wm = (warp >> 1) * 32;   // 0,32,64,96
    const int wn = (warp & 1) * 32;    // 0,32
    const int jt = blockIdx.x;         // hidden slice

    // ---- load W_hh tile to smem as fp16 (once) ----
    #pragma unroll
    for (int it = 0; it < 32; it++) {
        int task = tid + it * 256;
        int row = task >> 7;
        int c4  = task & 127;
        int grow = (row >> 4) * Hd + jt * 16 + (row & 15);
        float4 v = *reinterpret_cast<const float4*>(Whh + (size_t)grow * Hd + c4 * 4);
        int ck = c4 >> 5;
        int kc = (c4 & 31) * 4;
        __half2 h01 = __floats2half2_rn(v.x, v.y);
        __half2 h23 = __floats2half2_rn(v.z, v.w);
        uint16_t* dst = Ws + ck * W_CH + row * TSTR + kc;
        *reinterpret_cast<__half2*>(dst)     = h01;
        *reinterpret_cast<__half2*>(dst + 2) = h23;
    }

    const int jj = tid & 15;
    float creg[8];
    #pragma unroll
    for (int i = 0; i < 8; i++) creg[i] = 0.0f;
    float bs[4];
    #pragma unroll
    for (int g = 0; g < 4; g++) bs[g] = bhh[g * Hd + jt * 16 + jj];

    // zero this CTA's h slice
    #pragma unroll
    for (int it = 0; it < 8; it++) {
        int bl = (tid >> 4) + it * 16;
        g_hfp16[bl * Hd + jt * 16 + jj] = __float2half_rn(0.0f);
    }
    grid_sync_n(32);

    // xg slice prefetch: 128 bl x 4 gates x 16 floats = 2048 x 16B tasks
    auto issue_xg = [&](const float* xg_t) {
        #pragma unroll
        for (int it = 0; it < 8; it++) {
            int task = tid + it * 256;
            int bl  = task >> 4;
            int rem = task & 15;
            int g = rem >> 2, q = rem & 3;
            uint32_t dst = smem_u32(&Xs[bl * 68 + g * 16 + q * 4]);
            const void* src = xg_t + (size_t)bl * H4 + g * Hd + jt * 16 + q * 4;
            asm volatile("cp.async.cg.shared.global [%0],[%1],16;\n" :: "r"(dst), "l"(src));
        }
        asm volatile("cp.async.commit_group;\n");
    };

    // h chunk: 128 rows x 128 halves = 2048 x 16B tasks
    auto issue_h = [&](int stage, int ck) {
        #pragma unroll
        for (int it = 0; it < 8; it++) {
            int task = tid + it * 256;
            int r  = task >> 4;
            int c8 = task & 15;
            uint32_t dst = smem_u32(&Hb[stage * H_STG + r * TSTR + c8 * 8]);
            const void* src = g_hfp16 + r * Hd + ck * LCH + c8 * 8;
            asm volatile("cp.async.cg.shared.global [%0],[%1],16;\n" :: "r"(dst), "l"(src));
        }
        asm volatile("cp.async.commit_group;\n");
    };

    // xg for t=0 issued ahead of the step loop (lands during pipeline fill)
    issue_xg(g_xg);

    for (int t = 0; t < Tl; t++) {
        float acc[2][4][4];
        #pragma unroll
        for (int i = 0; i < 2; i++)
            #pragma unroll
            for (int j = 0; j < 4; j++)
                #pragma unroll
                for (int r = 0; r < 4; r++) acc[i][j][r] = 0.0f;

        issue_h(0, 0);     // group: h0   (xg(t) is the older group)
        issue_h(1, 1);     // group: h1

        #pragma unroll
        for (int ck = 0; ck < NCH; ck++) {
            if (ck < 3) cp_wait<1>();
            else        cp_wait<0>();
            __syncthreads();

            const int stage = ck & 1;
            const uint16_t* hs = Hb + stage * H_STG;
            const uint16_t* ws = Ws + ck * W_CH;

            #pragma unroll
            for (int kk = 0; kk < LCH; kk += 16) {
                uint32_t afr[2][4];
                #pragma unroll
                for (int i = 0; i < 2; i++) {
                    int row = wm + i * 16 + (lane & 15);
                    int col = kk + (lane >> 4) * 8;
                    uint32_t addr = smem_u32(&hs[row * TSTR + col]);
                    asm volatile("ldmatrix.sync.aligned.m8n8.x4.shared.b16 {%0,%1,%2,%3},[%4];"
                                 : "=r"(afr[i][0]), "=r"(afr[i][1]), "=r"(afr[i][2]), "=r"(afr[i][3])
                                 : "r"(addr));
                }
                uint32_t bfr[4][2];
                #pragma unroll
                for (int j = 0; j < 2; j++) {
                    int grp = lane >> 3;
                    int row = wn + j * 16 + (grp >> 1) * 8 + (lane & 7);
                    int col = kk + (grp & 1) * 8;
                    uint32_t addr = smem_u32(&ws[row * TSTR + col]);
                    uint32_t r0, r1, r2, r3;
                    asm volatile("ldmatrix.sync.aligned.m8n8.x4.shared.b16 {%0,%1,%2,%3},[%4];"
                                 : "=r"(r0), "=r"(r1), "=r"(r2), "=r"(r3) : "r"(addr));
                    bfr[j * 2][0] = r0; bfr[j * 2][1] = r1;
                    bfr[j * 2 + 1][0] = r2; bfr[j * 2 + 1][1] = r3;
                }
                #pragma unroll
                for (int i = 0; i < 2; i++)
                    #pragma unroll
                    for (int j = 0; j < 4; j++) {
                        asm volatile(
                            "mma.sync.aligned.m16n8k16.row.col.f32.f16.f16.f32 "
                            "{%0,%1,%2,%3},{%4,%5,%6,%7},{%8,%9},{%0,%1,%2,%3};"
                            : "+f"(acc[i][j][0]), "+f"(acc[i][j][1]),
                              "+f"(acc[i][j][2]), "+f"(acc[i][j][3])
                            : "r"(afr[i][0]), "r"(afr[i][1]), "r"(afr[i][2]), "r"(afr[i][3]),
                              "r"(bfr[j][0]), "r"(bfr[j][1]));
                    }
            }
            __syncthreads();

            if (ck == 0) issue_h(0, 2);
            else if (ck == 1) issue_h(1, 3);
        }

        // write gate pre-activations (h@W^T part) to smem
        const int mrow = lane >> 2, nc2 = (lane & 3) * 2;
        #pragma unroll
        for (int i = 0; i < 2; i++) {
            int r0 = wm + i * 16 + mrow;
            #pragma unroll
            for (int j = 0; j < 4; j++) {
                int col = wn + j * 8 + nc2;
                Gs[r0 * 68 + col]       = acc[i][j][0];
                Gs[r0 * 68 + col + 1]   = acc[i][j][1];
                Gs[(r0 + 8) * 68 + col]     = acc[i][j][2];
                Gs[(r0 + 8) * 68 + col + 1] = acc[i][j][3];
            }
        }
        __syncthreads();

        // cell update: 8 cells per thread, all operands in smem
        #pragma unroll
        for (int it = 0; it < 8; it++) {
            int bl = (tid >> 4) + it * 16;
            float gi = fsig (Gs[bl * 68 +  0 + jj] + Xs[bl * 68 +  0 + jj] + bs[0]);
            float gf = fsig (Gs[bl * 68 + 16 + jj] + Xs[bl * 68 + 16 + jj] + bs[1]);
            float gg = ftanh(Gs[bl * 68 + 32 + jj] + Xs[bl * 68 + 32 + jj] + bs[2]);
            float go = fsig (Gs[bl * 68 + 48 + jj] + Xs[bl * 68 + 48 + jj] + bs[3]);
            float c = fmaf(gf, creg[it], gi * gg);
            creg[it] = c;
            __half h16 = __float2half_rn(go * ftanh(c));
            g_hfp16[bl * Hd + jt * 16 + jj] = h16;
            s_hid[((size_t)bl * Tl + t) * Hd + jt * 16 + jj] = h16;
        }

        // hoist next step's xg fetch across the barrier (lands during sync)
        __syncthreads();
        if (t + 1 < Tl) issue_xg(g_xg + (size_t)(t + 1) * Bb * H4);

        grid_sync_n(32);
    }
}

// ---------------- launch --------------------------------------------------------
extern "C" void kernel_launch(void* const* d_in, const int* in_sizes, int n_in,
                              void* d_out, int out_size)
{
    const float* features = (const float*)d_in[0];   // [B,F]
    const int*   seqs     = (const int*)  d_in[1];   // [B,T-1]
    const float* W_in  = (const float*)d_in[3];      // [E,F]
    const float* b_in  = (const float*)d_in[4];      // [E]
    const float* emb   = (const float*)d_in[5];      // [V,E]
    const float* W_ih  = (const float*)d_in[6];      // [4H,E]
    const float* W_hh  = (const float*)d_in[7];      // [4H,H]
    const float* b_ih  = (const float*)d_in[8];      // [4H]
    const float* b_hh  = (const float*)d_in[9];      // [4H]
    const float* W_out = (const float*)d_in[10];     // [V,H]
    const float* b_out = (const float*)d_in[11];     // [V]
    float* out = (float*)d_out;                      // [B,T,V]

    float* p_xg;
    cudaGetSymbolAddress((void**)&p_xg, g_xg);
    __half *p_sseq, *p_Wih, *p_hid, *p_Wout;
    cudaGetSymbolAddress((void**)&p_sseq, s_seq);
    cudaGetSymbolAddress((void**)&p_Wih,  s_Wih);
    cudaGetSymbolAddress((void**)&p_hid,  s_hid);
    cudaGetSymbolAddress((void**)&p_Wout, s_Wout);

    cudaFuncSetAttribute(gemm_mma, cudaFuncAttributeMaxDynamicSharedMemorySize, SMEM_MM);
    cudaFuncSetAttribute(lstm_tc,  cudaFuncAttributeMaxDynamicSharedMemorySize, SMEM_LSTM);

    const int TPB = 256;
    auto nb = [](size_t n, int t) { return (int)((n + t - 1) / t); };

    // 1) x0 = features @ W_in^T + b_in (fp32 accum) -> s_seq rows [0,128) fp16
    {
        dim3 grid(Ed / 32, Bb / 32);   // 64 CTAs
        gemm_tn_h<32, 32, 8, 2, 2><<<grid, 256>>>(
            features, W_in, b_in, p_sseq, Bb, Ed, Fdim);
    }

    // 2) gather embeddings (fp16) for t = 1..T-1
    gather_emb<<<(Tl - 1) * Bb, 128>>>(seqs, emb);

    // 3) W_ih -> fp16, xg GEMM  [5120, 2048] K=512 (single fp16)
    tofp16<<<nb((size_t)H4 * Ed, TPB), TPB>>>(W_ih, p_Wih, (size_t)H4 * Ed);
    {
        dim3 grid(H4 / 128, BT / 128);   // (16,40)
        gemm_mma<<<grid, 256, SMEM_MM>>>(p_sseq, p_Wih, b_ih, p_xg, BT, H4, Ed);
    }

    // 4) persistent tensor-core recurrence (writes h fp16 into s_hid)
    lstm_tc<<<32, 256, SMEM_LSTM>>>(W_hh, b_hh);

    // 5) W_out -> fp16, output GEMM [5120, 10000] K=512 (single fp16)
    tofp16<<<nb((size_t)Vd * Hd, TPB), TPB>>>(W_out, p_Wout, (size_t)Vd * Hd);
    {
        dim3 grid((Vd + 127) / 128, BT / 128);   // (79,40)
        gemm_mma<<<grid, 256, SMEM_MM>>>(p_hid, p_Wout, b_out, out, BT, Vd, Ed);
    }
}

// round 12
// speedup vs baseline: 2.7513x; 1.0167x over previous
#include <cuda_runtime.h>
#include <cuda_bf16.h>
#include <cuda_fp16.h>
#include <cstdint>

// Problem constants
#define Bb   128
#define Fdim 1536
#define Ed   512
#define Hd   512
#define H4   2048
#define Vd   10000
#define Tl   40
#define BT   (Bb*Tl)     // 5120

// ---------------- scratch (static device memory) -----------------------------
__device__ float g_xg[(size_t)BT * H4];            // [T*B, 4H]
__device__ __align__(16) __half g_hfp16[Bb * Hd];  // recurrent h (fp16)

// fp16 operand buffers
__device__ __align__(16) __half s_seq [(size_t)BT * Ed];    // A of xg (fp16 seq)
__device__ __align__(16) __half s_Wih [(size_t)H4 * Ed];    // B of xg
__device__ __align__(16) __half s_hid [(size_t)BT * Ed];    // A of out GEMM
__device__ __align__(16) __half s_Wout[(size_t)Vd * Ed];    // B of out GEMM

// grid barrier state
__device__ unsigned int g_bar_cnt = 0;
__device__ volatile unsigned int g_bar_gen = 0;

// fast MUFU-only activations (EX2 + RCP; ~2ulp)
__device__ __forceinline__ float fsig(float x) {
    return __fdividef(1.0f, 1.0f + __expf(-x));
}
__device__ __forceinline__ float ftanh(float x) {
    return fmaf(-2.0f, __fdividef(1.0f, 1.0f + __expf(2.0f * x)), 1.0f);
}

__device__ __forceinline__ uint32_t smem_u32(const void* p) {
    return (uint32_t)__cvta_generic_to_shared(p);
}

template<int N>
__device__ __forceinline__ void cp_wait() {
    asm volatile("cp.async.wait_group %0;\n" :: "n"(N));
}

// ---------------- fp32 SIMT GEMM for x0, fp16 output: C = A @ B^T + bias ------
template<int BM, int BN, int BK, int TM, int TN>
__global__ void gemm_tn_h(const float* __restrict__ A,
                          const float* __restrict__ Bw,
                          const float* __restrict__ bias,
                          __half* __restrict__ C,
                          int M, int N, int K)
{
    constexpr int NT = (BM / TM) * (BN / TN);
    static_assert(NT == 256, "need 256 threads");
    __shared__ float As[BK][BM];
    __shared__ float Bs[BK][BN];

    const int m0 = blockIdx.y * BM;
    const int n0 = blockIdx.x * BN;
    const int tid = threadIdx.x;
    constexpr int NTX = BN / TN;
    const int tc = tid % NTX;
    const int tr = tid / NTX;

    float acc[TM][TN];
    #pragma unroll
    for (int i = 0; i < TM; i++)
        #pragma unroll
        for (int j = 0; j < TN; j++) acc[i][j] = 0.0f;

    constexpr int A_LD4 = BM * BK / 4;
    constexpr int B_LD4 = BN * BK / 4;
    constexpr int K4 = BK / 4;

    for (int k0 = 0; k0 < K; k0 += BK) {
        #pragma unroll
        for (int i = tid; i < A_LD4; i += NT) {
            int row = i / K4;
            int kc  = (i % K4) * 4;
            float4 v = *reinterpret_cast<const float4*>(
                A + (size_t)(m0 + row) * K + k0 + kc);
            As[kc + 0][row] = v.x; As[kc + 1][row] = v.y;
            As[kc + 2][row] = v.z; As[kc + 3][row] = v.w;
        }
        #pragma unroll
        for (int i = tid; i < B_LD4; i += NT) {
            int row = i / K4;
            int kc  = (i % K4) * 4;
            float4 v = *reinterpret_cast<const float4*>(
                Bw + (size_t)(n0 + row) * K + k0 + kc);
            Bs[kc + 0][row] = v.x; Bs[kc + 1][row] = v.y;
            Bs[kc + 2][row] = v.z; Bs[kc + 3][row] = v.w;
        }
        __syncthreads();

        #pragma unroll
        for (int k = 0; k < BK; k++) {
            float ra[TM], rb[TN];
            #pragma unroll
            for (int i = 0; i < TM; i++) ra[i] = As[k][tr * TM + i];
            #pragma unroll
            for (int j = 0; j < TN; j++) rb[j] = Bs[k][tc * TN + j];
            #pragma unroll
            for (int i = 0; i < TM; i++)
                #pragma unroll
                for (int j = 0; j < TN; j++)
                    acc[i][j] = fmaf(ra[i], rb[j], acc[i][j]);
        }
        __syncthreads();
    }

    #pragma unroll
    for (int i = 0; i < TM; i++) {
        int m = m0 + tr * TM + i;
        #pragma unroll
        for (int j = 0; j < TN; j++) {
            int n = n0 + tc * TN + j;
            C[(size_t)m * N + n] = __float2half_rn(acc[i][j] + bias[n]);
        }
    }
}

// ---------------- fp16 HMMA GEMM: C = A @ B^T + bias ---------------------------
// Tile 128x128, 256 threads. K-chunk 64, 3-stage cp.async ring (distance 2),
// ONE __syncthreads per 64-K chunk; next-stage issue happens AFTER the barrier
// so the overwritten stage's readers (iteration ck-1) are provably done.
// 4 independent (LDSM+HMMA) micro-iterations per barrier window. 2 CTAs/SM.
#define KC      64
#define STRIDEg 72                         // row stride (halves): 4 mod 32 words -> conflict-free
#define SA_ST   (128 * STRIDEg)            // 9216 halves per stage per matrix
#define NST     3
#define SMEM_MM (NST * 2 * SA_ST * 2)      // 110592 bytes

__global__ void __launch_bounds__(256, 2)
gemm_mma(const __half* __restrict__ A,
         const __half* __restrict__ B,
         const float* __restrict__ bias,
         float* __restrict__ C,
         int M, int N, int K)
{
    extern __shared__ __align__(16) uint16_t smbuf[];
    uint16_t* Asm = smbuf;
    uint16_t* Bsm = smbuf + NST * SA_ST;

    const int tid  = threadIdx.x;
    const int warp = tid >> 5, lane = tid & 31;
    const int wm = (warp >> 2) * 64;
    const int wn = (warp & 3) * 32;
    const int m0 = blockIdx.y * 128, n0 = blockIdx.x * 128;
    const int KT = K / KC;

    float acc[4][4][4];
    #pragma unroll
    for (int i = 0; i < 4; i++)
        #pragma unroll
        for (int j = 0; j < 4; j++)
            #pragma unroll
            for (int r = 0; r < 4; r++) acc[i][j][r] = 0.0f;

    // one 64-K stage: 128 rows x 64 halves per matrix = 1024 x 16B tasks each
    auto load_tile = [&](int buf, int kt) {
        const int k0 = kt * KC;
        #pragma unroll
        for (int it = 0; it < 4; it++) {
            int task = tid + it * 256;
            int r = task >> 3, c = task & 7;
            uint32_t dst = smem_u32(&Asm[buf * SA_ST + r * STRIDEg + c * 8]);
            const void* src = A + (size_t)(m0 + r) * K + k0 + c * 8;
            asm volatile("cp.async.cg.shared.global [%0],[%1],16;\n" :: "r"(dst), "l"(src));
        }
        #pragma unroll
        for (int it = 0; it < 4; it++) {
            int task = tid + it * 256;
            int r = task >> 3, c = task & 7;
            if (n0 + r < N) {
                uint32_t dst = smem_u32(&Bsm[buf * SA_ST + r * STRIDEg + c * 8]);
                const void* src = B + (size_t)(n0 + r) * K + k0 + c * 8;
                asm volatile("cp.async.cg.shared.global [%0],[%1],16;\n" :: "r"(dst), "l"(src));
            }
        }
        asm volatile("cp.async.commit_group;\n");
    };

    // prefetch 2 stages
    load_tile(0, 0);
    if (KT > 1) load_tile(1, 1); else asm volatile("cp.async.commit_group;\n");

    int buf = 0, pbuf = 2;
    for (int ck = 0; ck < KT; ck++) {
        cp_wait<1>();          // group(ck) complete; <=1 newer pending
        __syncthreads();       // also: all readers of stage pbuf (iter ck-1) done
        if (ck + 2 < KT) load_tile(pbuf, ck + 2);
        else             asm volatile("cp.async.commit_group;\n");

        const uint16_t* as = Asm + buf * SA_ST;
        const uint16_t* bs = Bsm + buf * SA_ST;

        #pragma unroll
        for (int kk = 0; kk < KC; kk += 16) {
            uint32_t afr[4][4];
            #pragma unroll
            for (int i = 0; i < 4; i++) {
                int row = wm + i * 16 + (lane & 15);
                int col = kk + (lane >> 4) * 8;
                uint32_t addr = smem_u32(&as[row * STRIDEg + col]);
                asm volatile("ldmatrix.sync.aligned.m8n8.x4.shared.b16 {%0,%1,%2,%3},[%4];"
                             : "=r"(afr[i][0]), "=r"(afr[i][1]), "=r"(afr[i][2]), "=r"(afr[i][3])
                             : "r"(addr));
            }
            uint32_t bfr[4][2];
            #pragma unroll
            for (int j = 0; j < 2; j++) {
                int grp = lane >> 3;
                int row = wn + j * 16 + (grp >> 1) * 8 + (lane & 7);
                int col = kk + (grp & 1) * 8;
                uint32_t addr = smem_u32(&bs[row * STRIDEg + col]);
                uint32_t r0, r1, r2, r3;
                asm volatile("ldmatrix.sync.aligned.m8n8.x4.shared.b16 {%0,%1,%2,%3},[%4];"
                             : "=r"(r0), "=r"(r1), "=r"(r2), "=r"(r3) : "r"(addr));
                bfr[j * 2][0] = r0; bfr[j * 2][1] = r1;
                bfr[j * 2 + 1][0] = r2; bfr[j * 2 + 1][1] = r3;
            }
            #pragma unroll
            for (int i = 0; i < 4; i++)
                #pragma unroll
                for (int j = 0; j < 4; j++) {
                    asm volatile(
                        "mma.sync.aligned.m16n8k16.row.col.f32.f16.f16.f32 "
                        "{%0,%1,%2,%3},{%4,%5,%6,%7},{%8,%9},{%0,%1,%2,%3};"
                        : "+f"(acc[i][j][0]), "+f"(acc[i][j][1]),
                          "+f"(acc[i][j][2]), "+f"(acc[i][j][3])
                        : "r"(afr[i][0]), "r"(afr[i][1]), "r"(afr[i][2]), "r"(afr[i][3]),
                          "r"(bfr[j][0]), "r"(bfr[j][1]));
                }
        }
        buf  = (buf  + 1 == NST) ? 0 : buf + 1;
        pbuf = (pbuf + 1 == NST) ? 0 : pbuf + 1;
    }

    const int mrow = lane >> 2, nc2 = (lane & 3) * 2;
    #pragma unroll
    for (int i = 0; i < 4; i++) {
        int gm = m0 + wm + i * 16 + mrow;
        float* Crow0 = C + (size_t)gm * N;
        float* Crow1 = C + (size_t)(gm + 8) * N;
        #pragma unroll
        for (int j = 0; j < 4; j++) {
            int gn = n0 + wn + j * 8 + nc2;
            if (gn < N) {
                float bv = bias[gn];
                Crow0[gn] = acc[i][j][0] + bv;
                Crow1[gn] = acc[i][j][2] + bv;
            }
            if (gn + 1 < N) {
                float bv = bias[gn + 1];
                Crow0[gn + 1] = acc[i][j][1] + bv;
                Crow1[gn + 1] = acc[i][j][3] + bv;
            }
        }
    }
}

// ---------------- convert kernel -------------------------------------------------
__global__ void tofp16(const float* __restrict__ X, __half* __restrict__ Y, size_t total)
{
    size_t i = (size_t)blockIdx.x * blockDim.x + threadIdx.x;
    if (i < total) Y[i] = __float2half_rn(X[i]);
}

// ---------------- gather word embeddings (fp32 -> fp16) into s_seq rows t>=1 ---
__global__ void gather_emb(const int* __restrict__ seqs,
                           const float* __restrict__ emb)
{
    int bid = blockIdx.x;
    int t1  = bid / Bb;
    int b   = bid % Bb;
    int word = seqs[b * (Tl - 1) + t1];
    const float4* src = reinterpret_cast<const float4*>(emb + (size_t)word * Ed);
    __half* dst = s_seq + (size_t)((t1 + 1) * Bb + b) * Ed;
    for (int i = threadIdx.x; i < Ed / 4; i += blockDim.x) {
        float4 v = src[i];
        __half2 h01 = __floats2half2_rn(v.x, v.y);
        __half2 h23 = __floats2half2_rn(v.z, v.w);
        *reinterpret_cast<__half2*>(dst + i * 4)     = h01;
        *reinterpret_cast<__half2*>(dst + i * 4 + 2) = h23;
    }
}

// ---------------- persistent tensor-core LSTM recurrence ------------------------
#define LCH   128                      // K per chunk
#define NCH   (Hd / LCH)               // 4
#define TSTR  136                      // chunk tile row stride (halves)
#define W_CH  (64 * TSTR)
#define H_STG (128 * TSTR)
#define SMEM_LSTM ((NCH * W_CH + 2 * H_STG) * 2 + 2 * 128 * 68 * 4)  // 208896 B

__device__ __forceinline__ void grid_sync_n(unsigned int nctas)
{
    __threadfence();
    __syncthreads();
    if (threadIdx.x == 0) {
        unsigned gen = g_bar_gen;
        if (atomicAdd(&g_bar_cnt, 1u) == nctas - 1u) {
            g_bar_cnt = 0;
            __threadfence();
            g_bar_gen = gen + 1;
        } else {
            while (g_bar_gen == gen) __nanosleep(16);
            __threadfence();
        }
    }
    __syncthreads();
}

__global__ void __launch_bounds__(256, 1)
lstm_tc(const float* __restrict__ Whh,   // [4H, H]
        const float* __restrict__ bhh)   // [4H]
{
    extern __shared__ __align__(16) uint16_t lsm[];
    uint16_t* Ws = lsm;                          // NCH x 64 x TSTR
    uint16_t* Hb = lsm + NCH * W_CH;             // 2 x 128 x TSTR
    float*    Gs = (float*)(Hb + 2 * H_STG);     // 128 x 68
    float*    Xs = Gs + 128 * 68;                // 128 x 68 (xg slice)

    const int tid  = threadIdx.x;
    const int warp = tid >> 5, lane = tid & 31;
    const int wm = (warp >> 1) * 32;   // 0,32,64,96
    const int wn = (warp & 1) * 32;    // 0,32
    const int jt = blockIdx.x;         // hidden slice

    // ---- load W_hh tile to smem as fp16 (once) ----
    #pragma unroll
    for (int it = 0; it < 32; it++) {
        int task = tid + it * 256;
        int row = task >> 7;
        int c4  = task & 127;
        int grow = (row >> 4) * Hd + jt * 16 + (row & 15);
        float4 v = *reinterpret_cast<const float4*>(Whh + (size_t)grow * Hd + c4 * 4);
        int ck = c4 >> 5;
        int kc = (c4 & 31) * 4;
        __half2 h01 = __floats2half2_rn(v.x, v.y);
        __half2 h23 = __floats2half2_rn(v.z, v.w);
        uint16_t* dst = Ws + ck * W_CH + row * TSTR + kc;
        *reinterpret_cast<__half2*>(dst)     = h01;
        *reinterpret_cast<__half2*>(dst + 2) = h23;
    }

    const int jj = tid & 15;
    float creg[8];
    #pragma unroll
    for (int i = 0; i < 8; i++) creg[i] = 0.0f;
    float bs[4];
    #pragma unroll
    for (int g = 0; g < 4; g++) bs[g] = bhh[g * Hd + jt * 16 + jj];

    // zero this CTA's h slice
    #pragma unroll
    for (int it = 0; it < 8; it++) {
        int bl = (tid >> 4) + it * 16;
        g_hfp16[bl * Hd + jt * 16 + jj] = __float2half_rn(0.0f);
    }
    grid_sync_n(32);

    // xg slice prefetch: 128 bl x 4 gates x 16 floats = 2048 x 16B tasks
    auto issue_xg = [&](const float* xg_t) {
        #pragma unroll
        for (int it = 0; it < 8; it++) {
            int task = tid + it * 256;
            int bl  = task >> 4;
            int rem = task & 15;
            int g = rem >> 2, q = rem & 3;
            uint32_t dst = smem_u32(&Xs[bl * 68 + g * 16 + q * 4]);
            const void* src = xg_t + (size_t)bl * H4 + g * Hd + jt * 16 + q * 4;
            asm volatile("cp.async.cg.shared.global [%0],[%1],16;\n" :: "r"(dst), "l"(src));
        }
        asm volatile("cp.async.commit_group;\n");
    };

    // h chunk: 128 rows x 128 halves = 2048 x 16B tasks
    auto issue_h = [&](int stage, int ck) {
        #pragma unroll
        for (int it = 0; it < 8; it++) {
            int task = tid + it * 256;
            int r  = task >> 4;
            int c8 = task & 15;
            uint32_t dst = smem_u32(&Hb[stage * H_STG + r * TSTR + c8 * 8]);
            const void* src = g_hfp16 + r * Hd + ck * LCH + c8 * 8;
            asm volatile("cp.async.cg.shared.global [%0],[%1],16;\n" :: "r"(dst), "l"(src));
        }
        asm volatile("cp.async.commit_group;\n");
    };

    // xg for t=0 issued ahead of the step loop (lands during pipeline fill)
    issue_xg(g_xg);

    for (int t = 0; t < Tl; t++) {
        float acc[2][4][4];
        #pragma unroll
        for (int i = 0; i < 2; i++)
            #pragma unroll
            for (int j = 0; j < 4; j++)
                #pragma unroll
                for (int r = 0; r < 4; r++) acc[i][j][r] = 0.0f;

        issue_h(0, 0);     // group: h0   (xg(t) is the older group)
        issue_h(1, 1);     // group: h1

        #pragma unroll
        for (int ck = 0; ck < NCH; ck++) {
            if (ck < 3) cp_wait<1>();
            else        cp_wait<0>();
            __syncthreads();

            const int stage = ck & 1;
            const uint16_t* hs = Hb + stage * H_STG;
            const uint16_t* ws = Ws + ck * W_CH;

            #pragma unroll
            for (int kk = 0; kk < LCH; kk += 16) {
                uint32_t afr[2][4];
                #pragma unroll
                for (int i = 0; i < 2; i++) {
                    int row = wm + i * 16 + (lane & 15);
                    int col = kk + (lane >> 4) * 8;
                    uint32_t addr = smem_u32(&hs[row * TSTR + col]);
                    asm volatile("ldmatrix.sync.aligned.m8n8.x4.shared.b16 {%0,%1,%2,%3},[%4];"
                                 : "=r"(afr[i][0]), "=r"(afr[i][1]), "=r"(afr[i][2]), "=r"(afr[i][3])
                                 : "r"(addr));
                }
                uint32_t bfr[4][2];
                #pragma unroll
                for (int j = 0; j < 2; j++) {
                    int grp = lane >> 3;
                    int row = wn + j * 16 + (grp >> 1) * 8 + (lane & 7);
                    int col = kk + (grp & 1) * 8;
                    uint32_t addr = smem_u32(&ws[row * TSTR + col]);
                    uint32_t r0, r1, r2, r3;
                    asm volatile("ldmatrix.sync.aligned.m8n8.x4.shared.b16 {%0,%1,%2,%3},[%4];"
                                 : "=r"(r0), "=r"(r1), "=r"(r2), "=r"(r3) : "r"(addr));
                    bfr[j * 2][0] = r0; bfr[j * 2][1] = r1;
                    bfr[j * 2 + 1][0] = r2; bfr[j * 2 + 1][1] = r3;
                }
                #pragma unroll
                for (int i = 0; i < 2; i++)
                    #pragma unroll
                    for (int j = 0; j < 4; j++) {
                        asm volatile(
                            "mma.sync.aligned.m16n8k16.row.col.f32.f16.f16.f32 "
                            "{%0,%1,%2,%3},{%4,%5,%6,%7},{%8,%9},{%0,%1,%2,%3};"
                            : "+f"(acc[i][j][0]), "+f"(acc[i][j][1]),
                              "+f"(acc[i][j][2]), "+f"(acc[i][j][3])
                            : "r"(afr[i][0]), "r"(afr[i][1]), "r"(afr[i][2]), "r"(afr[i][3]),
                              "r"(bfr[j][0]), "r"(bfr[j][1]));
                    }
            }
            __syncthreads();

            if (ck == 0) issue_h(0, 2);
            else if (ck == 1) issue_h(1, 3);
        }

        // write gate pre-activations (h@W^T part) to smem
        const int mrow = lane >> 2, nc2 = (lane & 3) * 2;
        #pragma unroll
        for (int i = 0; i < 2; i++) {
            int r0 = wm + i * 16 + mrow;
            #pragma unroll
            for (int j = 0; j < 4; j++) {
                int col = wn + j * 8 + nc2;
                Gs[r0 * 68 + col]       = acc[i][j][0];
                Gs[r0 * 68 + col + 1]   = acc[i][j][1];
                Gs[(r0 + 8) * 68 + col]     = acc[i][j][2];
                Gs[(r0 + 8) * 68 + col + 1] = acc[i][j][3];
            }
        }
        __syncthreads();

        // cell update: 8 cells per thread, all operands in smem
        #pragma unroll
        for (int it = 0; it < 8; it++) {
            int bl = (tid >> 4) + it * 16;
            float gi = fsig (Gs[bl * 68 +  0 + jj] + Xs[bl * 68 +  0 + jj] + bs[0]);
            float gf = fsig (Gs[bl * 68 + 16 + jj] + Xs[bl * 68 + 16 + jj] + bs[1]);
            float gg = ftanh(Gs[bl * 68 + 32 + jj] + Xs[bl * 68 + 32 + jj] + bs[2]);
            float go = fsig (Gs[bl * 68 + 48 + jj] + Xs[bl * 68 + 48 + jj] + bs[3]);
            float c = fmaf(gf, creg[it], gi * gg);
            creg[it] = c;
            __half h16 = __float2half_rn(go * ftanh(c));
            g_hfp16[bl * Hd + jt * 16 + jj] = h16;
            s_hid[((size_t)bl * Tl + t) * Hd + jt * 16 + jj] = h16;
        }

        // hoist next step's xg fetch across the barrier (lands during sync)
        __syncthreads();
        if (t + 1 < Tl) issue_xg(g_xg + (size_t)(t + 1) * Bb * H4);

        grid_sync_n(32);
    }
}

// ---------------- launch --------------------------------------------------------
extern "C" void kernel_launch(void* const* d_in, const int* in_sizes, int n_in,
                              void* d_out, int out_size)
{
    const float* features = (const float*)d_in[0];   // [B,F]
    const int*   seqs     = (const int*)  d_in[1];   // [B,T-1]
    const float* W_in  = (const float*)d_in[3];      // [E,F]
    const float* b_in  = (const float*)d_in[4];      // [E]
    const float* emb   = (const float*)d_in[5];      // [V,E]
    const float* W_ih  = (const float*)d_in[6];      // [4H,E]
    const float* W_hh  = (const float*)d_in[7];      // [4H,H]
    const float* b_ih  = (const float*)d_in[8];      // [4H]
    const float* b_hh  = (const float*)d_in[9];      // [4H]
    const float* W_out = (const float*)d_in[10];     // [V,H]
    const float* b_out = (const float*)d_in[11];     // [V]
    float* out = (float*)d_out;                      // [B,T,V]

    float* p_xg;
    cudaGetSymbolAddress((void**)&p_xg, g_xg);
    __half *p_sseq, *p_Wih, *p_hid, *p_Wout;
    cudaGetSymbolAddress((void**)&p_sseq, s_seq);
    cudaGetSymbolAddress((void**)&p_Wih,  s_Wih);
    cudaGetSymbolAddress((void**)&p_hid,  s_hid);
    cudaGetSymbolAddress((void**)&p_Wout, s_Wout);

    cudaFuncSetAttribute(gemm_mma, cudaFuncAttributeMaxDynamicSharedMemorySize, SMEM_MM);
    cudaFuncSetAttribute(lstm_tc,  cudaFuncAttributeMaxDynamicSharedMemorySize, SMEM_LSTM);

    const int TPB = 256;
    auto nb = [](size_t n, int t) { return (int)((n + t - 1) / t); };

    // 1) x0 = features @ W_in^T + b_in (fp32 accum) -> s_seq rows [0,128) fp16
    {
        dim3 grid(Ed / 32, Bb / 32);   // 64 CTAs
        gemm_tn_h<32, 32, 8, 2, 2><<<grid, 256>>>(
            features, W_in, b_in, p_sseq, Bb, Ed, Fdim);
    }

    // 2) gather embeddings (fp16) for t = 1..T-1
    gather_emb<<<(Tl - 1) * Bb, 128>>>(seqs, emb);

    // 3) W_ih -> fp16, xg GEMM  [5120, 2048] K=512 (single fp16)
    tofp16<<<nb((size_t)H4 * Ed, TPB), TPB>>>(W_ih, p_Wih, (size_t)H4 * Ed);
    {
        dim3 grid(H4 / 128, BT / 128);   // (16,40)
        gemm_mma<<<grid, 256, SMEM_MM>>>(p_sseq, p_Wih, b_ih, p_xg, BT, H4, Ed);
    }

    // 4) persistent tensor-core recurrence (writes h fp16 into s_hid)
    lstm_tc<<<32, 256, SMEM_LSTM>>>(W_hh, b_hh);

    // 5) W_out -> fp16, output GEMM [5120, 10000] K=512 (single fp16)
    tofp16<<<nb((size_t)Vd * Hd, TPB), TPB>>>(W_out, p_Wout, (size_t)Vd * Hd);
    {
        dim3 grid((Vd + 127) / 128, BT / 128);   // (79,40)
        gemm_mma<<<grid, 256, SMEM_MM>>>(p_hid, p_Wout, b_out, out, BT, Vd, Ed);
    }
}

// round 13
// speedup vs baseline: 3.0836x; 1.1208x over previous
#include <cuda_runtime.h>
#include <cuda_bf16.h>
#include <cuda_fp16.h>
#include <cstdint>

// Problem constants
#define Bb   128
#define Fdim 1536
#define Ed   512
#define Hd   512
#define H4   2048
#define Vd   10000
#define Tl   40
#define BT   (Bb*Tl)     // 5120

// ---------------- scratch (static device memory) -----------------------------
__device__ float g_xg[(size_t)BT * H4];            // [T*B, 4H]
__device__ __align__(16) __half g_hfp16[Bb * Hd];  // recurrent h (fp16)

// fp16 operand buffers
__device__ __align__(16) __half s_seq [(size_t)BT * Ed];    // A of xg (fp16 seq)
__device__ __align__(16) __half s_Wih [(size_t)H4 * Ed];    // B of xg
__device__ __align__(16) __half s_hid [(size_t)BT * Ed];    // A of out GEMM
__device__ __align__(16) __half s_Wout[(size_t)Vd * Ed];    // B of out GEMM

// grid barrier state
__device__ unsigned int g_bar_cnt = 0;
__device__ volatile unsigned int g_bar_gen = 0;

// fast MUFU-only activations (EX2 + RCP; ~2ulp)
__device__ __forceinline__ float fsig(float x) {
    return __fdividef(1.0f, 1.0f + __expf(-x));
}
__device__ __forceinline__ float ftanh(float x) {
    return fmaf(-2.0f, __fdividef(1.0f, 1.0f + __expf(2.0f * x)), 1.0f);
}

__device__ __forceinline__ uint32_t smem_u32(const void* p) {
    return (uint32_t)__cvta_generic_to_shared(p);
}

template<int N>
__device__ __forceinline__ void cp_wait() {
    asm volatile("cp.async.wait_group %0;\n" :: "n"(N));
}

// ---------------- fp32 SIMT GEMM for x0, fp16 output: C = A @ B^T + bias ------
template<int BM, int BN, int BK, int TM, int TN>
__global__ void gemm_tn_h(const float* __restrict__ A,
                          const float* __restrict__ Bw,
                          const float* __restrict__ bias,
                          __half* __restrict__ C,
                          int M, int N, int K)
{
    constexpr int NT = (BM / TM) * (BN / TN);
    static_assert(NT == 256, "need 256 threads");
    __shared__ float As[BK][BM];
    __shared__ float Bs[BK][BN];

    const int m0 = blockIdx.y * BM;
    const int n0 = blockIdx.x * BN;
    const int tid = threadIdx.x;
    constexpr int NTX = BN / TN;
    const int tc = tid % NTX;
    const int tr = tid / NTX;

    float acc[TM][TN];
    #pragma unroll
    for (int i = 0; i < TM; i++)
        #pragma unroll
        for (int j = 0; j < TN; j++) acc[i][j] = 0.0f;

    constexpr int A_LD4 = BM * BK / 4;
    constexpr int B_LD4 = BN * BK / 4;
    constexpr int K4 = BK / 4;

    for (int k0 = 0; k0 < K; k0 += BK) {
        #pragma unroll
        for (int i = tid; i < A_LD4; i += NT) {
            int row = i / K4;
            int kc  = (i % K4) * 4;
            float4 v = *reinterpret_cast<const float4*>(
                A + (size_t)(m0 + row) * K + k0 + kc);
            As[kc + 0][row] = v.x; As[kc + 1][row] = v.y;
            As[kc + 2][row] = v.z; As[kc + 3][row] = v.w;
        }
        #pragma unroll
        for (int i = tid; i < B_LD4; i += NT) {
            int row = i / K4;
            int kc  = (i % K4) * 4;
            float4 v = *reinterpret_cast<const float4*>(
                Bw + (size_t)(n0 + row) * K + k0 + kc);
            Bs[kc + 0][row] = v.x; Bs[kc + 1][row] = v.y;
            Bs[kc + 2][row] = v.z; Bs[kc + 3][row] = v.w;
        }
        __syncthreads();

        #pragma unroll
        for (int k = 0; k < BK; k++) {
            float ra[TM], rb[TN];
            #pragma unroll
            for (int i = 0; i < TM; i++) ra[i] = As[k][tr * TM + i];
            #pragma unroll
            for (int j = 0; j < TN; j++) rb[j] = Bs[k][tc * TN + j];
            #pragma unroll
            for (int i = 0; i < TM; i++)
                #pragma unroll
                for (int j = 0; j < TN; j++)
                    acc[i][j] = fmaf(ra[i], rb[j], acc[i][j]);
        }
        __syncthreads();
    }

    #pragma unroll
    for (int i = 0; i < TM; i++) {
        int m = m0 + tr * TM + i;
        #pragma unroll
        for (int j = 0; j < TN; j++) {
            int n = n0 + tc * TN + j;
            C[(size_t)m * N + n] = __float2half_rn(acc[i][j] + bias[n]);
        }
    }
}

// ---------------- fp16 HMMA GEMM: C = A @ B^T + bias ---------------------------
// Tile 128x128, 512 threads (16 warps, warp tile 32x32, 32 accum regs/thread,
// <=64 regs -> 2 CTAs/SM = 32 warps/SM). K-chunk 64, 3-stage cp.async ring
// (distance 2), one __syncthreads per chunk.
#define KC      64
#define STRIDEg 72                         // row stride (halves): conflict-free
#define SA_ST   (128 * STRIDEg)
#define NST     3
#define SMEM_MM (NST * 2 * SA_ST * 2)      // 110592 bytes

__global__ void __launch_bounds__(512, 2)
gemm_mma(const __half* __restrict__ A,
         const __half* __restrict__ B,
         const float* __restrict__ bias,
         float* __restrict__ C,
         int M, int N, int K)
{
    extern __shared__ __align__(16) uint16_t smbuf[];
    uint16_t* Asm = smbuf;
    uint16_t* Bsm = smbuf + NST * SA_ST;

    const int tid  = threadIdx.x;
    const int warp = tid >> 5, lane = tid & 31;
    const int wm = (warp >> 2) * 32;   // 4 M-groups
    const int wn = (warp & 3) * 32;    // 4 N-groups
    const int m0 = blockIdx.y * 128, n0 = blockIdx.x * 128;
    const int KT = K / KC;

    float acc[2][4][4];
    #pragma unroll
    for (int i = 0; i < 2; i++)
        #pragma unroll
        for (int j = 0; j < 4; j++)
            #pragma unroll
            for (int r = 0; r < 4; r++) acc[i][j][r] = 0.0f;

    // one 64-K stage: 128 rows x 64 halves per matrix = 1024 x 16B tasks each
    auto load_tile = [&](int buf, int kt) {
        const int k0 = kt * KC;
        #pragma unroll
        for (int it = 0; it < 2; it++) {
            int task = tid + it * 512;
            int r = task >> 3, c = task & 7;
            uint32_t dst = smem_u32(&Asm[buf * SA_ST + r * STRIDEg + c * 8]);
            const void* src = A + (size_t)(m0 + r) * K + k0 + c * 8;
            asm volatile("cp.async.cg.shared.global [%0],[%1],16;\n" :: "r"(dst), "l"(src));
        }
        #pragma unroll
        for (int it = 0; it < 2; it++) {
            int task = tid + it * 512;
            int r = task >> 3, c = task & 7;
            if (n0 + r < N) {
                uint32_t dst = smem_u32(&Bsm[buf * SA_ST + r * STRIDEg + c * 8]);
                const void* src = B + (size_t)(n0 + r) * K + k0 + c * 8;
                asm volatile("cp.async.cg.shared.global [%0],[%1],16;\n" :: "r"(dst), "l"(src));
            }
        }
        asm volatile("cp.async.commit_group;\n");
    };

    // prefetch 2 stages
    load_tile(0, 0);
    if (KT > 1) load_tile(1, 1); else asm volatile("cp.async.commit_group;\n");

    int buf = 0, pbuf = 2;
    for (int ck = 0; ck < KT; ck++) {
        cp_wait<1>();
        __syncthreads();
        if (ck + 2 < KT) load_tile(pbuf, ck + 2);
        else             asm volatile("cp.async.commit_group;\n");

        const uint16_t* as = Asm + buf * SA_ST;
        const uint16_t* bs = Bsm + buf * SA_ST;

        #pragma unroll
        for (int kk = 0; kk < KC; kk += 16) {
            uint32_t afr[2][4];
            #pragma unroll
            for (int i = 0; i < 2; i++) {
                int row = wm + i * 16 + (lane & 15);
                int col = kk + (lane >> 4) * 8;
                uint32_t addr = smem_u32(&as[row * STRIDEg + col]);
                asm volatile("ldmatrix.sync.aligned.m8n8.x4.shared.b16 {%0,%1,%2,%3},[%4];"
                             : "=r"(afr[i][0]), "=r"(afr[i][1]), "=r"(afr[i][2]), "=r"(afr[i][3])
                             : "r"(addr));
            }
            uint32_t bfr[4][2];
            #pragma unroll
            for (int j = 0; j < 2; j++) {
                int grp = lane >> 3;
                int row = wn + j * 16 + (grp >> 1) * 8 + (lane & 7);
                int col = kk + (grp & 1) * 8;
                uint32_t addr = smem_u32(&bs[row * STRIDEg + col]);
                uint32_t r0, r1, r2, r3;
                asm volatile("ldmatrix.sync.aligned.m8n8.x4.shared.b16 {%0,%1,%2,%3},[%4];"
                             : "=r"(r0), "=r"(r1), "=r"(r2), "=r"(r3) : "r"(addr));
                bfr[j * 2][0] = r0; bfr[j * 2][1] = r1;
                bfr[j * 2 + 1][0] = r2; bfr[j * 2 + 1][1] = r3;
            }
            #pragma unroll
            for (int i = 0; i < 2; i++)
                #pragma unroll
                for (int j = 0; j < 4; j++) {
                    asm volatile(
                        "mma.sync.aligned.m16n8k16.row.col.f32.f16.f16.f32 "
                        "{%0,%1,%2,%3},{%4,%5,%6,%7},{%8,%9},{%0,%1,%2,%3};"
                        : "+f"(acc[i][j][0]), "+f"(acc[i][j][1]),
                          "+f"(acc[i][j][2]), "+f"(acc[i][j][3])
                        : "r"(afr[i][0]), "r"(afr[i][1]), "r"(afr[i][2]), "r"(afr[i][3]),
                          "r"(bfr[j][0]), "r"(bfr[j][1]));
                }
        }
        buf  = (buf  + 1 == NST) ? 0 : buf + 1;
        pbuf = (pbuf + 1 == NST) ? 0 : pbuf + 1;
    }

    const int mrow = lane >> 2, nc2 = (lane & 3) * 2;
    #pragma unroll
    for (int i = 0; i < 2; i++) {
        int gm = m0 + wm + i * 16 + mrow;
        float* Crow0 = C + (size_t)gm * N;
        float* Crow1 = C + (size_t)(gm + 8) * N;
        #pragma unroll
        for (int j = 0; j < 4; j++) {
            int gn = n0 + wn + j * 8 + nc2;
            if (gn < N) {
                float bv = bias[gn];
                Crow0[gn] = acc[i][j][0] + bv;
                Crow1[gn] = acc[i][j][2] + bv;
            }
            if (gn + 1 < N) {
                float bv = bias[gn + 1];
                Crow0[gn + 1] = acc[i][j][1] + bv;
                Crow1[gn + 1] = acc[i][j][3] + bv;
            }
        }
    }
}

// ---------------- convert kernel -------------------------------------------------
__global__ void tofp16(const float* __restrict__ X, __half* __restrict__ Y, size_t total)
{
    size_t i = (size_t)blockIdx.x * blockDim.x + threadIdx.x;
    if (i < total) Y[i] = __float2half_rn(X[i]);
}

// ---------------- gather word embeddings (fp32 -> fp16) into s_seq rows t>=1 ---
__global__ void gather_emb(const int* __restrict__ seqs,
                           const float* __restrict__ emb)
{
    int bid = blockIdx.x;
    int t1  = bid / Bb;
    int b   = bid % Bb;
    int word = seqs[b * (Tl - 1) + t1];
    const float4* src = reinterpret_cast<const float4*>(emb + (size_t)word * Ed);
    __half* dst = s_seq + (size_t)((t1 + 1) * Bb + b) * Ed;
    for (int i = threadIdx.x; i < Ed / 4; i += blockDim.x) {
        float4 v = src[i];
        __half2 h01 = __floats2half2_rn(v.x, v.y);
        __half2 h23 = __floats2half2_rn(v.z, v.w);
        *reinterpret_cast<__half2*>(dst + i * 4)     = h01;
        *reinterpret_cast<__half2*>(dst + i * 4 + 2) = h23;
    }
}

// ---------------- persistent tensor-core LSTM recurrence ------------------------
// 64 CTAs: (jt 0..31, batch-half 0..1). Each CTA: 64 batch rows x 64 gate cols.
// W_hh tile fp16 in smem (duplicated per batch-half pair); h via 2-stage
// cp.async pipeline; xg slice prefetched per step; c in registers.
#define LCH   128
#define NCH   (Hd / LCH)               // 4
#define TSTR  136
#define W_CH  (64 * TSTR)
#define H_STG (64 * TSTR)              // 64 batch rows per CTA now
#define SMEM_LSTM ((NCH * W_CH + 2 * H_STG) * 2 + 2 * 64 * 68 * 4)  // 139264 B

__device__ __forceinline__ void grid_sync_n(unsigned int nctas)
{
    __threadfence();
    __syncthreads();
    if (threadIdx.x == 0) {
        unsigned gen = g_bar_gen;
        if (atomicAdd(&g_bar_cnt, 1u) == nctas - 1u) {
            g_bar_cnt = 0;
            __threadfence();
            g_bar_gen = gen + 1;
        } else {
            while (g_bar_gen == gen) __nanosleep(16);
            __threadfence();
        }
    }
    __syncthreads();
}

__global__ void __launch_bounds__(256, 1)
lstm_tc(const float* __restrict__ Whh,   // [4H, H]
        const float* __restrict__ bhh)   // [4H]
{
    extern __shared__ __align__(16) uint16_t lsm[];
    uint16_t* Ws = lsm;                          // NCH x 64 x TSTR
    uint16_t* Hb = lsm + NCH * W_CH;             // 2 x 64 x TSTR
    float*    Gs = (float*)(Hb + 2 * H_STG);     // 64 x 68
    float*    Xs = Gs + 64 * 68;                 // 64 x 68

    const int tid  = threadIdx.x;
    const int warp = tid >> 5, lane = tid & 31;
    const int wm = (warp >> 1) * 16;   // 4 M-groups of 16 batch rows
    const int wn = (warp & 1) * 32;    // 2 N-groups of 32 gate cols
    const int jt = blockIdx.x >> 1;    // hidden slice 0..31
    const int b0 = (blockIdx.x & 1) * 64;   // batch-half origin

    // ---- load W_hh tile to smem as fp16 (once) ----
    #pragma unroll
    for (int it = 0; it < 32; it++) {
        int task = tid + it * 256;
        int row = task >> 7;
        int c4  = task & 127;
        int grow = (row >> 4) * Hd + jt * 16 + (row & 15);
        float4 v = *reinterpret_cast<const float4*>(Whh + (size_t)grow * Hd + c4 * 4);
        int ck = c4 >> 5;
        int kc = (c4 & 31) * 4;
        __half2 h01 = __floats2half2_rn(v.x, v.y);
        __half2 h23 = __floats2half2_rn(v.z, v.w);
        uint16_t* dst = Ws + ck * W_CH + row * TSTR + kc;
        *reinterpret_cast<__half2*>(dst)     = h01;
        *reinterpret_cast<__half2*>(dst + 2) = h23;
    }

    const int jj = tid & 15;
    float creg[4];
    #pragma unroll
    for (int i = 0; i < 4; i++) creg[i] = 0.0f;
    float bs[4];
    #pragma unroll
    for (int g = 0; g < 4; g++) bs[g] = bhh[g * Hd + jt * 16 + jj];

    // zero this CTA's h slice (64 rows x 16 cols)
    #pragma unroll
    for (int it = 0; it < 4; it++) {
        int bl = (tid >> 4) + it * 16;
        g_hfp16[(b0 + bl) * Hd + jt * 16 + jj] = __float2half_rn(0.0f);
    }
    grid_sync_n(64);

    // xg slice prefetch: 64 bl x 16 tasks = 1024 x 16B tasks
    auto issue_xg = [&](const float* xg_t) {
        #pragma unroll
        for (int it = 0; it < 4; it++) {
            int task = tid + it * 256;
            int bl  = task >> 4;
            int rem = task & 15;
            int g = rem >> 2, q = rem & 3;
            uint32_t dst = smem_u32(&Xs[bl * 68 + g * 16 + q * 4]);
            const void* src = xg_t + (size_t)(b0 + bl) * H4 + g * Hd + jt * 16 + q * 4;
            asm volatile("cp.async.cg.shared.global [%0],[%1],16;\n" :: "r"(dst), "l"(src));
        }
        asm volatile("cp.async.commit_group;\n");
    };

    // h chunk: 64 rows x 128 halves = 1024 x 16B tasks
    auto issue_h = [&](int stage, int ck) {
        #pragma unroll
        for (int it = 0; it < 4; it++) {
            int task = tid + it * 256;
            int r  = task >> 4;
            int c8 = task & 15;
            uint32_t dst = smem_u32(&Hb[stage * H_STG + r * TSTR + c8 * 8]);
            const void* src = g_hfp16 + (b0 + r) * Hd + ck * LCH + c8 * 8;
            asm volatile("cp.async.cg.shared.global [%0],[%1],16;\n" :: "r"(dst), "l"(src));
        }
        asm volatile("cp.async.commit_group;\n");
    };

    // xg for t=0 issued ahead of the step loop
    issue_xg(g_xg);

    for (int t = 0; t < Tl; t++) {
        float acc[4][4];
        #pragma unroll
        for (int j = 0; j < 4; j++)
            #pragma unroll
            for (int r = 0; r < 4; r++) acc[j][r] = 0.0f;

        issue_h(0, 0);     // group: h0   (xg(t) is the older group)
        issue_h(1, 1);     // group: h1

        #pragma unroll
        for (int ck = 0; ck < NCH; ck++) {
            if (ck < 3) cp_wait<1>();
            else        cp_wait<0>();
            __syncthreads();

            const int stage = ck & 1;
            const uint16_t* hs = Hb + stage * H_STG;
            const uint16_t* ws = Ws + ck * W_CH;

            #pragma unroll
            for (int kk = 0; kk < LCH; kk += 16) {
                uint32_t afr[4];
                {
                    int row = wm + (lane & 15);
                    int col = kk + (lane >> 4) * 8;
                    uint32_t addr = smem_u32(&hs[row * TSTR + col]);
                    asm volatile("ldmatrix.sync.aligned.m8n8.x4.shared.b16 {%0,%1,%2,%3},[%4];"
                                 : "=r"(afr[0]), "=r"(afr[1]), "=r"(afr[2]), "=r"(afr[3])
                                 : "r"(addr));
                }
                uint32_t bfr[4][2];
                #pragma unroll
                for (int j = 0; j < 2; j++) {
                    int grp = lane >> 3;
                    int row = wn + j * 16 + (grp >> 1) * 8 + (lane & 7);
                    int col = kk + (grp & 1) * 8;
                    uint32_t addr = smem_u32(&ws[row * TSTR + col]);
                    uint32_t r0, r1, r2, r3;
                    asm volatile("ldmatrix.sync.aligned.m8n8.x4.shared.b16 {%0,%1,%2,%3},[%4];"
                                 : "=r"(r0), "=r"(r1), "=r"(r2), "=r"(r3) : "r"(addr));
                    bfr[j * 2][0] = r0; bfr[j * 2][1] = r1;
                    bfr[j * 2 + 1][0] = r2; bfr[j * 2 + 1][1] = r3;
                }
                #pragma unroll
                for (int j = 0; j < 4; j++) {
                    asm volatile(
                        "mma.sync.aligned.m16n8k16.row.col.f32.f16.f16.f32 "
                        "{%0,%1,%2,%3},{%4,%5,%6,%7},{%8,%9},{%0,%1,%2,%3};"
                        : "+f"(acc[j][0]), "+f"(acc[j][1]),
                          "+f"(acc[j][2]), "+f"(acc[j][3])
                        : "r"(afr[0]), "r"(afr[1]), "r"(afr[2]), "r"(afr[3]),
                          "r"(bfr[j][0]), "r"(bfr[j][1]));
                }
            }
            __syncthreads();

            if (ck == 0) issue_h(0, 2);
            else if (ck == 1) issue_h(1, 3);
        }

        // write gate pre-activations (h@W^T part) to smem
        const int mrow = lane >> 2, nc2 = (lane & 3) * 2;
        {
            int r0 = wm + mrow;
            #pragma unroll
            for (int j = 0; j < 4; j++) {
                int col = wn + j * 8 + nc2;
                Gs[r0 * 68 + col]           = acc[j][0];
                Gs[r0 * 68 + col + 1]       = acc[j][1];
                Gs[(r0 + 8) * 68 + col]     = acc[j][2];
                Gs[(r0 + 8) * 68 + col + 1] = acc[j][3];
            }
        }
        __syncthreads();

        // cell update: 4 cells per thread, all operands in smem
        #pragma unroll
        for (int it = 0; it < 4; it++) {
            int bl = (tid >> 4) + it * 16;
            float gi = fsig (Gs[bl * 68 +  0 + jj] + Xs[bl * 68 +  0 + jj] + bs[0]);
            float gf = fsig (Gs[bl * 68 + 16 + jj] + Xs[bl * 68 + 16 + jj] + bs[1]);
            float gg = ftanh(Gs[bl * 68 + 32 + jj] + Xs[bl * 68 + 32 + jj] + bs[2]);
            float go = fsig (Gs[bl * 68 + 48 + jj] + Xs[bl * 68 + 48 + jj] + bs[3]);
            float c = fmaf(gf, creg[it], gi * gg);
            creg[it] = c;
            __half h16 = __float2half_rn(go * ftanh(c));
            g_hfp16[(b0 + bl) * Hd + jt * 16 + jj] = h16;
            s_hid[((size_t)(b0 + bl) * Tl + t) * Hd + jt * 16 + jj] = h16;
        }

        // hoist next step's xg fetch across the barrier
        __syncthreads();
        if (t + 1 < Tl) issue_xg(g_xg + (size_t)(t + 1) * Bb * H4);

        grid_sync_n(64);
    }
}

// ---------------- launch --------------------------------------------------------
extern "C" void kernel_launch(void* const* d_in, const int* in_sizes, int n_in,
                              void* d_out, int out_size)
{
    const float* features = (const float*)d_in[0];   // [B,F]
    const int*   seqs     = (const int*)  d_in[1];   // [B,T-1]
    const float* W_in  = (const float*)d_in[3];      // [E,F]
    const float* b_in  = (const float*)d_in[4];      // [E]
    const float* emb   = (const float*)d_in[5];      // [V,E]
    const float* W_ih  = (const float*)d_in[6];      // [4H,E]
    const float* W_hh  = (const float*)d_in[7];      // [4H,H]
    const float* b_ih  = (const float*)d_in[8];      // [4H]
    const float* b_hh  = (const float*)d_in[9];      // [4H]
    const float* W_out = (const float*)d_in[10];     // [V,H]
    const float* b_out = (const float*)d_in[11];     // [V]
    float* out = (float*)d_out;                      // [B,T,V]

    float* p_xg;
    cudaGetSymbolAddress((void**)&p_xg, g_xg);
    __half *p_sseq, *p_Wih, *p_hid, *p_Wout;
    cudaGetSymbolAddress((void**)&p_sseq, s_seq);
    cudaGetSymbolAddress((void**)&p_Wih,  s_Wih);
    cudaGetSymbolAddress((void**)&p_hid,  s_hid);
    cudaGetSymbolAddress((void**)&p_Wout, s_Wout);

    cudaFuncSetAttribute(gemm_mma, cudaFuncAttributeMaxDynamicSharedMemorySize, SMEM_MM);
    cudaFuncSetAttribute(lstm_tc,  cudaFuncAttributeMaxDynamicSharedMemorySize, SMEM_LSTM);

    const int TPB = 256;
    auto nb = [](size_t n, int t) { return (int)((n + t - 1) / t); };

    // 1) x0 = features @ W_in^T + b_in (fp32 accum) -> s_seq rows [0,128) fp16
    {
        dim3 grid(Ed / 32, Bb / 32);   // 64 CTAs
        gemm_tn_h<32, 32, 8, 2, 2><<<grid, 256>>>(
            features, W_in, b_in, p_sseq, Bb, Ed, Fdim);
    }

    // 2) gather embeddings (fp16) for t = 1..T-1
    gather_emb<<<(Tl - 1) * Bb, 128>>>(seqs, emb);

    // 3) W_ih -> fp16, xg GEMM  [5120, 2048] K=512 (single fp16)
    tofp16<<<nb((size_t)H4 * Ed, TPB), TPB>>>(W_ih, p_Wih, (size_t)H4 * Ed);
    {
        dim3 grid(H4 / 128, BT / 128);   // (16,40)
        gemm_mma<<<grid, 512, SMEM_MM>>>(p_sseq, p_Wih, b_ih, p_xg, BT, H4, Ed);
    }

    // 4) persistent tensor-core recurrence (64 CTAs; writes h fp16 into s_hid)
    lstm_tc<<<64, 256, SMEM_LSTM>>>(W_hh, b_hh);

    // 5) W_out -> fp16, output GEMM [5120, 10000] K=512 (single fp16)
    tofp16<<<nb((size_t)Vd * Hd, TPB), TPB>>>(W_out, p_Wout, (size_t)Vd * Hd);
    {
        dim3 grid((Vd + 127) / 128, BT / 128);   // (79,40)
        gemm_mma<<<grid, 512, SMEM_MM>>>(p_hid, p_Wout, b_out, out, BT, Vd, Ed);
    }
}

// round 14
// speedup vs baseline: 3.2934x; 1.0680x over previous
#include <cuda_runtime.h>
#include <cuda_bf16.h>
#include <cuda_fp16.h>
#include <cstdint>

// Problem constants
#define Bb   128
#define Fdim 1536
#define Ed   512
#define Hd   512
#define H4   2048
#define Vd   10000
#define Tl   40
#define BT   (Bb*Tl)     // 5120

// ---------------- scratch (static device memory) -----------------------------
__device__ float g_xg[(size_t)BT * H4];            // [T*B, 4H]
__device__ __align__(16) __half g_hfp16[Bb * Hd];  // recurrent h (fp16)

// fp16 operand buffers
__device__ __align__(16) __half s_seq [(size_t)BT * Ed];    // A of xg (fp16 seq)
__device__ __align__(16) __half s_Wih [(size_t)H4 * Ed];    // B of xg
__device__ __align__(16) __half s_hid [(size_t)BT * Ed];    // A of out GEMM
__device__ __align__(16) __half s_Wout[(size_t)Vd * Ed];    // B of out GEMM

// grid barrier state
__device__ unsigned int g_bar_cnt = 0;
__device__ volatile unsigned int g_bar_gen = 0;

// fast MUFU-only activations (EX2 + RCP; ~2ulp)
__device__ __forceinline__ float fsig(float x) {
    return __fdividef(1.0f, 1.0f + __expf(-x));
}
__device__ __forceinline__ float ftanh(float x) {
    return fmaf(-2.0f, __fdividef(1.0f, 1.0f + __expf(2.0f * x)), 1.0f);
}

__device__ __forceinline__ uint32_t smem_u32(const void* p) {
    return (uint32_t)__cvta_generic_to_shared(p);
}

template<int N>
__device__ __forceinline__ void cp_wait() {
    asm volatile("cp.async.wait_group %0;\n" :: "n"(N));
}

// ---------------- fp32 SIMT GEMM for x0, fp16 output: C = A @ B^T + bias ------
template<int BM, int BN, int BK, int TM, int TN>
__global__ void gemm_tn_h(const float* __restrict__ A,
                          const float* __restrict__ Bw,
                          const float* __restrict__ bias,
                          __half* __restrict__ C,
                          int M, int N, int K)
{
    constexpr int NT = (BM / TM) * (BN / TN);
    static_assert(NT == 256, "need 256 threads");
    __shared__ float As[BK][BM];
    __shared__ float Bs[BK][BN];

    const int m0 = blockIdx.y * BM;
    const int n0 = blockIdx.x * BN;
    const int tid = threadIdx.x;
    constexpr int NTX = BN / TN;
    const int tc = tid % NTX;
    const int tr = tid / NTX;

    float acc[TM][TN];
    #pragma unroll
    for (int i = 0; i < TM; i++)
        #pragma unroll
        for (int j = 0; j < TN; j++) acc[i][j] = 0.0f;

    constexpr int A_LD4 = BM * BK / 4;
    constexpr int B_LD4 = BN * BK / 4;
    constexpr int K4 = BK / 4;

    for (int k0 = 0; k0 < K; k0 += BK) {
        #pragma unroll
        for (int i = tid; i < A_LD4; i += NT) {
            int row = i / K4;
            int kc  = (i % K4) * 4;
            float4 v = *reinterpret_cast<const float4*>(
                A + (size_t)(m0 + row) * K + k0 + kc);
            As[kc + 0][row] = v.x; As[kc + 1][row] = v.y;
            As[kc + 2][row] = v.z; As[kc + 3][row] = v.w;
        }
        #pragma unroll
        for (int i = tid; i < B_LD4; i += NT) {
            int row = i / K4;
            int kc  = (i % K4) * 4;
            float4 v = *reinterpret_cast<const float4*>(
                Bw + (size_t)(n0 + row) * K + k0 + kc);
            Bs[kc + 0][row] = v.x; Bs[kc + 1][row] = v.y;
            Bs[kc + 2][row] = v.z; Bs[kc + 3][row] = v.w;
        }
        __syncthreads();

        #pragma unroll
        for (int k = 0; k < BK; k++) {
            float ra[TM], rb[TN];
            #pragma unroll
            for (int i = 0; i < TM; i++) ra[i] = As[k][tr * TM + i];
            #pragma unroll
            for (int j = 0; j < TN; j++) rb[j] = Bs[k][tc * TN + j];
            #pragma unroll
            for (int i = 0; i < TM; i++)
                #pragma unroll
                for (int j = 0; j < TN; j++)
                    acc[i][j] = fmaf(ra[i], rb[j], acc[i][j]);
        }
        __syncthreads();
    }

    #pragma unroll
    for (int i = 0; i < TM; i++) {
        int m = m0 + tr * TM + i;
        #pragma unroll
        for (int j = 0; j < TN; j++) {
            int n = n0 + tc * TN + j;
            C[(size_t)m * N + n] = __float2half_rn(acc[i][j] + bias[n]);
        }
    }
}

// ---------------- fp16 HMMA GEMM: C = A @ B^T + bias ---------------------------
// Tile 128x128, 512 threads (16 warps, warp tile 32x32), K-chunk 64, 3-stage
// cp.async ring (distance 2), one __syncthreads per chunk, 2 CTAs/SM.
#define KC      64
#define STRIDEg 72
#define SA_ST   (128 * STRIDEg)
#define NST     3
#define SMEM_MM (NST * 2 * SA_ST * 2)      // 110592 bytes

__global__ void __launch_bounds__(512, 2)
gemm_mma(const __half* __restrict__ A,
         const __half* __restrict__ B,
         const float* __restrict__ bias,
         float* __restrict__ C,
         int M, int N, int K)
{
    extern __shared__ __align__(16) uint16_t smbuf[];
    uint16_t* Asm = smbuf;
    uint16_t* Bsm = smbuf + NST * SA_ST;

    const int tid  = threadIdx.x;
    const int warp = tid >> 5, lane = tid & 31;
    const int wm = (warp >> 2) * 32;
    const int wn = (warp & 3) * 32;
    const int m0 = blockIdx.y * 128, n0 = blockIdx.x * 128;
    const int KT = K / KC;

    float acc[2][4][4];
    #pragma unroll
    for (int i = 0; i < 2; i++)
        #pragma unroll
        for (int j = 0; j < 4; j++)
            #pragma unroll
            for (int r = 0; r < 4; r++) acc[i][j][r] = 0.0f;

    auto load_tile = [&](int buf, int kt) {
        const int k0 = kt * KC;
        #pragma unroll
        for (int it = 0; it < 2; it++) {
            int task = tid + it * 512;
            int r = task >> 3, c = task & 7;
            uint32_t dst = smem_u32(&Asm[buf * SA_ST + r * STRIDEg + c * 8]);
            const void* src = A + (size_t)(m0 + r) * K + k0 + c * 8;
            asm volatile("cp.async.cg.shared.global [%0],[%1],16;\n" :: "r"(dst), "l"(src));
        }
        #pragma unroll
        for (int it = 0; it < 2; it++) {
            int task = tid + it * 512;
            int r = task >> 3, c = task & 7;
            if (n0 + r < N) {
                uint32_t dst = smem_u32(&Bsm[buf * SA_ST + r * STRIDEg + c * 8]);
                const void* src = B + (size_t)(n0 + r) * K + k0 + c * 8;
                asm volatile("cp.async.cg.shared.global [%0],[%1],16;\n" :: "r"(dst), "l"(src));
            }
        }
        asm volatile("cp.async.commit_group;\n");
    };

    load_tile(0, 0);
    if (KT > 1) load_tile(1, 1); else asm volatile("cp.async.commit_group;\n");

    int buf = 0, pbuf = 2;
    for (int ck = 0; ck < KT; ck++) {
        cp_wait<1>();
        __syncthreads();
        if (ck + 2 < KT) load_tile(pbuf, ck + 2);
        else             asm volatile("cp.async.commit_group;\n");

        const uint16_t* as = Asm + buf * SA_ST;
        const uint16_t* bs = Bsm + buf * SA_ST;

        #pragma unroll
        for (int kk = 0; kk < KC; kk += 16) {
            uint32_t afr[2][4];
            #pragma unroll
            for (int i = 0; i < 2; i++) {
                int row = wm + i * 16 + (lane & 15);
                int col = kk + (lane >> 4) * 8;
                uint32_t addr = smem_u32(&as[row * STRIDEg + col]);
                asm volatile("ldmatrix.sync.aligned.m8n8.x4.shared.b16 {%0,%1,%2,%3},[%4];"
                             : "=r"(afr[i][0]), "=r"(afr[i][1]), "=r"(afr[i][2]), "=r"(afr[i][3])
                             : "r"(addr));
            }
            uint32_t bfr[4][2];
            #pragma unroll
            for (int j = 0; j < 2; j++) {
                int grp = lane >> 3;
                int row = wn + j * 16 + (grp >> 1) * 8 + (lane & 7);
                int col = kk + (grp & 1) * 8;
                uint32_t addr = smem_u32(&bs[row * STRIDEg + col]);
                uint32_t r0, r1, r2, r3;
                asm volatile("ldmatrix.sync.aligned.m8n8.x4.shared.b16 {%0,%1,%2,%3},[%4];"
                             : "=r"(r0), "=r"(r1), "=r"(r2), "=r"(r3) : "r"(addr));
                bfr[j * 2][0] = r0; bfr[j * 2][1] = r1;
                bfr[j * 2 + 1][0] = r2; bfr[j * 2 + 1][1] = r3;
            }
            #pragma unroll
            for (int i = 0; i < 2; i++)
                #pragma unroll
                for (int j = 0; j < 4; j++) {
                    asm volatile(
                        "mma.sync.aligned.m16n8k16.row.col.f32.f16.f16.f32 "
                        "{%0,%1,%2,%3},{%4,%5,%6,%7},{%8,%9},{%0,%1,%2,%3};"
                        : "+f"(acc[i][j][0]), "+f"(acc[i][j][1]),
                          "+f"(acc[i][j][2]), "+f"(acc[i][j][3])
                        : "r"(afr[i][0]), "r"(afr[i][1]), "r"(afr[i][2]), "r"(afr[i][3]),
                          "r"(bfr[j][0]), "r"(bfr[j][1]));
                }
        }
        buf  = (buf  + 1 == NST) ? 0 : buf + 1;
        pbuf = (pbuf + 1 == NST) ? 0 : pbuf + 1;
    }

    const int mrow = lane >> 2, nc2 = (lane & 3) * 2;
    #pragma unroll
    for (int i = 0; i < 2; i++) {
        int gm = m0 + wm + i * 16 + mrow;
        float* Crow0 = C + (size_t)gm * N;
        float* Crow1 = C + (size_t)(gm + 8) * N;
        #pragma unroll
        for (int j = 0; j < 4; j++) {
            int gn = n0 + wn + j * 8 + nc2;
            if (gn < N) {
                float bv = bias[gn];
                Crow0[gn] = acc[i][j][0] + bv;
                Crow1[gn] = acc[i][j][2] + bv;
            }
            if (gn + 1 < N) {
                float bv = bias[gn + 1];
                Crow0[gn + 1] = acc[i][j][1] + bv;
                Crow1[gn + 1] = acc[i][j][3] + bv;
            }
        }
    }
}

// ---------------- fused weight conversion (W_ih ++ W_out) ------------------------
#define N_WIH ((size_t)H4 * Ed)
#define N_WOUT ((size_t)Vd * Hd)
__global__ void conv_weights(const float* __restrict__ Wih,
                             const float* __restrict__ Wout)
{
    size_t i = (size_t)blockIdx.x * blockDim.x + threadIdx.x;
    if (i < N_WIH) {
        s_Wih[i] = __float2half_rn(Wih[i]);
    } else if (i < N_WIH + N_WOUT) {
        size_t k = i - N_WIH;
        s_Wout[k] = __float2half_rn(Wout[k]);
    }
}

// ---------------- gather word embeddings (fp32 -> fp16) into s_seq rows t>=1 ---
__global__ void gather_emb(const int* __restrict__ seqs,
                           const float* __restrict__ emb)
{
    int bid = blockIdx.x;
    int t1  = bid / Bb;
    int b   = bid % Bb;
    int word = seqs[b * (Tl - 1) + t1];
    const float4* src = reinterpret_cast<const float4*>(emb + (size_t)word * Ed);
    __half* dst = s_seq + (size_t)((t1 + 1) * Bb + b) * Ed;
    for (int i = threadIdx.x; i < Ed / 4; i += blockDim.x) {
        float4 v = src[i];
        __half2 h01 = __floats2half2_rn(v.x, v.y);
        __half2 h23 = __floats2half2_rn(v.z, v.w);
        *reinterpret_cast<__half2*>(dst + i * 4)     = h01;
        *reinterpret_cast<__half2*>(dst + i * 4 + 2) = h23;
    }
}

// ---------------- persistent tensor-core LSTM recurrence ------------------------
// 128 CTAs: (jt 0..31) x (batch-quarter 0..3). Each CTA: 32 batch rows x 64
// gate cols. W_hh tile fp16 in smem; h via 2-stage cp.async pipeline; xg slice
// prefetched across the grid barrier; c in registers.
#define LCH   128
#define NCH   (Hd / LCH)               // 4
#define TSTR  136
#define W_CH  (64 * TSTR)
#define H_STG (32 * TSTR)              // 32 batch rows per CTA
#define SMEM_LSTM ((NCH * W_CH + 2 * H_STG) * 2 + 2 * 32 * 68 * 4)  // 104448 B

__device__ __forceinline__ void grid_sync_n(unsigned int nctas)
{
    __threadfence();
    __syncthreads();
    if (threadIdx.x == 0) {
        unsigned gen = g_bar_gen;
        if (atomicAdd(&g_bar_cnt, 1u) == nctas - 1u) {
            g_bar_cnt = 0;
            __threadfence();
            g_bar_gen = gen + 1;
        } else {
            while (g_bar_gen == gen) __nanosleep(16);
            __threadfence();
        }
    }
    __syncthreads();
}

__global__ void __launch_bounds__(256, 1)
lstm_tc(const float* __restrict__ Whh,   // [4H, H]
        const float* __restrict__ bhh)   // [4H]
{
    extern __shared__ __align__(16) uint16_t lsm[];
    uint16_t* Ws = lsm;                          // NCH x 64 x TSTR
    uint16_t* Hb = lsm + NCH * W_CH;             // 2 x 32 x TSTR
    float*    Gs = (float*)(Hb + 2 * H_STG);     // 32 x 68
    float*    Xs = Gs + 32 * 68;                 // 32 x 68

    const int tid  = threadIdx.x;
    const int warp = tid >> 5, lane = tid & 31;
    const int wm = (warp >> 2) * 16;        // 2 M-groups of 16 batch rows
    const int wn = (warp & 3) * 16;         // 4 N-groups of 16 gate cols
    const int jt = blockIdx.x >> 2;         // hidden slice 0..31
    const int b0 = (blockIdx.x & 3) * 32;   // batch-quarter origin

    // ---- load W_hh tile to smem as fp16 (once) ----
    #pragma unroll
    for (int it = 0; it < 32; it++) {
        int task = tid + it * 256;
        int row = task >> 7;
        int c4  = task & 127;
        int grow = (row >> 4) * Hd + jt * 16 + (row & 15);
        float4 v = *reinterpret_cast<const float4*>(Whh + (size_t)grow * Hd + c4 * 4);
        int ck = c4 >> 5;
        int kc = (c4 & 31) * 4;
        __half2 h01 = __floats2half2_rn(v.x, v.y);
        __half2 h23 = __floats2half2_rn(v.z, v.w);
        uint16_t* dst = Ws + ck * W_CH + row * TSTR + kc;
        *reinterpret_cast<__half2*>(dst)     = h01;
        *reinterpret_cast<__half2*>(dst + 2) = h23;
    }

    const int jj = tid & 15;
    float creg[2];
    creg[0] = 0.0f; creg[1] = 0.0f;
    float bs[4];
    #pragma unroll
    for (int g = 0; g < 4; g++) bs[g] = bhh[g * Hd + jt * 16 + jj];

    // zero this CTA's h slice (32 rows x 16 cols)
    #pragma unroll
    for (int it = 0; it < 2; it++) {
        int bl = (tid >> 4) + it * 16;
        g_hfp16[(b0 + bl) * Hd + jt * 16 + jj] = __float2half_rn(0.0f);
    }
    grid_sync_n(128);

    // xg slice prefetch: 32 bl x 16 tasks = 512 x 16B tasks
    auto issue_xg = [&](const float* xg_t) {
        #pragma unroll
        for (int it = 0; it < 2; it++) {
            int task = tid + it * 256;
            int bl  = task >> 4;
            int rem = task & 15;
            int g = rem >> 2, q = rem & 3;
            uint32_t dst = smem_u32(&Xs[bl * 68 + g * 16 + q * 4]);
            const void* src = xg_t + (size_t)(b0 + bl) * H4 + g * Hd + jt * 16 + q * 4;
            asm volatile("cp.async.cg.shared.global [%0],[%1],16;\n" :: "r"(dst), "l"(src));
        }
        asm volatile("cp.async.commit_group;\n");
    };

    // h chunk: 32 rows x 128 halves = 512 x 16B tasks
    auto issue_h = [&](int stage, int ck) {
        #pragma unroll
        for (int it = 0; it < 2; it++) {
            int task = tid + it * 256;
            int r  = task >> 4;
            int c8 = task & 15;
            uint32_t dst = smem_u32(&Hb[stage * H_STG + r * TSTR + c8 * 8]);
            const void* src = g_hfp16 + (b0 + r) * Hd + ck * LCH + c8 * 8;
            asm volatile("cp.async.cg.shared.global [%0],[%1],16;\n" :: "r"(dst), "l"(src));
        }
        asm volatile("cp.async.commit_group;\n");
    };

    // xg for t=0 issued ahead of the step loop
    issue_xg(g_xg);

    for (int t = 0; t < Tl; t++) {
        float acc[2][4];
        #pragma unroll
        for (int j = 0; j < 2; j++)
            #pragma unroll
            for (int r = 0; r < 4; r++) acc[j][r] = 0.0f;

        issue_h(0, 0);     // group: h0   (xg(t) is the older group)
        issue_h(1, 1);     // group: h1

        #pragma unroll
        for (int ck = 0; ck < NCH; ck++) {
            if (ck < 3) cp_wait<1>();
            else        cp_wait<0>();
            __syncthreads();

            const int stage = ck & 1;
            const uint16_t* hs = Hb + stage * H_STG;
            const uint16_t* ws = Ws + ck * W_CH;

            #pragma unroll
            for (int kk = 0; kk < LCH; kk += 16) {
                uint32_t afr[4];
                {
                    int row = wm + (lane & 15);
                    int col = kk + (lane >> 4) * 8;
                    uint32_t addr = smem_u32(&hs[row * TSTR + col]);
                    asm volatile("ldmatrix.sync.aligned.m8n8.x4.shared.b16 {%0,%1,%2,%3},[%4];"
                                 : "=r"(afr[0]), "=r"(afr[1]), "=r"(afr[2]), "=r"(afr[3])
                                 : "r"(addr));
                }
                uint32_t bfr[2][2];
                {
                    int grp = lane >> 3;
                    int row = wn + (grp >> 1) * 8 + (lane & 7);
                    int col = kk + (grp & 1) * 8;
                    uint32_t addr = smem_u32(&ws[row * TSTR + col]);
                    uint32_t r0, r1, r2, r3;
                    asm volatile("ldmatrix.sync.aligned.m8n8.x4.shared.b16 {%0,%1,%2,%3},[%4];"
                                 : "=r"(r0), "=r"(r1), "=r"(r2), "=r"(r3) : "r"(addr));
                    bfr[0][0] = r0; bfr[0][1] = r1;
                    bfr[1][0] = r2; bfr[1][1] = r3;
                }
                #pragma unroll
                for (int j = 0; j < 2; j++) {
                    asm volatile(
                        "mma.sync.aligned.m16n8k16.row.col.f32.f16.f16.f32 "
                        "{%0,%1,%2,%3},{%4,%5,%6,%7},{%8,%9},{%0,%1,%2,%3};"
                        : "+f"(acc[j][0]), "+f"(acc[j][1]),
                          "+f"(acc[j][2]), "+f"(acc[j][3])
                        : "r"(afr[0]), "r"(afr[1]), "r"(afr[2]), "r"(afr[3]),
                          "r"(bfr[j][0]), "r"(bfr[j][1]));
                }
            }
            __syncthreads();

            if (ck == 0) issue_h(0, 2);
            else if (ck == 1) issue_h(1, 3);
        }

        // write gate pre-activations (h@W^T part) to smem
        const int mrow = lane >> 2, nc2 = (lane & 3) * 2;
        {
            int r0 = wm + mrow;
            #pragma unroll
            for (int j = 0; j < 2; j++) {
                int col = wn + j * 8 + nc2;
                Gs[r0 * 68 + col]           = acc[j][0];
                Gs[r0 * 68 + col + 1]       = acc[j][1];
                Gs[(r0 + 8) * 68 + col]     = acc[j][2];
                Gs[(r0 + 8) * 68 + col + 1] = acc[j][3];
            }
        }
        __syncthreads();

        // cell update: 2 cells per thread, all operands in smem
        #pragma unroll
        for (int it = 0; it < 2; it++) {
            int bl = (tid >> 4) + it * 16;
            float gi = fsig (Gs[bl * 68 +  0 + jj] + Xs[bl * 68 +  0 + jj] + bs[0]);
            float gf = fsig (Gs[bl * 68 + 16 + jj] + Xs[bl * 68 + 16 + jj] + bs[1]);
            float gg = ftanh(Gs[bl * 68 + 32 + jj] + Xs[bl * 68 + 32 + jj] + bs[2]);
            float go = fsig (Gs[bl * 68 + 48 + jj] + Xs[bl * 68 + 48 + jj] + bs[3]);
            float c = fmaf(gf, creg[it], gi * gg);
            creg[it] = c;
            __half h16 = __float2half_rn(go * ftanh(c));
            g_hfp16[(b0 + bl) * Hd + jt * 16 + jj] = h16;
            s_hid[((size_t)(b0 + bl) * Tl + t) * Hd + jt * 16 + jj] = h16;
        }

        // hoist next step's xg fetch across the barrier
        __syncthreads();
        if (t + 1 < Tl) issue_xg(g_xg + (size_t)(t + 1) * Bb * H4);

        grid_sync_n(128);
    }
}

// ---------------- launch --------------------------------------------------------
extern "C" void kernel_launch(void* const* d_in, const int* in_sizes, int n_in,
                              void* d_out, int out_size)
{
    const float* features = (const float*)d_in[0];   // [B,F]
    const int*   seqs     = (const int*)  d_in[1];   // [B,T-1]
    const float* W_in  = (const float*)d_in[3];      // [E,F]
    const float* b_in  = (const float*)d_in[4];      // [E]
    const float* emb   = (const float*)d_in[5];      // [V,E]
    const float* W_ih  = (const float*)d_in[6];      // [4H,E]
    const float* W_hh  = (const float*)d_in[7];      // [4H,H]
    const float* b_ih  = (const float*)d_in[8];      // [4H]
    const float* b_hh  = (const float*)d_in[9];      // [4H]
    const float* W_out = (const float*)d_in[10];     // [V,H]
    const float* b_out = (const float*)d_in[11];     // [V]
    float* out = (float*)d_out;                      // [B,T,V]

    float* p_xg;
    cudaGetSymbolAddress((void**)&p_xg, g_xg);
    __half *p_sseq, *p_Wih, *p_hid, *p_Wout;
    cudaGetSymbolAddress((void**)&p_sseq, s_seq);
    cudaGetSymbolAddress((void**)&p_Wih,  s_Wih);
    cudaGetSymbolAddress((void**)&p_hid,  s_hid);
    cudaGetSymbolAddress((void**)&p_Wout, s_Wout);

    cudaFuncSetAttribute(gemm_mma, cudaFuncAttributeMaxDynamicSharedMemorySize, SMEM_MM);
    cudaFuncSetAttribute(lstm_tc,  cudaFuncAttributeMaxDynamicSharedMemorySize, SMEM_LSTM);

    const int TPB = 256;
    auto nb = [](size_t n, int t) { return (int)((n + t - 1) / t); };

    // 1) x0 = features @ W_in^T + b_in (fp32 accum) -> s_seq rows [0,128) fp16
    {
        dim3 grid(Ed / 32, Bb / 32);   // 64 CTAs
        gemm_tn_h<32, 32, 8, 2, 2><<<grid, 256>>>(
            features, W_in, b_in, p_sseq, Bb, Ed, Fdim);
    }

    // 2) gather embeddings (fp16) for t = 1..T-1
    gather_emb<<<(Tl - 1) * Bb, 128>>>(seqs, emb);

    // 3) fused weight conversion (W_ih + W_out) in one launch
    conv_weights<<<nb(N_WIH + N_WOUT, TPB), TPB>>>(W_ih, W_out);

    // 4) xg GEMM  [5120, 2048] K=512 (single fp16)
    {
        dim3 grid(H4 / 128, BT / 128);   // (16,40)
        gemm_mma<<<grid, 512, SMEM_MM>>>(p_sseq, p_Wih, b_ih, p_xg, BT, H4, Ed);
    }

    // 5) persistent tensor-core recurrence (128 CTAs; writes h fp16 into s_hid)
    lstm_tc<<<128, 256, SMEM_LSTM>>>(W_hh, b_hh);

    // 6) output GEMM [5120, 10000] K=512 (single fp16)
    {
        dim3 grid((Vd + 127) / 128, BT / 128);   // (79,40)
        gemm_mma<<<grid, 512, SMEM_MM>>>(p_hid, p_Wout, b_out, out, BT, Vd, Ed);
    }
}

// round 15
// speedup vs baseline: 3.3115x; 1.0055x over previous
#include <cuda_runtime.h>
#include <cuda_bf16.h>
#include <cuda_fp16.h>
#include <cstdint>

// Problem constants
#define Bb   128
#define Fdim 1536
#define Ed   512
#define Hd   512
#define H4   2048
#define Vd   10000
#define Tl   40
#define BT   (Bb*Tl)     // 5120

// ---------------- scratch (static device memory) -----------------------------
__device__ float g_xg[(size_t)BT * H4];            // [T*B, 4H]
__device__ __align__(16) __half g_hfp16[Bb * Hd];  // recurrent h (fp16)

// fp16 operand buffers
__device__ __align__(16) __half s_seq [(size_t)BT * Ed];    // A of xg (fp16 seq)
__device__ __align__(16) __half s_Wih [(size_t)H4 * Ed];    // B of xg
__device__ __align__(16) __half s_hid [(size_t)BT * Ed];    // A of out GEMM
__device__ __align__(16) __half s_Wout[(size_t)Vd * Ed];    // B of out GEMM

// grid barrier state
__device__ unsigned int g_bar_cnt = 0;
__device__ volatile unsigned int g_bar_gen = 0;

// fast MUFU-only activations (EX2 + RCP; ~2ulp)
__device__ __forceinline__ float fsig(float x) {
    return __fdividef(1.0f, 1.0f + __expf(-x));
}
__device__ __forceinline__ float ftanh(float x) {
    return fmaf(-2.0f, __fdividef(1.0f, 1.0f + __expf(2.0f * x)), 1.0f);
}

__device__ __forceinline__ uint32_t smem_u32(const void* p) {
    return (uint32_t)__cvta_generic_to_shared(p);
}

template<int N>
__device__ __forceinline__ void cp_wait() {
    asm volatile("cp.async.wait_group %0;\n" :: "n"(N));
}

// ---------------- fp32 SIMT GEMM for x0, fp16 output: C = A @ B^T + bias ------
template<int BM, int BN, int BK, int TM, int TN>
__global__ void gemm_tn_h(const float* __restrict__ A,
                          const float* __restrict__ Bw,
                          const float* __restrict__ bias,
                          __half* __restrict__ C,
                          int M, int N, int K)
{
    constexpr int NT = (BM / TM) * (BN / TN);
    static_assert(NT == 256, "need 256 threads");
    __shared__ float As[BK][BM];
    __shared__ float Bs[BK][BN];

    const int m0 = blockIdx.y * BM;
    const int n0 = blockIdx.x * BN;
    const int tid = threadIdx.x;
    constexpr int NTX = BN / TN;
    const int tc = tid % NTX;
    const int tr = tid / NTX;

    float acc[TM][TN];
    #pragma unroll
    for (int i = 0; i < TM; i++)
        #pragma unroll
        for (int j = 0; j < TN; j++) acc[i][j] = 0.0f;

    constexpr int A_LD4 = BM * BK / 4;
    constexpr int B_LD4 = BN * BK / 4;
    constexpr int K4 = BK / 4;

    for (int k0 = 0; k0 < K; k0 += BK) {
        #pragma unroll
        for (int i = tid; i < A_LD4; i += NT) {
            int row = i / K4;
            int kc  = (i % K4) * 4;
            float4 v = *reinterpret_cast<const float4*>(
                A + (size_t)(m0 + row) * K + k0 + kc);
            As[kc + 0][row] = v.x; As[kc + 1][row] = v.y;
            As[kc + 2][row] = v.z; As[kc + 3][row] = v.w;
        }
        #pragma unroll
        for (int i = tid; i < B_LD4; i += NT) {
            int row = i / K4;
            int kc  = (i % K4) * 4;
            float4 v = *reinterpret_cast<const float4*>(
                Bw + (size_t)(n0 + row) * K + k0 + kc);
            Bs[kc + 0][row] = v.x; Bs[kc + 1][row] = v.y;
            Bs[kc + 2][row] = v.z; Bs[kc + 3][row] = v.w;
        }
        __syncthreads();

        #pragma unroll
        for (int k = 0; k < BK; k++) {
            float ra[TM], rb[TN];
            #pragma unroll
            for (int i = 0; i < TM; i++) ra[i] = As[k][tr * TM + i];
            #pragma unroll
            for (int j = 0; j < TN; j++) rb[j] = Bs[k][tc * TN + j];
            #pragma unroll
            for (int i = 0; i < TM; i++)
                #pragma unroll
                for (int j = 0; j < TN; j++)
                    acc[i][j] = fmaf(ra[i], rb[j], acc[i][j]);
        }
        __syncthreads();
    }

    #pragma unroll
    for (int i = 0; i < TM; i++) {
        int m = m0 + tr * TM + i;
        #pragma unroll
        for (int j = 0; j < TN; j++) {
            int n = n0 + tc * TN + j;
            C[(size_t)m * N + n] = __float2half_rn(acc[i][j] + bias[n]);
        }
    }
}

// ---------------- fp16 HMMA GEMM: C = A @ B^T + bias ---------------------------
// Tile 128x128, 512 threads (16 warps, warp tile 32x32), K-chunk 64, 3-stage
// cp.async ring (distance 2), one __syncthreads per chunk, 2 CTAs/SM.
#define KC      64
#define STRIDEg 72
#define SA_ST   (128 * STRIDEg)
#define NST     3
#define SMEM_MM (NST * 2 * SA_ST * 2)      // 110592 bytes

__global__ void __launch_bounds__(512, 2)
gemm_mma(const __half* __restrict__ A,
         const __half* __restrict__ B,
         const float* __restrict__ bias,
         float* __restrict__ C,
         int M, int N, int K)
{
    extern __shared__ __align__(16) uint16_t smbuf[];
    uint16_t* Asm = smbuf;
    uint16_t* Bsm = smbuf + NST * SA_ST;

    const int tid  = threadIdx.x;
    const int warp = tid >> 5, lane = tid & 31;
    const int wm = (warp >> 2) * 32;
    const int wn = (warp & 3) * 32;
    const int m0 = blockIdx.y * 128, n0 = blockIdx.x * 128;
    const int KT = K / KC;

    float acc[2][4][4];
    #pragma unroll
    for (int i = 0; i < 2; i++)
        #pragma unroll
        for (int j = 0; j < 4; j++)
            #pragma unroll
            for (int r = 0; r < 4; r++) acc[i][j][r] = 0.0f;

    auto load_tile = [&](int buf, int kt) {
        const int k0 = kt * KC;
        #pragma unroll
        for (int it = 0; it < 2; it++) {
            int task = tid + it * 512;
            int r = task >> 3, c = task & 7;
            uint32_t dst = smem_u32(&Asm[buf * SA_ST + r * STRIDEg + c * 8]);
            const void* src = A + (size_t)(m0 + r) * K + k0 + c * 8;
            asm volatile("cp.async.cg.shared.global [%0],[%1],16;\n" :: "r"(dst), "l"(src));
        }
        #pragma unroll
        for (int it = 0; it < 2; it++) {
            int task = tid + it * 512;
            int r = task >> 3, c = task & 7;
            if (n0 + r < N) {
                uint32_t dst = smem_u32(&Bsm[buf * SA_ST + r * STRIDEg + c * 8]);
                const void* src = B + (size_t)(n0 + r) * K + k0 + c * 8;
                asm volatile("cp.async.cg.shared.global [%0],[%1],16;\n" :: "r"(dst), "l"(src));
            }
        }
        asm volatile("cp.async.commit_group;\n");
    };

    load_tile(0, 0);
    if (KT > 1) load_tile(1, 1); else asm volatile("cp.async.commit_group;\n");

    int buf = 0, pbuf = 2;
    for (int ck = 0; ck < KT; ck++) {
        cp_wait<1>();
        __syncthreads();
        if (ck + 2 < KT) load_tile(pbuf, ck + 2);
        else             asm volatile("cp.async.commit_group;\n");

        const uint16_t* as = Asm + buf * SA_ST;
        const uint16_t* bs = Bsm + buf * SA_ST;

        #pragma unroll
        for (int kk = 0; kk < KC; kk += 16) {
            uint32_t afr[2][4];
            #pragma unroll
            for (int i = 0; i < 2; i++) {
                int row = wm + i * 16 + (lane & 15);
                int col = kk + (lane >> 4) * 8;
                uint32_t addr = smem_u32(&as[row * STRIDEg + col]);
                asm volatile("ldmatrix.sync.aligned.m8n8.x4.shared.b16 {%0,%1,%2,%3},[%4];"
                             : "=r"(afr[i][0]), "=r"(afr[i][1]), "=r"(afr[i][2]), "=r"(afr[i][3])
                             : "r"(addr));
            }
            uint32_t bfr[4][2];
            #pragma unroll
            for (int j = 0; j < 2; j++) {
                int grp = lane >> 3;
                int row = wn + j * 16 + (grp >> 1) * 8 + (lane & 7);
                int col = kk + (grp & 1) * 8;
                uint32_t addr = smem_u32(&bs[row * STRIDEg + col]);
                uint32_t r0, r1, r2, r3;
                asm volatile("ldmatrix.sync.aligned.m8n8.x4.shared.b16 {%0,%1,%2,%3},[%4];"
                             : "=r"(r0), "=r"(r1), "=r"(r2), "=r"(r3) : "r"(addr));
                bfr[j * 2][0] = r0; bfr[j * 2][1] = r1;
                bfr[j * 2 + 1][0] = r2; bfr[j * 2 + 1][1] = r3;
            }
            #pragma unroll
            for (int i = 0; i < 2; i++)
                #pragma unroll
                for (int j = 0; j < 4; j++) {
                    asm volatile(
                        "mma.sync.aligned.m16n8k16.row.col.f32.f16.f16.f32 "
                        "{%0,%1,%2,%3},{%4,%5,%6,%7},{%8,%9},{%0,%1,%2,%3};"
                        : "+f"(acc[i][j][0]), "+f"(acc[i][j][1]),
                          "+f"(acc[i][j][2]), "+f"(acc[i][j][3])
                        : "r"(afr[i][0]), "r"(afr[i][1]), "r"(afr[i][2]), "r"(afr[i][3]),
                          "r"(bfr[j][0]), "r"(bfr[j][1]));
                }
        }
        buf  = (buf  + 1 == NST) ? 0 : buf + 1;
        pbuf = (pbuf + 1 == NST) ? 0 : pbuf + 1;
    }

    const int mrow = lane >> 2, nc2 = (lane & 3) * 2;
    #pragma unroll
    for (int i = 0; i < 2; i++) {
        int gm = m0 + wm + i * 16 + mrow;
        float* Crow0 = C + (size_t)gm * N;
        float* Crow1 = C + (size_t)(gm + 8) * N;
        #pragma unroll
        for (int j = 0; j < 4; j++) {
            int gn = n0 + wn + j * 8 + nc2;
            if (gn < N) {
                float bv = bias[gn];
                Crow0[gn] = acc[i][j][0] + bv;
                Crow1[gn] = acc[i][j][2] + bv;
            }
            if (gn + 1 < N) {
                float bv = bias[gn + 1];
                Crow0[gn + 1] = acc[i][j][1] + bv;
                Crow1[gn + 1] = acc[i][j][3] + bv;
            }
        }
    }
}

// ---------------- fused weight conversion (W_ih ++ W_out) ------------------------
#define N_WIH ((size_t)H4 * Ed)
#define N_WOUT ((size_t)Vd * Hd)
__global__ void conv_weights(const float* __restrict__ Wih,
                             const float* __restrict__ Wout)
{
    size_t i = (size_t)blockIdx.x * blockDim.x + threadIdx.x;
    if (i < N_WIH) {
        s_Wih[i] = __float2half_rn(Wih[i]);
    } else if (i < N_WIH + N_WOUT) {
        size_t k = i - N_WIH;
        s_Wout[k] = __float2half_rn(Wout[k]);
    }
}

// ---------------- gather word embeddings (fp32 -> fp16) into s_seq rows t>=1 ---
__global__ void gather_emb(const int* __restrict__ seqs,
                           const float* __restrict__ emb)
{
    int bid = blockIdx.x;
    int t1  = bid / Bb;
    int b   = bid % Bb;
    int word = seqs[b * (Tl - 1) + t1];
    const float4* src = reinterpret_cast<const float4*>(emb + (size_t)word * Ed);
    __half* dst = s_seq + (size_t)((t1 + 1) * Bb + b) * Ed;
    for (int i = threadIdx.x; i < Ed / 4; i += blockDim.x) {
        float4 v = src[i];
        __half2 h01 = __floats2half2_rn(v.x, v.y);
        __half2 h23 = __floats2half2_rn(v.z, v.w);
        *reinterpret_cast<__half2*>(dst + i * 4)     = h01;
        *reinterpret_cast<__half2*>(dst + i * 4 + 2) = h23;
    }
}

// ---------------- persistent tensor-core LSTM recurrence ------------------------
// 128 CTAs: (jt 0..31) x (batch-quarter 0..3). Each CTA: 32 batch rows x 64
// gate cols. Single K-chunk (512): whole h slice loaded per step with one
// cp.async group; 32 uninterrupted LDSM+HMMA micro-iterations; 3 block
// barriers + 1 grid barrier per step.
#define TSTR2 520                      // 512 + 8 halves: conflict-free stride
#define W_SZ  (64 * TSTR2)             // W_hh tile (halves)
#define H_SZ  (32 * TSTR2)             // h slice (halves)
#define SMEM_LSTM ((W_SZ + H_SZ) * 2 + 2 * 32 * 68 * 4)  // 117248 B

__device__ __forceinline__ void grid_sync_n(unsigned int nctas)
{
    __threadfence();
    __syncthreads();
    if (threadIdx.x == 0) {
        unsigned gen = g_bar_gen;
        if (atomicAdd(&g_bar_cnt, 1u) == nctas - 1u) {
            g_bar_cnt = 0;
            __threadfence();
            g_bar_gen = gen + 1;
        } else {
            while (g_bar_gen == gen) __nanosleep(16);
            __threadfence();
        }
    }
    __syncthreads();
}

__global__ void __launch_bounds__(256, 1)
lstm_tc(const float* __restrict__ Whh,   // [4H, H]
        const float* __restrict__ bhh)   // [4H]
{
    extern __shared__ __align__(16) uint16_t lsm[];
    uint16_t* Ws = lsm;                          // 64 x TSTR2
    uint16_t* Hb = lsm + W_SZ;                   // 32 x TSTR2
    float*    Gs = (float*)(Hb + H_SZ);          // 32 x 68
    float*    Xs = Gs + 32 * 68;                 // 32 x 68

    const int tid  = threadIdx.x;
    const int warp = tid >> 5, lane = tid & 31;
    const int wm = (warp >> 2) * 16;        // 2 M-groups of 16 batch rows
    const int wn = (warp & 3) * 16;         // 4 N-groups of 16 gate cols
    const int jt = blockIdx.x >> 2;         // hidden slice 0..31
    const int b0 = (blockIdx.x & 3) * 32;   // batch-quarter origin

    // ---- load W_hh tile to smem as fp16 (once): 64 rows x 512 cols ----
    #pragma unroll
    for (int it = 0; it < 32; it++) {
        int task = tid + it * 256;     // 8192 float4 tasks
        int row = task >> 7;
        int c4  = task & 127;
        int grow = (row >> 4) * Hd + jt * 16 + (row & 15);
        float4 v = *reinterpret_cast<const float4*>(Whh + (size_t)grow * Hd + c4 * 4);
        __half2 h01 = __floats2half2_rn(v.x, v.y);
        __half2 h23 = __floats2half2_rn(v.z, v.w);
        uint16_t* dst = Ws + row * TSTR2 + c4 * 4;
        *reinterpret_cast<__half2*>(dst)     = h01;
        *reinterpret_cast<__half2*>(dst + 2) = h23;
    }

    const int jj = tid & 15;
    float creg[2];
    creg[0] = 0.0f; creg[1] = 0.0f;
    float bs[4];
    #pragma unroll
    for (int g = 0; g < 4; g++) bs[g] = bhh[g * Hd + jt * 16 + jj];

    // zero this CTA's h slice (32 rows x 16 cols)
    #pragma unroll
    for (int it = 0; it < 2; it++) {
        int bl = (tid >> 4) + it * 16;
        g_hfp16[(b0 + bl) * Hd + jt * 16 + jj] = __float2half_rn(0.0f);
    }
    grid_sync_n(128);

    // xg slice prefetch: 32 bl x 16 tasks = 512 x 16B tasks
    auto issue_xg = [&](const float* xg_t) {
        #pragma unroll
        for (int it = 0; it < 2; it++) {
            int task = tid + it * 256;
            int bl  = task >> 4;
            int rem = task & 15;
            int g = rem >> 2, q = rem & 3;
            uint32_t dst = smem_u32(&Xs[bl * 68 + g * 16 + q * 4]);
            const void* src = xg_t + (size_t)(b0 + bl) * H4 + g * Hd + jt * 16 + q * 4;
            asm volatile("cp.async.cg.shared.global [%0],[%1],16;\n" :: "r"(dst), "l"(src));
        }
        asm volatile("cp.async.commit_group;\n");
    };

    // full h slice: 32 rows x 512 halves = 2048 x 16B tasks
    auto issue_h = [&]() {
        #pragma unroll
        for (int it = 0; it < 8; it++) {
            int task = tid + it * 256;
            int r  = task >> 6;           // 0..31
            int c8 = task & 63;           // 0..63 (x8 halves)
            uint32_t dst = smem_u32(&Hb[r * TSTR2 + c8 * 8]);
            const void* src = g_hfp16 + (b0 + r) * Hd + c8 * 8;
            asm volatile("cp.async.cg.shared.global [%0],[%1],16;\n" :: "r"(dst), "l"(src));
        }
        asm volatile("cp.async.commit_group;\n");
    };

    // xg for t=0 issued ahead of the step loop
    issue_xg(g_xg);

    for (int t = 0; t < Tl; t++) {
        float acc[2][4];
        #pragma unroll
        for (int j = 0; j < 2; j++)
            #pragma unroll
            for (int r = 0; r < 4; r++) acc[j][r] = 0.0f;

        issue_h();
        cp_wait<0>();        // xg(t) and h both complete
        __syncthreads();

        // 32 uninterrupted micro-iterations over K=512
        #pragma unroll 8
        for (int kk = 0; kk < Hd; kk += 16) {
            uint32_t afr[4];
            {
                int row = wm + (lane & 15);
                int col = kk + (lane >> 4) * 8;
                uint32_t addr = smem_u32(&Hb[row * TSTR2 + col]);
                asm volatile("ldmatrix.sync.aligned.m8n8.x4.shared.b16 {%0,%1,%2,%3},[%4];"
                             : "=r"(afr[0]), "=r"(afr[1]), "=r"(afr[2]), "=r"(afr[3])
                             : "r"(addr));
            }
            uint32_t bfr[2][2];
            {
                int grp = lane >> 3;
                int row = wn + (grp >> 1) * 8 + (lane & 7);
                int col = kk + (grp & 1) * 8;
                uint32_t addr = smem_u32(&Ws[row * TSTR2 + col]);
                uint32_t r0, r1, r2, r3;
                asm volatile("ldmatrix.sync.aligned.m8n8.x4.shared.b16 {%0,%1,%2,%3},[%4];"
                             : "=r"(r0), "=r"(r1), "=r"(r2), "=r"(r3) : "r"(addr));
                bfr[0][0] = r0; bfr[0][1] = r1;
                bfr[1][0] = r2; bfr[1][1] = r3;
            }
            #pragma unroll
            for (int j = 0; j < 2; j++) {
                asm volatile(
                    "mma.sync.aligned.m16n8k16.row.col.f32.f16.f16.f32 "
                    "{%0,%1,%2,%3},{%4,%5,%6,%7},{%8,%9},{%0,%1,%2,%3};"
                    : "+f"(acc[j][0]), "+f"(acc[j][1]),
                      "+f"(acc[j][2]), "+f"(acc[j][3])
                    : "r"(afr[0]), "r"(afr[1]), "r"(afr[2]), "r"(afr[3]),
                      "r"(bfr[j][0]), "r"(bfr[j][1]));
            }
        }

        // write gate pre-activations (h@W^T part) to smem
        const int mrow = lane >> 2, nc2 = (lane & 3) * 2;
        {
            int r0 = wm + mrow;
            #pragma unroll
            for (int j = 0; j < 2; j++) {
                int col = wn + j * 8 + nc2;
                Gs[r0 * 68 + col]           = acc[j][0];
                Gs[r0 * 68 + col + 1]       = acc[j][1];
                Gs[(r0 + 8) * 68 + col]     = acc[j][2];
                Gs[(r0 + 8) * 68 + col + 1] = acc[j][3];
            }
        }
        __syncthreads();

        // cell update: 2 cells per thread, all operands in smem
        #pragma unroll
        for (int it = 0; it < 2; it++) {
            int bl = (tid >> 4) + it * 16;
            float gi = fsig (Gs[bl * 68 +  0 + jj] + Xs[bl * 68 +  0 + jj] + bs[0]);
            float gf = fsig (Gs[bl * 68 + 16 + jj] + Xs[bl * 68 + 16 + jj] + bs[1]);
            float gg = ftanh(Gs[bl * 68 + 32 + jj] + Xs[bl * 68 + 32 + jj] + bs[2]);
            float go = fsig (Gs[bl * 68 + 48 + jj] + Xs[bl * 68 + 48 + jj] + bs[3]);
            float c = fmaf(gf, creg[it], gi * gg);
            creg[it] = c;
            __half h16 = __float2half_rn(go * ftanh(c));
            g_hfp16[(b0 + bl) * Hd + jt * 16 + jj] = h16;
            s_hid[((size_t)(b0 + bl) * Tl + t) * Hd + jt * 16 + jj] = h16;
        }

        // hoist next step's xg fetch across the barrier
        __syncthreads();
        if (t + 1 < Tl) issue_xg(g_xg + (size_t)(t + 1) * Bb * H4);

        grid_sync_n(128);
    }
}

// ---------------- launch --------------------------------------------------------
extern "C" void kernel_launch(void* const* d_in, const int* in_sizes, int n_in,
                              void* d_out, int out_size)
{
    const float* features = (const float*)d_in[0];   // [B,F]
    const int*   seqs     = (const int*)  d_in[1];   // [B,T-1]
    const float* W_in  = (const float*)d_in[3];      // [E,F]
    const float* b_in  = (const float*)d_in[4];      // [E]
    const float* emb   = (const float*)d_in[5];      // [V,E]
    const float* W_ih  = (const float*)d_in[6];      // [4H,E]
    const float* W_hh  = (const float*)d_in[7];      // [4H,H]
    const float* b_ih  = (const float*)d_in[8];      // [4H]
    const float* b_hh  = (const float*)d_in[9];      // [4H]
    const float* W_out = (const float*)d_in[10];     // [V,H]
    const float* b_out = (const float*)d_in[11];     // [V]
    float* out = (float*)d_out;                      // [B,T,V]

    float* p_xg;
    cudaGetSymbolAddress((void**)&p_xg, g_xg);
    __half *p_sseq, *p_Wih, *p_hid, *p_Wout;
    cudaGetSymbolAddress((void**)&p_sseq, s_seq);
    cudaGetSymbolAddress((void**)&p_Wih,  s_Wih);
    cudaGetSymbolAddress((void**)&p_hid,  s_hid);
    cudaGetSymbolAddress((void**)&p_Wout, s_Wout);

    cudaFuncSetAttribute(gemm_mma, cudaFuncAttributeMaxDynamicSharedMemorySize, SMEM_MM);
    cudaFuncSetAttribute(lstm_tc,  cudaFuncAttributeMaxDynamicSharedMemorySize, SMEM_LSTM);

    const int TPB = 256;
    auto nb = [](size_t n, int t) { return (int)((n + t - 1) / t); };

    // 1) x0 = features @ W_in^T + b_in (fp32 accum) -> s_seq rows [0,128) fp16
    {
        dim3 grid(Ed / 32, Bb / 32);   // 64 CTAs
        gemm_tn_h<32, 32, 8, 2, 2><<<grid, 256>>>(
            features, W_in, b_in, p_sseq, Bb, Ed, Fdim);
    }

    // 2) gather embeddings (fp16) for t = 1..T-1
    gather_emb<<<(Tl - 1) * Bb, 128>>>(seqs, emb);

    // 3) fused weight conversion (W_ih + W_out) in one launch
    conv_weights<<<nb(N_WIH + N_WOUT, TPB), TPB>>>(W_ih, W_out);

    // 4) xg GEMM  [5120, 2048] K=512 (single fp16)
    {
        dim3 grid(H4 / 128, BT / 128);   // (16,40)
        gemm_mma<<<grid, 512, SMEM_MM>>>(p_sseq, p_Wih, b_ih, p_xg, BT, H4, Ed);
    }

    // 5) persistent tensor-core recurrence (128 CTAs; writes h fp16 into s_hid)
    lstm_tc<<<128, 256, SMEM_LSTM>>>(W_hh, b_hh);

    // 6) output GEMM [5120, 10000] K=512 (single fp16)
    {
        dim3 grid((Vd + 127) / 128, BT / 128);   // (79,40)
        gemm_mma<<<grid, 512, SMEM_MM>>>(p_hid, p_Wout, b_out, out, BT, Vd, Ed);
    }
}

// round 16
// speedup vs baseline: 3.3917x; 1.0242x over previous
#include <cuda_runtime.h>
#include <cuda_bf16.h>
#include <cuda_fp16.h>
#include <cstdint>

// Problem constants
#define Bb   128
#define Fdim 1536
#define Ed   512
#define Hd   512
#define H4   2048
#define Vd   10000
#define Tl   40
#define BT   (Bb*Tl)     // 5120

// ---------------- scratch (static device memory) -----------------------------
__device__ float g_xg[(size_t)BT * H4];            // [T*B, 4H]
__device__ __align__(16) __half g_hfp16[Bb * Hd];  // recurrent h (fp16)

// fp16 operand buffers
__device__ __align__(16) __half s_seq [(size_t)BT * Ed];    // A of xg (fp16 seq)
__device__ __align__(16) __half s_Wih [(size_t)H4 * Ed];    // B of xg
__device__ __align__(16) __half s_hid [(size_t)BT * Ed];    // A of out GEMM
__device__ __align__(16) __half s_Wout[(size_t)Vd * Ed];    // B of out GEMM

// per-quarter barrier state (padded 128B apart)
__device__ unsigned int g_qbar_cnt[4 * 32];
__device__ volatile unsigned int g_qbar_gen[4 * 32];

// fast MUFU-only activations (EX2 + RCP; ~2ulp)
__device__ __forceinline__ float fsig(float x) {
    return __fdividef(1.0f, 1.0f + __expf(-x));
}
__device__ __forceinline__ float ftanh(float x) {
    return fmaf(-2.0f, __fdividef(1.0f, 1.0f + __expf(2.0f * x)), 1.0f);
}

__device__ __forceinline__ uint32_t smem_u32(const void* p) {
    return (uint32_t)__cvta_generic_to_shared(p);
}

template<int N>
__device__ __forceinline__ void cp_wait() {
    asm volatile("cp.async.wait_group %0;\n" :: "n"(N));
}

// ---------------- fp32 SIMT GEMM for x0, fp16 output: C = A @ B^T + bias ------
template<int BM, int BN, int BK, int TM, int TN>
__global__ void gemm_tn_h(const float* __restrict__ A,
                          const float* __restrict__ Bw,
                          const float* __restrict__ bias,
                          __half* __restrict__ C,
                          int M, int N, int K)
{
    constexpr int NT = (BM / TM) * (BN / TN);
    static_assert(NT == 256, "need 256 threads");
    __shared__ float As[BK][BM];
    __shared__ float Bs[BK][BN];

    const int m0 = blockIdx.y * BM;
    const int n0 = blockIdx.x * BN;
    const int tid = threadIdx.x;
    constexpr int NTX = BN / TN;
    const int tc = tid % NTX;
    const int tr = tid / NTX;

    float acc[TM][TN];
    #pragma unroll
    for (int i = 0; i < TM; i++)
        #pragma unroll
        for (int j = 0; j < TN; j++) acc[i][j] = 0.0f;

    constexpr int A_LD4 = BM * BK / 4;
    constexpr int B_LD4 = BN * BK / 4;
    constexpr int K4 = BK / 4;

    for (int k0 = 0; k0 < K; k0 += BK) {
        #pragma unroll
        for (int i = tid; i < A_LD4; i += NT) {
            int row = i / K4;
            int kc  = (i % K4) * 4;
            float4 v = *reinterpret_cast<const float4*>(
                A + (size_t)(m0 + row) * K + k0 + kc);
            As[kc + 0][row] = v.x; As[kc + 1][row] = v.y;
            As[kc + 2][row] = v.z; As[kc + 3][row] = v.w;
        }
        #pragma unroll
        for (int i = tid; i < B_LD4; i += NT) {
            int row = i / K4;
            int kc  = (i % K4) * 4;
            float4 v = *reinterpret_cast<const float4*>(
                Bw + (size_t)(n0 + row) * K + k0 + kc);
            Bs[kc + 0][row] = v.x; Bs[kc + 1][row] = v.y;
            Bs[kc + 2][row] = v.z; Bs[kc + 3][row] = v.w;
        }
        __syncthreads();

        #pragma unroll
        for (int k = 0; k < BK; k++) {
            float ra[TM], rb[TN];
            #pragma unroll
            for (int i = 0; i < TM; i++) ra[i] = As[k][tr * TM + i];
            #pragma unroll
            for (int j = 0; j < TN; j++) rb[j] = Bs[k][tc * TN + j];
            #pragma unroll
            for (int i = 0; i < TM; i++)
                #pragma unroll
                for (int j = 0; j < TN; j++)
                    acc[i][j] = fmaf(ra[i], rb[j], acc[i][j]);
        }
        __syncthreads();
    }

    #pragma unroll
    for (int i = 0; i < TM; i++) {
        int m = m0 + tr * TM + i;
        #pragma unroll
        for (int j = 0; j < TN; j++) {
            int n = n0 + tc * TN + j;
            C[(size_t)m * N + n] = __float2half_rn(acc[i][j] + bias[n]);
        }
    }
}

// ---------------- fp16 HMMA GEMM: C = A @ B^T + bias ---------------------------
// Tile 128x128, 512 threads (16 warps, warp tile 32x32), K-chunk 64, 3-stage
// cp.async ring (distance 2), one __syncthreads per chunk, 2 CTAs/SM.
#define KC      64
#define STRIDEg 72
#define SA_ST   (128 * STRIDEg)
#define NST     3
#define SMEM_MM (NST * 2 * SA_ST * 2)      // 110592 bytes

__global__ void __launch_bounds__(512, 2)
gemm_mma(const __half* __restrict__ A,
         const __half* __restrict__ B,
         const float* __restrict__ bias,
         float* __restrict__ C,
         int M, int N, int K)
{
    extern __shared__ __align__(16) uint16_t smbuf[];
    uint16_t* Asm = smbuf;
    uint16_t* Bsm = smbuf + NST * SA_ST;

    const int tid  = threadIdx.x;
    const int warp = tid >> 5, lane = tid & 31;
    const int wm = (warp >> 2) * 32;
    const int wn = (warp & 3) * 32;
    const int m0 = blockIdx.y * 128, n0 = blockIdx.x * 128;
    const int KT = K / KC;

    float acc[2][4][4];
    #pragma unroll
    for (int i = 0; i < 2; i++)
        #pragma unroll
        for (int j = 0; j < 4; j++)
            #pragma unroll
            for (int r = 0; r < 4; r++) acc[i][j][r] = 0.0f;

    auto load_tile = [&](int buf, int kt) {
        const int k0 = kt * KC;
        #pragma unroll
        for (int it = 0; it < 2; it++) {
            int task = tid + it * 512;
            int r = task >> 3, c = task & 7;
            uint32_t dst = smem_u32(&Asm[buf * SA_ST + r * STRIDEg + c * 8]);
            const void* src = A + (size_t)(m0 + r) * K + k0 + c * 8;
            asm volatile("cp.async.cg.shared.global [%0],[%1],16;\n" :: "r"(dst), "l"(src));
        }
        #pragma unroll
        for (int it = 0; it < 2; it++) {
            int task = tid + it * 512;
            int r = task >> 3, c = task & 7;
            if (n0 + r < N) {
                uint32_t dst = smem_u32(&Bsm[buf * SA_ST + r * STRIDEg + c * 8]);
                const void* src = B + (size_t)(n0 + r) * K + k0 + c * 8;
                asm volatile("cp.async.cg.shared.global [%0],[%1],16;\n" :: "r"(dst), "l"(src));
            }
        }
        asm volatile("cp.async.commit_group;\n");
    };

    load_tile(0, 0);
    if (KT > 1) load_tile(1, 1); else asm volatile("cp.async.commit_group;\n");

    int buf = 0, pbuf = 2;
    for (int ck = 0; ck < KT; ck++) {
        cp_wait<1>();
        __syncthreads();
        if (ck + 2 < KT) load_tile(pbuf, ck + 2);
        else             asm volatile("cp.async.commit_group;\n");

        const uint16_t* as = Asm + buf * SA_ST;
        const uint16_t* bs = Bsm + buf * SA_ST;

        #pragma unroll
        for (int kk = 0; kk < KC; kk += 16) {
            uint32_t afr[2][4];
            #pragma unroll
            for (int i = 0; i < 2; i++) {
                int row = wm + i * 16 + (lane & 15);
                int col = kk + (lane >> 4) * 8;
                uint32_t addr = smem_u32(&as[row * STRIDEg + col]);
                asm volatile("ldmatrix.sync.aligned.m8n8.x4.shared.b16 {%0,%1,%2,%3},[%4];"
                             : "=r"(afr[i][0]), "=r"(afr[i][1]), "=r"(afr[i][2]), "=r"(afr[i][3])
                             : "r"(addr));
            }
            uint32_t bfr[4][2];
            #pragma unroll
            for (int j = 0; j < 2; j++) {
                int grp = lane >> 3;
                int row = wn + j * 16 + (grp >> 1) * 8 + (lane & 7);
                int col = kk + (grp & 1) * 8;
                uint32_t addr = smem_u32(&bs[row * STRIDEg + col]);
                uint32_t r0, r1, r2, r3;
                asm volatile("ldmatrix.sync.aligned.m8n8.x4.shared.b16 {%0,%1,%2,%3},[%4];"
                             : "=r"(r0), "=r"(r1), "=r"(r2), "=r"(r3) : "r"(addr));
                bfr[j * 2][0] = r0; bfr[j * 2][1] = r1;
                bfr[j * 2 + 1][0] = r2; bfr[j * 2 + 1][1] = r3;
            }
            #pragma unroll
            for (int i = 0; i < 2; i++)
                #pragma unroll
                for (int j = 0; j < 4; j++) {
                    asm volatile(
                        "mma.sync.aligned.m16n8k16.row.col.f32.f16.f16.f32 "
                        "{%0,%1,%2,%3},{%4,%5,%6,%7},{%8,%9},{%0,%1,%2,%3};"
                        : "+f"(acc[i][j][0]), "+f"(acc[i][j][1]),
                          "+f"(acc[i][j][2]), "+f"(acc[i][j][3])
                        : "r"(afr[i][0]), "r"(afr[i][1]), "r"(afr[i][2]), "r"(afr[i][3]),
                          "r"(bfr[j][0]), "r"(bfr[j][1]));
                }
        }
        buf  = (buf  + 1 == NST) ? 0 : buf + 1;
        pbuf = (pbuf + 1 == NST) ? 0 : pbuf + 1;
    }

    const int mrow = lane >> 2, nc2 = (lane & 3) * 2;
    #pragma unroll
    for (int i = 0; i < 2; i++) {
        int gm = m0 + wm + i * 16 + mrow;
        float* Crow0 = C + (size_t)gm * N;
        float* Crow1 = C + (size_t)(gm + 8) * N;
        #pragma unroll
        for (int j = 0; j < 4; j++) {
            int gn = n0 + wn + j * 8 + nc2;
            if (gn < N) {
                float bv = bias[gn];
                Crow0[gn] = acc[i][j][0] + bv;
                Crow1[gn] = acc[i][j][2] + bv;
            }
            if (gn + 1 < N) {
                float bv = bias[gn + 1];
                Crow0[gn + 1] = acc[i][j][1] + bv;
                Crow1[gn + 1] = acc[i][j][3] + bv;
            }
        }
    }
}

// ---------------- fused weight conversion (W_ih ++ W_out) ------------------------
#define N_WIH ((size_t)H4 * Ed)
#define N_WOUT ((size_t)Vd * Hd)
__global__ void conv_weights(const float* __restrict__ Wih,
                             const float* __restrict__ Wout)
{
    size_t i = (size_t)blockIdx.x * blockDim.x + threadIdx.x;
    if (i < N_WIH) {
        s_Wih[i] = __float2half_rn(Wih[i]);
    } else if (i < N_WIH + N_WOUT) {
        size_t k = i - N_WIH;
        s_Wout[k] = __float2half_rn(Wout[k]);
    }
}

// ---------------- gather word embeddings (fp32 -> fp16) into s_seq rows t>=1 ---
__global__ void gather_emb(const int* __restrict__ seqs,
                           const float* __restrict__ emb)
{
    int bid = blockIdx.x;
    int t1  = bid / Bb;
    int b   = bid % Bb;
    int word = seqs[b * (Tl - 1) + t1];
    const float4* src = reinterpret_cast<const float4*>(emb + (size_t)word * Ed);
    __half* dst = s_seq + (size_t)((t1 + 1) * Bb + b) * Ed;
    for (int i = threadIdx.x; i < Ed / 4; i += blockDim.x) {
        float4 v = src[i];
        __half2 h01 = __floats2half2_rn(v.x, v.y);
        __half2 h23 = __floats2half2_rn(v.z, v.w);
        *reinterpret_cast<__half2*>(dst + i * 4)     = h01;
        *reinterpret_cast<__half2*>(dst + i * 4 + 2) = h23;
    }
}

// ---------------- persistent tensor-core LSTM recurrence ------------------------
// 128 CTAs: (jt 0..31) x (batch-quarter 0..3). Each CTA: 32 batch rows x 64
// gate cols. The four batch-quarters are fully independent chains -> each
// synchronizes only its own 32 CTAs via a per-quarter barrier (padded
// counters). Single K-chunk (512), 3 block barriers + 1 quarter barrier/step.
#define TSTR2 520                      // 512 + 8 halves: conflict-free stride
#define W_SZ  (64 * TSTR2)             // W_hh tile (halves)
#define H_SZ  (32 * TSTR2)             // h slice (halves)
#define SMEM_LSTM ((W_SZ + H_SZ) * 2 + 2 * 32 * 68 * 4)  // 117248 B

__device__ __forceinline__ void quarter_sync(int q)
{
    __threadfence();
    __syncthreads();
    if (threadIdx.x == 0) {
        const int s = q * 32;
        unsigned gen = g_qbar_gen[s];
        if (atomicAdd(&g_qbar_cnt[s], 1u) == 31u) {
            g_qbar_cnt[s] = 0;
            __threadfence();
            g_qbar_gen[s] = gen + 1;
        } else {
            while (g_qbar_gen[s] == gen) __nanosleep(16);
            __threadfence();
        }
    }
    __syncthreads();
}

__global__ void __launch_bounds__(256, 1)
lstm_tc(const float* __restrict__ Whh,   // [4H, H]
        const float* __restrict__ bhh)   // [4H]
{
    extern __shared__ __align__(16) uint16_t lsm[];
    uint16_t* Ws = lsm;                          // 64 x TSTR2
    uint16_t* Hb = lsm + W_SZ;                   // 32 x TSTR2
    float*    Gs = (float*)(Hb + H_SZ);          // 32 x 68
    float*    Xs = Gs + 32 * 68;                 // 32 x 68

    const int tid  = threadIdx.x;
    const int warp = tid >> 5, lane = tid & 31;
    const int wm = (warp >> 2) * 16;        // 2 M-groups of 16 batch rows
    const int wn = (warp & 3) * 16;         // 4 N-groups of 16 gate cols
    const int jt = blockIdx.x >> 2;         // hidden slice 0..31
    const int q  = blockIdx.x & 3;          // batch quarter
    const int b0 = q * 32;                  // batch-quarter origin

    // ---- load W_hh tile to smem as fp16 (once): 64 rows x 512 cols ----
    #pragma unroll
    for (int it = 0; it < 32; it++) {
        int task = tid + it * 256;     // 8192 float4 tasks
        int row = task >> 7;
        int c4  = task & 127;
        int grow = (row >> 4) * Hd + jt * 16 + (row & 15);
        float4 v = *reinterpret_cast<const float4*>(Whh + (size_t)grow * Hd + c4 * 4);
        __half2 h01 = __floats2half2_rn(v.x, v.y);
        __half2 h23 = __floats2half2_rn(v.z, v.w);
        uint16_t* dst = Ws + row * TSTR2 + c4 * 4;
        *reinterpret_cast<__half2*>(dst)     = h01;
        *reinterpret_cast<__half2*>(dst + 2) = h23;
    }

    const int jj = tid & 15;
    float creg[2];
    creg[0] = 0.0f; creg[1] = 0.0f;
    float bs[4];
    #pragma unroll
    for (int g = 0; g < 4; g++) bs[g] = bhh[g * Hd + jt * 16 + jj];

    // zero this CTA's h slice (32 rows x 16 cols)
    #pragma unroll
    for (int it = 0; it < 2; it++) {
        int bl = (tid >> 4) + it * 16;
        g_hfp16[(b0 + bl) * Hd + jt * 16 + jj] = __float2half_rn(0.0f);
    }
    quarter_sync(q);

    // xg slice prefetch: 32 bl x 16 tasks = 512 x 16B tasks
    auto issue_xg = [&](const float* xg_t) {
        #pragma unroll
        for (int it = 0; it < 2; it++) {
            int task = tid + it * 256;
            int bl  = task >> 4;
            int rem = task & 15;
            int g = rem >> 2, qq = rem & 3;
            uint32_t dst = smem_u32(&Xs[bl * 68 + g * 16 + qq * 4]);
            const void* src = xg_t + (size_t)(b0 + bl) * H4 + g * Hd + jt * 16 + qq * 4;
            asm volatile("cp.async.cg.shared.global [%0],[%1],16;\n" :: "r"(dst), "l"(src));
        }
        asm volatile("cp.async.commit_group;\n");
    };

    // full h slice: 32 rows x 512 halves = 2048 x 16B tasks
    auto issue_h = [&]() {
        #pragma unroll
        for (int it = 0; it < 8; it++) {
            int task = tid + it * 256;
            int r  = task >> 6;
            int c8 = task & 63;
            uint32_t dst = smem_u32(&Hb[r * TSTR2 + c8 * 8]);
            const void* src = g_hfp16 + (b0 + r) * Hd + c8 * 8;
            asm volatile("cp.async.cg.shared.global [%0],[%1],16;\n" :: "r"(dst), "l"(src));
        }
        asm volatile("cp.async.commit_group;\n");
    };

    // xg for t=0 issued ahead of the step loop
    issue_xg(g_xg);

    for (int t = 0; t < Tl; t++) {
        float acc[2][4];
        #pragma unroll
        for (int j = 0; j < 2; j++)
            #pragma unroll
            for (int r = 0; r < 4; r++) acc[j][r] = 0.0f;

        issue_h();
        cp_wait<0>();        // xg(t) and h both complete
        __syncthreads();

        // 32 uninterrupted micro-iterations over K=512
        #pragma unroll 8
        for (int kk = 0; kk < Hd; kk += 16) {
            uint32_t afr[4];
            {
                int row = wm + (lane & 15);
                int col = kk + (lane >> 4) * 8;
                uint32_t addr = smem_u32(&Hb[row * TSTR2 + col]);
                asm volatile("ldmatrix.sync.aligned.m8n8.x4.shared.b16 {%0,%1,%2,%3},[%4];"
                             : "=r"(afr[0]), "=r"(afr[1]), "=r"(afr[2]), "=r"(afr[3])
                             : "r"(addr));
            }
            uint32_t bfr[2][2];
            {
                int grp = lane >> 3;
                int row = wn + (grp >> 1) * 8 + (lane & 7);
                int col = kk + (grp & 1) * 8;
                uint32_t addr = smem_u32(&Ws[row * TSTR2 + col]);
                uint32_t r0, r1, r2, r3;
                asm volatile("ldmatrix.sync.aligned.m8n8.x4.shared.b16 {%0,%1,%2,%3},[%4];"
                             : "=r"(r0), "=r"(r1), "=r"(r2), "=r"(r3) : "r"(addr));
                bfr[0][0] = r0; bfr[0][1] = r1;
                bfr[1][0] = r2; bfr[1][1] = r3;
            }
            #pragma unroll
            for (int j = 0; j < 2; j++) {
                asm volatile(
                    "mma.sync.aligned.m16n8k16.row.col.f32.f16.f16.f32 "
                    "{%0,%1,%2,%3},{%4,%5,%6,%7},{%8,%9},{%0,%1,%2,%3};"
                    : "+f"(acc[j][0]), "+f"(acc[j][1]),
                      "+f"(acc[j][2]), "+f"(acc[j][3])
                    : "r"(afr[0]), "r"(afr[1]), "r"(afr[2]), "r"(afr[3]),
                      "r"(bfr[j][0]), "r"(bfr[j][1]));
            }
        }

        // write gate pre-activations (h@W^T part) to smem
        const int mrow = lane >> 2, nc2 = (lane & 3) * 2;
        {
            int r0 = wm + mrow;
            #pragma unroll
            for (int j = 0; j < 2; j++) {
                int col = wn + j * 8 + nc2;
                Gs[r0 * 68 + col]           = acc[j][0];
                Gs[r0 * 68 + col + 1]       = acc[j][1];
                Gs[(r0 + 8) * 68 + col]     = acc[j][2];
                Gs[(r0 + 8) * 68 + col + 1] = acc[j][3];
            }
        }
        __syncthreads();

        // cell update: 2 cells per thread, all operands in smem
        #pragma unroll
        for (int it = 0; it < 2; it++) {
            int bl = (tid >> 4) + it * 16;
            float gi = fsig (Gs[bl * 68 +  0 + jj] + Xs[bl * 68 +  0 + jj] + bs[0]);
            float gf = fsig (Gs[bl * 68 + 16 + jj] + Xs[bl * 68 + 16 + jj] + bs[1]);
            float gg = ftanh(Gs[bl * 68 + 32 + jj] + Xs[bl * 68 + 32 + jj] + bs[2]);
            float go = fsig (Gs[bl * 68 + 48 + jj] + Xs[bl * 68 + 48 + jj] + bs[3]);
            float c = fmaf(gf, creg[it], gi * gg);
            creg[it] = c;
            __half h16 = __float2half_rn(go * ftanh(c));
            g_hfp16[(b0 + bl) * Hd + jt * 16 + jj] = h16;
            s_hid[((size_t)(b0 + bl) * Tl + t) * Hd + jt * 16 + jj] = h16;
        }

        // hoist next step's xg fetch across the barrier
        __syncthreads();
        if (t + 1 < Tl) issue_xg(g_xg + (size_t)(t + 1) * Bb * H4);

        quarter_sync(q);
    }
}

// ---------------- launch --------------------------------------------------------
extern "C" void kernel_launch(void* const* d_in, const int* in_sizes, int n_in,
                              void* d_out, int out_size)
{
    const float* features = (const float*)d_in[0];   // [B,F]
    const int*   seqs     = (const int*)  d_in[1];   // [B,T-1]
    const float* W_in  = (const float*)d_in[3];      // [E,F]
    const float* b_in  = (const float*)d_in[4];      // [E]
    const float* emb   = (const float*)d_in[5];      // [V,E]
    const float* W_ih  = (const float*)d_in[6];      // [4H,E]
    const float* W_hh  = (const float*)d_in[7];      // [4H,H]
    const float* b_ih  = (const float*)d_in[8];      // [4H]
    const float* b_hh  = (const float*)d_in[9];      // [4H]
    const float* W_out = (const float*)d_in[10];     // [V,H]
    const float* b_out = (const float*)d_in[11];     // [V]
    float* out = (float*)d_out;                      // [B,T,V]

    float* p_xg;
    cudaGetSymbolAddress((void**)&p_xg, g_xg);
    __half *p_sseq, *p_Wih, *p_hid, *p_Wout;
    cudaGetSymbolAddress((void**)&p_sseq, s_seq);
    cudaGetSymbolAddress((void**)&p_Wih,  s_Wih);
    cudaGetSymbolAddress((void**)&p_hid,  s_hid);
    cudaGetSymbolAddress((void**)&p_Wout, s_Wout);

    cudaFuncSetAttribute(gemm_mma, cudaFuncAttributeMaxDynamicSharedMemorySize, SMEM_MM);
    cudaFuncSetAttribute(lstm_tc,  cudaFuncAttributeMaxDynamicSharedMemorySize, SMEM_LSTM);

    const int TPB = 256;
    auto nb = [](size_t n, int t) { return (int)((n + t - 1) / t); };

    // 1) x0 = features @ W_in^T + b_in (fp32 accum) -> s_seq rows [0,128) fp16
    {
        dim3 grid(Ed / 32, Bb / 32);   // 64 CTAs
        gemm_tn_h<32, 32, 8, 2, 2><<<grid, 256>>>(
            features, W_in, b_in, p_sseq, Bb, Ed, Fdim);
    }

    // 2) gather embeddings (fp16) for t = 1..T-1
    gather_emb<<<(Tl - 1) * Bb, 128>>>(seqs, emb);

    // 3) fused weight conversion (W_ih + W_out) in one launch
    conv_weights<<<nb(N_WIH + N_WOUT, TPB), TPB>>>(W_ih, W_out);

    // 4) xg GEMM  [5120, 2048] K=512 (single fp16)
    {
        dim3 grid(H4 / 128, BT / 128);   // (16,40)
        gemm_mma<<<grid, 512, SMEM_MM>>>(p_sseq, p_Wih, b_ih, p_xg, BT, H4, Ed);
    }

    // 5) persistent tensor-core recurrence (128 CTAs; writes h fp16 into s_hid)
    lstm_tc<<<128, 256, SMEM_LSTM>>>(W_hh, b_hh);

    // 6) output GEMM [5120, 10000] K=512 (single fp16)
    {
        dim3 grid((Vd + 127) / 128, BT / 128);   // (79,40)
        gemm_mma<<<grid, 512, SMEM_MM>>>(p_hid, p_Wout, b_out, out, BT, Vd, Ed);
    }
}